// round 10
// baseline (speedup 1.0000x reference)
#include <cuda_runtime.h>
#include <math.h>

#define NMAX 40000
#define EMAX 640000
#define DD   128
#define HH   8
#define DKK  16
#define TT   3
#define RR   4
#define N4   (NMAX * RR)

#define GN      128            // nodes per gemm block
#define XSTRIDE 132            // xs row stride (floats)
#define KTILE   32
#define NTILE   (DD / KTILE)
#define XS_BYTES (DD * XSTRIDE * 4)
#define WB_BYTES (2 * KTILE * 64 * 4)
#define SMEM_GEMM (XS_BYTES + WB_BYTES + GN * 2 * 4)

#define NPB  32              // nodes per final block
#define GST  36              // gsN row stride (floats)

typedef unsigned long long ull;

// ---------------- scratch (device globals) ------------------------------------
__device__ float g_k   [NMAX * DD];
__device__ float g_q   [NMAX * DD];
__device__ float g_v   [NMAX * DD];
__device__ float g_qt  [NMAX * RR * DD];
__device__ float g_sp  [NMAX * DD];
__device__ float g_aggr[NMAX * DD];
__device__ float g_Wsp [DD * DD];
__device__ float g_bsp [DD];
__device__ ull   g_Rp  [RR * HH * 8 * DKK];
__device__ int   g_win [NMAX];
__device__ int   g_thist[N4];
__device__ int   g_toff [N4 + 1];
__device__ int   g_tcur [N4];
__device__ int   g_epack[EMAX];
__device__ int   g_bsum [256];
__device__ int   g_typehist[TT];
__device__ int   g_typecur [TT];
__device__ int   g_perm [NMAX];

// ---------------- packed f32x2 helpers ----------------------------------------
__device__ __forceinline__ ull pack2(float a, float b) {
    ull r;
    asm("mov.b64 %0, {%1, %2};" : "=l"(r) : "f"(a), "f"(b));
    return r;
}
__device__ __forceinline__ void unpack2(ull v, float& lo, float& hi) {
    asm("mov.b64 {%0, %1}, %2;" : "=f"(lo), "=f"(hi) : "l"(v));
}
__device__ __forceinline__ void fma2(ull& acc, ull x, ull w) {
    asm("fma.rn.f32x2 %0, %1, %2, %0;" : "+l"(acc) : "l"(x), "l"(w));
}
__device__ __forceinline__ void cpasync16(void* dst, const void* src) {
    unsigned int da = (unsigned int)__cvta_generic_to_shared(dst);
    asm volatile("cp.async.cg.shared.global [%0], [%1], 16;"
                 :: "r"(da), "l"(src) : "memory");
}

// ------------------ init: zero hists + Wsp + packed Ratt ----------------------
__global__ void k_init(const float* __restrict__ Vw, const float* __restrict__ Vb,
                       const float* __restrict__ s2u, const float* __restrict__ Ratt,
                       int n, int zb) {
    int b = blockIdx.x;
    if (b < zb) {
        int i = b * 256 + threadIdx.x;
        if (i < n) g_win[i] = -1;
        if (i < 4 * n) g_thist[i] = 0;
        if (i < TT) { g_typehist[i] = 0; g_typecur[i] = 0; }
    } else if (b < zb + 65) {
        int bi  = b - zb;
        int row = bi * 2 + (threadIdx.x >> 7);
        int d   = threadIdx.x & 127;
        if (row < DD) {
            float acc = 0.f;
            for (int m = 0; m < DD; m++)
                acc += Vw[(DD + row) * DD + m] * s2u[m * DD + d];
            g_Wsp[row * DD + d] = acc;
        } else if (row == DD) {
            float acc = 0.f;
            for (int m = 0; m < DD; m++)
                acc += Vb[DD + m] * s2u[m * DD + d];
            g_bsp[d] = acc;
        }
    } else {
        int idx = (b - zb - 65) * 256 + threadIdx.x;
        if (idx < RR * HH * 8 * DKK) {
            int f   = idx & 15;
            int dkp = (idx >> 4) & 7;
            int h   = (idx >> 7) & 7;
            int r   = idx >> 10;
            float a0 = Ratt[((r * HH + h) * DKK + 2 * dkp)     * DKK + f];
            float a1 = Ratt[((r * HH + h) * DKK + 2 * dkp + 1) * DKK + f];
            g_Rp[idx] = pack2(a0, a1);
        }
    }
}

__global__ void k_nodehist(const int* __restrict__ ntype, int n) {
    int i = blockIdx.x * blockDim.x + threadIdx.x;
    if (i < n) atomicAdd(&g_typehist[ntype[i]], 1);
}

__global__ void k_nodescatter(const int* __restrict__ ntype, int n) {
    int i = blockIdx.x * blockDim.x + threadIdx.x;
    if (i >= n) return;
    int t = ntype[i];
    int off = 0;
    for (int ty = 0; ty < TT; ty++) if (ty < t) off += g_typehist[ty];
    int pos = off + atomicAdd(&g_typecur[t], 1);
    g_perm[pos] = i;
}

// ----------------- register-tiled GEMM: K/Q/V/speaker projections -------------
// grid: (ceil(n/128), 8). matrix = y>>1 in {K,Q,V,Wsp}, half = (y&1)*64.
__global__ void __launch_bounds__(256, 2)
k_gemm_proj(const float* __restrict__ x, const int* __restrict__ ntype,
            const float* __restrict__ Kw, const float* __restrict__ Kb,
            const float* __restrict__ Qw, const float* __restrict__ Qb,
            const float* __restrict__ Vw, const float* __restrict__ Vb, int n) {
    extern __shared__ __align__(16) unsigned char sraw[];
    float (*xs)[XSTRIDE] = (float (*)[XSTRIDE])sraw;
    float (*wbuf)[KTILE][64] = (float (*)[KTILE][64])(sraw + XS_BYTES);
    int* nodes_s = (int*)(sraw + XS_BYTES + WB_BYTES);
    int* types_s = nodes_s + GN;
    __shared__ int s_uni;

    int tid  = threadIdx.x;
    int base = blockIdx.x * GN;
    if (tid == 0) s_uni = 1;
    if (tid < GN) {
        int idx  = base + tid;
        int cidx = (idx < n) ? idx : (n - 1);
        nodes_s[tid] = (idx < n) ? g_perm[idx] : -1;
        types_s[tid] = ntype[g_perm[cidx]];
    }
    __syncthreads();
    if (tid < GN && types_s[tid] != types_s[0]) s_uni = 0;
    __syncthreads();
    int  t0      = types_s[0];
    bool uniform = (s_uni != 0);

    int mat  = blockIdx.y >> 1;
    int half = (blockIdx.y & 1) * 64;
    const float* W; const float* B; float* dst;
    switch (mat) {
        case 0:  W = Kw + t0 * DD * DD; B = Kb + t0 * DD; dst = g_k;  break;
        case 1:  W = Qw + t0 * DD * DD; B = Qb + t0 * DD; dst = g_q;  break;
        case 2:  W = Vw + t0 * DD * DD; B = Vb + t0 * DD; dst = g_v;  break;
        default: W = g_Wsp;             B = g_bsp;        dst = g_sp; break;
    }

    if (uniform) {   // prologue: stage W tile 0
#pragma unroll
        for (int q = 0; q < 2; q++) {
            int f4  = tid + q * 256;
            int row = f4 >> 4;
            int c4  = f4 & 15;
            cpasync16(&wbuf[0][row][c4 * 4], W + row * DD + half + c4 * 4);
        }
        asm volatile("cp.async.commit_group;" ::: "memory");
    }

    // stage x transposed
#pragma unroll 4
    for (int it = 0; it < 16; it++) {
        int f4 = tid + it * 256;
        int j  = f4 >> 5;
        int c4 = f4 & 31;
        int nd = nodes_s[j];
        float4 v = (nd >= 0) ? *(const float4*)&x[nd * DD + c4 * 4]
                             : make_float4(0.f, 0.f, 0.f, 0.f);
        xs[c4 * 4 + 0][j] = v.x;
        xs[c4 * 4 + 1][j] = v.y;
        xs[c4 * 4 + 2][j] = v.z;
        xs[c4 * 4 + 3][j] = v.w;
    }
    __syncthreads();

    int cn = tid & 15, nn = tid >> 4;
    int col0 = half + cn * 4;
    int nb0  = nn * 8;

    if (uniform) {
        float4 bv = *(const float4*)&B[col0];
        ull bb0 = pack2(bv.x, bv.x), bb1 = pack2(bv.y, bv.y);
        ull bb2 = pack2(bv.z, bv.z), bb3 = pack2(bv.w, bv.w);
        ull acc[4][4];
#pragma unroll
        for (int np = 0; np < 4; np++) {
            acc[np][0] = bb0; acc[np][1] = bb1; acc[np][2] = bb2; acc[np][3] = bb3;
        }

        for (int tile = 0; tile < NTILE; tile++) {
            if (tile + 1 < NTILE) {
                int stg = (tile + 1) & 1;
#pragma unroll
                for (int q = 0; q < 2; q++) {
                    int f4  = tid + q * 256;
                    int row = f4 >> 4;
                    int c4  = f4 & 15;
                    cpasync16(&wbuf[stg][row][c4 * 4],
                              W + ((tile + 1) * KTILE + row) * DD + half + c4 * 4);
                }
                asm volatile("cp.async.commit_group;" ::: "memory");
                asm volatile("cp.async.wait_group 1;" ::: "memory");
            } else {
                asm volatile("cp.async.wait_group 0;" ::: "memory");
            }
            __syncthreads();
            int cur = tile & 1;
#pragma unroll
            for (int kk = 0; kk < KTILE; kk++) {
                int k = tile * KTILE + kk;
                ulonglong2 xlo = *(const ulonglong2*)&xs[k][nb0];
                ulonglong2 xhi = *(const ulonglong2*)&xs[k][nb0 + 4];
                float4 wv = *(const float4*)&wbuf[cur][kk][cn * 4];
                ull w0 = pack2(wv.x, wv.x), w1 = pack2(wv.y, wv.y);
                ull w2 = pack2(wv.z, wv.z), w3 = pack2(wv.w, wv.w);
                fma2(acc[0][0], xlo.x, w0); fma2(acc[0][1], xlo.x, w1);
                fma2(acc[0][2], xlo.x, w2); fma2(acc[0][3], xlo.x, w3);
                fma2(acc[1][0], xlo.y, w0); fma2(acc[1][1], xlo.y, w1);
                fma2(acc[1][2], xlo.y, w2); fma2(acc[1][3], xlo.y, w3);
                fma2(acc[2][0], xhi.x, w0); fma2(acc[2][1], xhi.x, w1);
                fma2(acc[2][2], xhi.x, w2); fma2(acc[2][3], xhi.x, w3);
                fma2(acc[3][0], xhi.y, w0); fma2(acc[3][1], xhi.y, w1);
                fma2(acc[3][2], xhi.y, w2); fma2(acc[3][3], xhi.y, w3);
            }
            __syncthreads();
        }

#pragma unroll
        for (int np = 0; np < 4; np++) {
            int n0 = nodes_s[nb0 + np * 2], n1 = nodes_s[nb0 + np * 2 + 1];
            float4 o0, o1;
            unpack2(acc[np][0], o0.x, o1.x);
            unpack2(acc[np][1], o0.y, o1.y);
            unpack2(acc[np][2], o0.z, o1.z);
            unpack2(acc[np][3], o0.w, o1.w);
            if (n0 >= 0) *(float4*)&dst[n0 * DD + col0] = o0;
            if (n1 >= 0) *(float4*)&dst[n1 * DD + col0] = o1;
        }
    } else {
        for (int j = 0; j < 8; j++) {
            int node = nb0 + j;
            int nd = nodes_s[node];
            if (nd < 0) continue;
            int t = types_s[node];
            const float* Wt; const float* Bt;
            switch (mat) {
                case 0:  Wt = Kw + t * DD * DD; Bt = Kb + t * DD; break;
                case 1:  Wt = Qw + t * DD * DD; Bt = Qb + t * DD; break;
                case 2:  Wt = Vw + t * DD * DD; Bt = Vb + t * DD; break;
                default: Wt = g_Wsp;            Bt = g_bsp;       break;
            }
            float4 a = *(const float4*)&Bt[col0];
            for (int k = 0; k < DD; k++) {
                float xv = xs[k][node];
                float4 w = *(const float4*)&Wt[k * DD + col0];
                a.x += xv * w.x; a.y += xv * w.y; a.z += xv * w.z; a.w += xv * w.w;
            }
            *(float4*)&dst[nd * DD + col0] = a;
        }
    }
}

// ----------------- q' per relation (reads g_q, writes g_qt) -------------------
__global__ void __launch_bounds__(256, 3)
k_qt(int n) {
    __shared__ float qsN[DD][20];
    __shared__ int nodes_s[16];
    int tid  = threadIdx.x;
    int base = blockIdx.x * 16;
    if (tid < 16) nodes_s[tid] = (base + tid < n) ? g_perm[base + tid] : -1;
    __syncthreads();
#pragma unroll
    for (int q = 0; q < 2; q++) {
        int f4 = tid + q * 256;
        int j  = f4 >> 5;
        int c4 = f4 & 31;
        int nd = nodes_s[j];
        float4 v = (nd >= 0) ? *(const float4*)&g_q[nd * DD + c4 * 4]
                             : make_float4(0.f, 0.f, 0.f, 0.f);
        qsN[c4 * 4 + 0][j] = v.x;
        qsN[c4 * 4 + 1][j] = v.y;
        qsN[c4 * 4 + 2][j] = v.z;
        qsN[c4 * 4 + 3][j] = v.w;
    }
    __syncthreads();

    int p  = tid & 63, g = tid >> 6;
    int d0 = 2 * p;
    int jb = g * 4;
    int h = d0 >> 4, dkp = (d0 >> 1) & 7;
    const ull* rp = g_Rp + (h * 8 + dkp) * DKK;
#pragma unroll
    for (int r = 0; r < RR; r++) {
        ull a0 = 0, a1 = 0, a2 = 0, a3 = 0;
#pragma unroll
        for (int f = 0; f < DKK; f++) {
            ull w = rp[(r * HH * 8) * DKK + f];
            float4 qf = *(const float4*)&qsN[(h << 4) + f][jb];
            fma2(a0, pack2(qf.x, qf.x), w);
            fma2(a1, pack2(qf.y, qf.y), w);
            fma2(a2, pack2(qf.z, qf.z), w);
            fma2(a3, pack2(qf.w, qf.w), w);
        }
        ull av[4] = {a0, a1, a2, a3};
#pragma unroll
        for (int j = 0; j < 4; j++) {
            int nd = nodes_s[jb + j];
            if (nd >= 0) {
                float lo, hi;
                unpack2(av[j], lo, hi);
                *(float2*)&g_qt[(nd * RR + r) * DD + d0] = make_float2(lo, hi);
            }
        }
    }
}

// ------------------------------ edge setup ------------------------------------
__global__ void k_edgestats(const int* __restrict__ ei, const int* __restrict__ et, int e) {
    int i = blockIdx.x * blockDim.x + threadIdx.x;
    if (i >= e) return;
    int tgt = ei[e + i];
    int r   = et[i];
    atomicAdd(&g_thist[tgt * RR + r], 1);
    if (r == 0) atomicMax(&g_win[ei[i]], i);
}

__global__ void k_scan1(int n4) {
    __shared__ int buf[1024];
    int t = threadIdx.x;
    int gid = blockIdx.x * 1024 + t;
    int v = (gid < n4) ? g_thist[gid] : 0;
    buf[t] = v;
    __syncthreads();
    for (int off = 1; off < 1024; off <<= 1) {
        int x = (t >= off) ? buf[t - off] : 0;
        __syncthreads();
        buf[t] += x;
        __syncthreads();
    }
    if (gid < n4) g_toff[gid] = buf[t] - v;
    if (t == 1023) g_bsum[blockIdx.x] = buf[t];
}

__global__ void k_scan2(int nblocks, int n4) {
    if (threadIdx.x == 0) {
        int run = 0;
        for (int b = 0; b < nblocks; b++) { int x = g_bsum[b]; g_bsum[b] = run; run += x; }
        g_toff[n4] = run;
    }
}

__global__ void k_scan3(int n4) {
    int gid = blockIdx.x * blockDim.x + threadIdx.x;
    if (gid < n4) {
        int v = g_toff[gid] + g_bsum[gid >> 10];
        g_toff[gid] = v;
        g_tcur[gid] = v;
    }
}

__global__ void k_scatter_edges(const int* __restrict__ ei, const int* __restrict__ et,
                                const int* __restrict__ ntype, int e) {
    int i = blockIdx.x * blockDim.x + threadIdx.x;
    if (i >= e) return;
    int src = ei[i];
    int tgt = ei[e + i];
    int r   = et[i];
    int st  = ntype[src];
    int pos = atomicAdd(&g_tcur[tgt * RR + r], 1);
    g_epack[pos] = src | (st << 16);
}

// ------- attention: warp per target, per-relation sub-loops, 2-wide unroll -----
__global__ void __launch_bounds__(256)
k_attn(const int* __restrict__ ntype, const float* __restrict__ pri,
       const float* __restrict__ Rmsg, int n) {
    __shared__ float accsh[8][RR][DD];
    int warp = threadIdx.x >> 5, lane = threadIdx.x & 31;
    int i = blockIdx.x * 8 + warp;
    if (i >= n) return;
    int d0 = lane * 4;
    int h  = lane >> 2;

    int tt = ntype[i];
    float p0[TT], p1[TT], p2[TT], p3[TT];
#pragma unroll
    for (int st = 0; st < TT; st++) {
        p0[st] = pri[((tt * RR + 0) * TT + st) * HH + h];
        p1[st] = pri[((tt * RR + 1) * TT + st) * HH + h];
        p2[st] = pri[((tt * RR + 2) * TT + st) * HH + h];
        p3[st] = pri[((tt * RR + 3) * TT + st) * HH + h];
    }

    float den = 0.f;
    float4 acc[RR];
#pragma unroll
    for (int r = 0; r < RR; r++) acc[r] = make_float4(0.f, 0.f, 0.f, 0.f);

#pragma unroll
    for (int r = 0; r < RR; r++) {
        int beg = g_toff[i * RR + r], end = g_toff[i * RR + r + 1];
        if (beg == end) continue;
        float4 qtr = *(const float4*)&g_qt[(i * RR + r) * DD + d0];
        float4 a = make_float4(0.f, 0.f, 0.f, 0.f);
        float pA = (r == 0) ? p0[0] : (r == 1) ? p1[0] : (r == 2) ? p2[0] : p3[0];
        float pB = (r == 0) ? p0[1] : (r == 1) ? p1[1] : (r == 2) ? p2[1] : p3[1];
        float pC = (r == 0) ? p0[2] : (r == 1) ? p1[2] : (r == 2) ? p2[2] : p3[2];
        int idx = beg;
        for (; idx + 2 <= end; idx += 2) {
            int pk0 = g_epack[idx];
            int pk1 = g_epack[idx + 1];
            int s0 = pk0 & 0xFFFF, st0 = pk0 >> 16;
            int s1 = pk1 & 0xFFFF, st1 = pk1 >> 16;
            const float4 ka = *(const float4*)&g_k[s0 * DD + d0];
            const float4 kb = *(const float4*)&g_k[s1 * DD + d0];
            const float4 va = *(const float4*)&g_v[s0 * DD + d0];
            const float4 vb = *(const float4*)&g_v[s1 * DD + d0];
            float sa = qtr.x * ka.x + qtr.y * ka.y + qtr.z * ka.z + qtr.w * ka.w;
            float sb = qtr.x * kb.x + qtr.y * kb.y + qtr.z * kb.z + qtr.w * kb.w;
            sa += __shfl_xor_sync(0xffffffffu, sa, 1);
            sb += __shfl_xor_sync(0xffffffffu, sb, 1);
            sa += __shfl_xor_sync(0xffffffffu, sa, 2);
            sb += __shfl_xor_sync(0xffffffffu, sb, 2);
            float pra = (st0 == 1) ? pB : (st0 == 2) ? pC : pA;
            float prb = (st1 == 1) ? pB : (st1 == 2) ? pC : pA;
            float pea = __expf(sa * pra * 0.25f);
            float peb = __expf(sb * prb * 0.25f);
            den += pea + peb;
            a.x += pea * va.x + peb * vb.x;
            a.y += pea * va.y + peb * vb.y;
            a.z += pea * va.z + peb * vb.z;
            a.w += pea * va.w + peb * vb.w;
        }
        if (idx < end) {
            int pk  = g_epack[idx];
            int src = pk & 0xFFFF;
            int st  = pk >> 16;
            const float4 k4 = *(const float4*)&g_k[src * DD + d0];
            float s = qtr.x * k4.x + qtr.y * k4.y + qtr.z * k4.z + qtr.w * k4.w;
            s += __shfl_xor_sync(0xffffffffu, s, 1);
            s += __shfl_xor_sync(0xffffffffu, s, 2);
            float pr = (st == 1) ? pB : (st == 2) ? pC : pA;
            float pe = __expf(s * pr * 0.25f);
            den += pe;
            const float4 v4 = *(const float4*)&g_v[src * DD + d0];
            a.x += pe * v4.x;
            a.y += pe * v4.y;
            a.z += pe * v4.z;
            a.w += pe * v4.w;
        }
        acc[r] = a;
    }

    float inv = 1.f / (den + 1e-16f);
#pragma unroll
    for (int r = 0; r < RR; r++) {
        accsh[warp][r][d0 + 0] = acc[r].x * inv;
        accsh[warp][r][d0 + 1] = acc[r].y * inv;
        accsh[warp][r][d0 + 2] = acc[r].z * inv;
        accsh[warp][r][d0 + 3] = acc[r].w * inv;
    }
    __syncwarp();

    int f0 = (lane & 3) * 4;
    float4 o = make_float4(0.f, 0.f, 0.f, 0.f);
#pragma unroll
    for (int r = 0; r < RR; r++) {
#pragma unroll 4
        for (int dk = 0; dk < DKK; dk++) {
            float a = accsh[warp][r][(h << 4) + dk];
            const float4 w = *(const float4*)&Rmsg[(((r * HH + h) * DKK + dk) * DKK) + f0];
            o.x += a * w.x;
            o.y += a * w.y;
            o.z += a * w.z;
            o.w += a * w.w;
        }
    }
    *(float4*)&g_aggr[i * DD + d0] = o;
}

// ------------- final: speaker add + GELU + per-type A projection + skip -------
__global__ void __launch_bounds__(256, 3)
k_final(const float* __restrict__ x, const int* __restrict__ ntype,
        const int* __restrict__ ei,
        const float* __restrict__ Aw, const float* __restrict__ Ab,
        const float* __restrict__ skip, float* __restrict__ out, int n, int e) {
    __shared__ __align__(16) float gsN[DD][GST];
    __shared__ int nodes_s[NPB], types_s[NPB], spsrc_s[NPB];
    int tid  = threadIdx.x;
    int base = blockIdx.x * NPB;
    if (tid < NPB) {
        int idx = base + tid;
        int cidx = (idx < n) ? idx : (n - 1);
        int nd = (idx < n) ? g_perm[idx] : -1;
        nodes_s[tid] = nd;
        types_s[tid] = ntype[g_perm[cidx]];
        int sps = -1;
        if (nd >= 0) {
            int we = g_win[nd];
            if (we >= 0) sps = ei[e + we];
        }
        spsrc_s[tid] = sps;
    }
    __syncthreads();

    for (int idx = tid; idx < NPB * DD; idx += 256) {
        int j = idx >> 7;
        int k = idx & 127;
        int nd = nodes_s[j];
        float v = 0.f;
        if (nd >= 0) {
            v = g_aggr[nd * DD + k];
            int sps = spsrc_s[j];
            if (sps >= 0) v += g_sp[sps * DD + k];
            v = 0.5f * v * (1.f + erff(v * 0.70710678118654752f));
        }
        gsN[k][j] = v;
    }
    __syncthreads();

    int g  = tid >> 6;
    int p  = tid & 63;
    int d0 = 2 * p;
    int jb = g * 8;

    int t0 = types_s[0];
    bool uniform = true;
#pragma unroll
    for (int j = 1; j < NPB; j++) uniform &= (types_s[j] == t0);

    if (uniform) {
        const float* pA = Aw + t0 * DD * DD + d0;
        ull bA = *(const ull*)&Ab[t0 * DD + d0];
        ull aA[8];
#pragma unroll
        for (int j = 0; j < 8; j++) aA[j] = bA;
#pragma unroll 4
        for (int k = 0; k < DD; k++) {
            ull w2 = *(const ull*)&pA[k * DD];
            float4 q0 = *(const float4*)&gsN[k][jb];
            float4 q1 = *(const float4*)&gsN[k][jb + 4];
            fma2(aA[0], pack2(q0.x, q0.x), w2);
            fma2(aA[1], pack2(q0.y, q0.y), w2);
            fma2(aA[2], pack2(q0.z, q0.z), w2);
            fma2(aA[3], pack2(q0.w, q0.w), w2);
            fma2(aA[4], pack2(q1.x, q1.x), w2);
            fma2(aA[5], pack2(q1.y, q1.y), w2);
            fma2(aA[6], pack2(q1.z, q1.z), w2);
            fma2(aA[7], pack2(q1.w, q1.w), w2);
        }
        float sk = skip[t0];
        float alpha = 1.f / (1.f + __expf(-sk));
        float beta  = 1.f - alpha;
#pragma unroll
        for (int j = 0; j < 8; j++) {
            int nd = nodes_s[jb + j];
            if (nd < 0) continue;
            float lo, hi;
            unpack2(aA[j], lo, hi);
            float2 xv = *(const float2*)&x[nd * DD + d0];
            *(float2*)&out[nd * DD + d0] =
                make_float2(lo * alpha + xv.x * beta, hi * alpha + xv.y * beta);
        }
    } else {
        for (int j = 0; j < 8; j++) {
            int nd = nodes_s[jb + j];
            if (nd < 0) continue;
            int t = types_s[jb + j];
            float2 aA = *(const float2*)&Ab[t * DD + d0];
            for (int k = 0; k < DD; k++) {
                float gv = gsN[k][jb + j];
                float2 w = *(const float2*)&Aw[(t * DD + k) * DD + d0];
                aA.x += gv * w.x; aA.y += gv * w.y;
            }
            float sk = skip[t];
            float alpha = 1.f / (1.f + __expf(-sk));
            float beta  = 1.f - alpha;
            float2 xv = *(const float2*)&x[nd * DD + d0];
            *(float2*)&out[nd * DD + d0] =
                make_float2(aA.x * alpha + xv.x * beta, aA.y * alpha + xv.y * beta);
        }
    }
}

// --------------------------------- launcher -----------------------------------
extern "C" void kernel_launch(void* const* d_in, const int* in_sizes, int n_in,
                              void* d_out, int out_size) {
    const float* node_inp  = (const float*)d_in[0];
    const int*   node_type = (const int*)  d_in[1];
    const int*   edge_index= (const int*)  d_in[2];
    const int*   edge_type = (const int*)  d_in[3];
    const float* Kw = (const float*)d_in[5];
    const float* Kb = (const float*)d_in[6];
    const float* Qw = (const float*)d_in[7];
    const float* Qb = (const float*)d_in[8];
    const float* Vw = (const float*)d_in[9];
    const float* Vb = (const float*)d_in[10];
    const float* Aw = (const float*)d_in[11];
    const float* Ab = (const float*)d_in[12];
    const float* pri  = (const float*)d_in[13];
    const float* Ratt = (const float*)d_in[14];
    const float* Rmsg = (const float*)d_in[15];
    const float* s2u  = (const float*)d_in[16];
    const float* skip = (const float*)d_in[17];
    float* out = (float*)d_out;

    int n = in_sizes[1];
    int e = in_sizes[3];
    if (n > NMAX) n = NMAX;
    if (e > EMAX) e = EMAX;
    int n4 = n * RR;

    int nb  = (n + 255) / 256;
    int n4b = (n4 + 255) / 256;
    int eb  = (e + 255) / 256;
    int sb  = (n4 + 1023) / 1024;
    int ngb = (n + GN - 1) / GN;

    cudaFuncSetAttribute(k_gemm_proj, cudaFuncAttributeMaxDynamicSharedMemorySize, SMEM_GEMM);

    k_init<<<n4b + 65 + 16, 256>>>(Vw, Vb, s2u, Ratt, n, n4b);
    k_nodehist<<<nb, 256>>>(node_type, n);
    k_nodescatter<<<nb, 256>>>(node_type, n);
    k_gemm_proj<<<dim3(ngb, 8), 256, SMEM_GEMM>>>(node_inp, node_type,
                                                  Kw, Kb, Qw, Qb, Vw, Vb, n);
    k_qt<<<(n + 15) / 16, 256>>>(n);
    k_edgestats<<<eb, 256>>>(edge_index, edge_type, e);
    k_scan1<<<sb, 1024>>>(n4);
    k_scan2<<<1, 32>>>(sb, n4);
    k_scan3<<<n4b, 256>>>(n4);
    k_scatter_edges<<<eb, 256>>>(edge_index, edge_type, node_type, e);
    k_attn<<<(n + 7) / 8, 256>>>(node_type, pri, Rmsg, n);
    k_final<<<(n + NPB - 1) / NPB, 256>>>(node_inp, node_type, edge_index,
                                          Aw, Ab, skip, out, n, e);
}

// round 11
// speedup vs baseline: 1.2111x; 1.2111x over previous
#include <cuda_runtime.h>
#include <math.h>

#define NMAX 40000
#define EMAX 640000
#define DD   128
#define HH   8
#define DKK  16
#define TT   3
#define RR   4
#define N4   (NMAX * RR)

#define GN      128            // nodes per gemm block
#define XSTRIDE 132            // xs row stride (floats)
#define KTILE   32
#define NTILE   (DD / KTILE)
#define XS_BYTES (DD * XSTRIDE * 4)
#define WB_BYTES (2 * KTILE * 64 * 4)
#define SMEM_GEMM (XS_BYTES + WB_BYTES + GN * 2 * 4)

#define NPB  32              // nodes per final block
#define GST  36              // gsN row stride (floats)

typedef unsigned long long ull;

// ---------------- scratch (device globals) ------------------------------------
__device__ float g_k   [NMAX * DD];
__device__ float g_v   [NMAX * DD];
__device__ float g_qt  [NMAX * RR * DD];
__device__ float g_sp  [NMAX * DD];
__device__ float g_aggr[NMAX * DD];
__device__ float g_Wsp [DD * DD];
__device__ float g_bsp [DD];
__device__ ull   g_Rp  [RR * HH * 8 * DKK];
__device__ int   g_win [NMAX];
__device__ int   g_thist[N4];
__device__ int   g_toff [N4 + 1];
__device__ int   g_tcur [N4];
__device__ int   g_epack[EMAX];
__device__ int   g_bsum [256];
__device__ int   g_typehist[TT];
__device__ int   g_typecur [TT];
__device__ int   g_perm [NMAX];

// ---------------- packed f32x2 helpers ----------------------------------------
__device__ __forceinline__ ull pack2(float a, float b) {
    ull r;
    asm("mov.b64 %0, {%1, %2};" : "=l"(r) : "f"(a), "f"(b));
    return r;
}
__device__ __forceinline__ void unpack2(ull v, float& lo, float& hi) {
    asm("mov.b64 {%0, %1}, %2;" : "=f"(lo), "=f"(hi) : "l"(v));
}
__device__ __forceinline__ void fma2(ull& acc, ull x, ull w) {
    asm("fma.rn.f32x2 %0, %1, %2, %0;" : "+l"(acc) : "l"(x), "l"(w));
}
__device__ __forceinline__ void cpasync16(void* dst, const void* src) {
    unsigned int da = (unsigned int)__cvta_generic_to_shared(dst);
    asm volatile("cp.async.cg.shared.global [%0], [%1], 16;"
                 :: "r"(da), "l"(src) : "memory");
}

// ------------------ init: zero hists + Wsp + packed Ratt ----------------------
__global__ void k_init(const float* __restrict__ Vw, const float* __restrict__ Vb,
                       const float* __restrict__ s2u, const float* __restrict__ Ratt,
                       int n, int zb) {
    int b = blockIdx.x;
    if (b < zb) {
        int i = b * 256 + threadIdx.x;
        if (i < n) g_win[i] = -1;
        if (i < 4 * n) g_thist[i] = 0;
        if (i < TT) { g_typehist[i] = 0; g_typecur[i] = 0; }
    } else if (b < zb + 65) {
        int bi  = b - zb;
        int row = bi * 2 + (threadIdx.x >> 7);
        int d   = threadIdx.x & 127;
        if (row < DD) {
            float acc = 0.f;
            for (int m = 0; m < DD; m++)
                acc += Vw[(DD + row) * DD + m] * s2u[m * DD + d];
            g_Wsp[row * DD + d] = acc;
        } else if (row == DD) {
            float acc = 0.f;
            for (int m = 0; m < DD; m++)
                acc += Vb[DD + m] * s2u[m * DD + d];
            g_bsp[d] = acc;
        }
    } else {
        int idx = (b - zb - 65) * 256 + threadIdx.x;
        if (idx < RR * HH * 8 * DKK) {
            int f   = idx & 15;
            int dkp = (idx >> 4) & 7;
            int h   = (idx >> 7) & 7;
            int r   = idx >> 10;
            float a0 = Ratt[((r * HH + h) * DKK + 2 * dkp)     * DKK + f];
            float a1 = Ratt[((r * HH + h) * DKK + 2 * dkp + 1) * DKK + f];
            g_Rp[idx] = pack2(a0, a1);
        }
    }
}

__global__ void k_nodehist(const int* __restrict__ ntype, int n) {
    int i = blockIdx.x * blockDim.x + threadIdx.x;
    if (i < n) atomicAdd(&g_typehist[ntype[i]], 1);
}

__global__ void k_nodescatter(const int* __restrict__ ntype, int n) {
    int i = blockIdx.x * blockDim.x + threadIdx.x;
    if (i >= n) return;
    int t = ntype[i];
    int off = 0;
    for (int ty = 0; ty < TT; ty++) if (ty < t) off += g_typehist[ty];
    int pos = off + atomicAdd(&g_typecur[t], 1);
    g_perm[pos] = i;
}

// ----------------- register-tiled GEMM: K/Q/V/speaker projections -------------
// grid: (ceil(n/128), 8). matrix = y>>1 in {K,Q,V,Wsp}, half = (y&1)*64.
// Q blocks (mat==1) compute the per-relation q' transform in-block and write
// g_qt directly (each 64-col half holds 4 complete heads); g_q is eliminated.
__global__ void __launch_bounds__(256, 2)
k_gemm_proj(const float* __restrict__ x, const int* __restrict__ ntype,
            const float* __restrict__ Kw, const float* __restrict__ Kb,
            const float* __restrict__ Qw, const float* __restrict__ Qb,
            const float* __restrict__ Vw, const float* __restrict__ Vb, int n) {
    extern __shared__ __align__(16) unsigned char sraw[];
    float (*xs)[XSTRIDE] = (float (*)[XSTRIDE])sraw;
    float* qs = (float*)sraw;                     // overlay: q half after GEMM
    float (*wbuf)[KTILE][64] = (float (*)[KTILE][64])(sraw + XS_BYTES);
    int* nodes_s = (int*)(sraw + XS_BYTES + WB_BYTES);
    int* types_s = nodes_s + GN;
    __shared__ int s_uni;

    int tid  = threadIdx.x;
    int base = blockIdx.x * GN;
    if (tid == 0) s_uni = 1;
    if (tid < GN) {
        int idx  = base + tid;
        int cidx = (idx < n) ? idx : (n - 1);
        nodes_s[tid] = (idx < n) ? g_perm[idx] : -1;
        types_s[tid] = ntype[g_perm[cidx]];
    }
    __syncthreads();
    if (tid < GN && types_s[tid] != types_s[0]) s_uni = 0;
    __syncthreads();
    int  t0      = types_s[0];
    bool uniform = (s_uni != 0);

    int mat  = blockIdx.y >> 1;
    int half = (blockIdx.y & 1) * 64;
    const float* W; const float* B; float* dst;
    switch (mat) {
        case 0:  W = Kw + t0 * DD * DD; B = Kb + t0 * DD; dst = g_k;  break;
        case 1:  W = Qw + t0 * DD * DD; B = Qb + t0 * DD; dst = 0;    break;
        case 2:  W = Vw + t0 * DD * DD; B = Vb + t0 * DD; dst = g_v;  break;
        default: W = g_Wsp;             B = g_bsp;        dst = g_sp; break;
    }

    if (uniform) {
#pragma unroll
        for (int q = 0; q < 2; q++) {
            int f4  = tid + q * 256;
            int row = f4 >> 4;
            int c4  = f4 & 15;
            cpasync16(&wbuf[0][row][c4 * 4], W + row * DD + half + c4 * 4);
        }
        asm volatile("cp.async.commit_group;" ::: "memory");
    }

    // stage x transposed
#pragma unroll 4
    for (int it = 0; it < 16; it++) {
        int f4 = tid + it * 256;
        int j  = f4 >> 5;
        int c4 = f4 & 31;
        int nd = nodes_s[j];
        float4 v = (nd >= 0) ? *(const float4*)&x[nd * DD + c4 * 4]
                             : make_float4(0.f, 0.f, 0.f, 0.f);
        xs[c4 * 4 + 0][j] = v.x;
        xs[c4 * 4 + 1][j] = v.y;
        xs[c4 * 4 + 2][j] = v.z;
        xs[c4 * 4 + 3][j] = v.w;
    }
    __syncthreads();

    int cn = tid & 15, nn = tid >> 4;
    int col0 = half + cn * 4;
    int nb0  = nn * 8;

    if (uniform) {
        float4 bv = *(const float4*)&B[col0];
        ull bb0 = pack2(bv.x, bv.x), bb1 = pack2(bv.y, bv.y);
        ull bb2 = pack2(bv.z, bv.z), bb3 = pack2(bv.w, bv.w);
        ull acc[4][4];
#pragma unroll
        for (int np = 0; np < 4; np++) {
            acc[np][0] = bb0; acc[np][1] = bb1; acc[np][2] = bb2; acc[np][3] = bb3;
        }

        for (int tile = 0; tile < NTILE; tile++) {
            if (tile + 1 < NTILE) {
                int stg = (tile + 1) & 1;
#pragma unroll
                for (int q = 0; q < 2; q++) {
                    int f4  = tid + q * 256;
                    int row = f4 >> 4;
                    int c4  = f4 & 15;
                    cpasync16(&wbuf[stg][row][c4 * 4],
                              W + ((tile + 1) * KTILE + row) * DD + half + c4 * 4);
                }
                asm volatile("cp.async.commit_group;" ::: "memory");
                asm volatile("cp.async.wait_group 1;" ::: "memory");
            } else {
                asm volatile("cp.async.wait_group 0;" ::: "memory");
            }
            __syncthreads();
            int cur = tile & 1;
#pragma unroll
            for (int kk = 0; kk < KTILE; kk++) {
                int k = tile * KTILE + kk;
                ulonglong2 xlo = *(const ulonglong2*)&xs[k][nb0];
                ulonglong2 xhi = *(const ulonglong2*)&xs[k][nb0 + 4];
                float4 wv = *(const float4*)&wbuf[cur][kk][cn * 4];
                ull w0 = pack2(wv.x, wv.x), w1 = pack2(wv.y, wv.y);
                ull w2 = pack2(wv.z, wv.z), w3 = pack2(wv.w, wv.w);
                fma2(acc[0][0], xlo.x, w0); fma2(acc[0][1], xlo.x, w1);
                fma2(acc[0][2], xlo.x, w2); fma2(acc[0][3], xlo.x, w3);
                fma2(acc[1][0], xlo.y, w0); fma2(acc[1][1], xlo.y, w1);
                fma2(acc[1][2], xlo.y, w2); fma2(acc[1][3], xlo.y, w3);
                fma2(acc[2][0], xhi.x, w0); fma2(acc[2][1], xhi.x, w1);
                fma2(acc[2][2], xhi.x, w2); fma2(acc[2][3], xhi.x, w3);
                fma2(acc[3][0], xhi.y, w0); fma2(acc[3][1], xhi.y, w1);
                fma2(acc[3][2], xhi.y, w2); fma2(acc[3][3], xhi.y, w3);
            }
            __syncthreads();
        }

        if (mat != 1) {
#pragma unroll
            for (int np = 0; np < 4; np++) {
                int n0 = nodes_s[nb0 + np * 2], n1 = nodes_s[nb0 + np * 2 + 1];
                float4 o0, o1;
                unpack2(acc[np][0], o0.x, o1.x);
                unpack2(acc[np][1], o0.y, o1.y);
                unpack2(acc[np][2], o0.z, o1.z);
                unpack2(acc[np][3], o0.w, o1.w);
                if (n0 >= 0) *(float4*)&dst[n0 * DD + col0] = o0;
                if (n1 >= 0) *(float4*)&dst[n1 * DD + col0] = o1;
            }
        } else {
            // stash q half into smem (row = local col, col = node)
#pragma unroll
            for (int np = 0; np < 4; np++) {
#pragma unroll
                for (int c = 0; c < 4; c++) {
                    float lo, hi;
                    unpack2(acc[np][c], lo, hi);
                    qs[(cn * 4 + c) * XSTRIDE + nb0 + 2 * np]     = lo;
                    qs[(cn * 4 + c) * XSTRIDE + nb0 + 2 * np + 1] = hi;
                }
            }
        }
    } else {
        float4 qtmp[8];
        for (int j = 0; j < 8; j++) {
            int node = nb0 + j;
            int nd = nodes_s[node];
            int t = types_s[node];
            const float* Wt; const float* Bt;
            switch (mat) {
                case 0:  Wt = Kw + t * DD * DD; Bt = Kb + t * DD; break;
                case 1:  Wt = Qw + t * DD * DD; Bt = Qb + t * DD; break;
                case 2:  Wt = Vw + t * DD * DD; Bt = Vb + t * DD; break;
                default: Wt = g_Wsp;            Bt = g_bsp;       break;
            }
            float4 a = *(const float4*)&Bt[col0];
            for (int k = 0; k < DD; k++) {
                float xv = xs[k][node];
                float4 w = *(const float4*)&Wt[k * DD + col0];
                a.x += xv * w.x; a.y += xv * w.y; a.z += xv * w.z; a.w += xv * w.w;
            }
            if (mat != 1) {
                if (nd >= 0) *(float4*)&dst[nd * DD + col0] = a;
            } else {
                qtmp[j] = a;
            }
        }
        if (mat == 1) {
            __syncthreads();   // all xs reads done block-wide before overlay
#pragma unroll
            for (int j = 0; j < 8; j++) {
                int node = nb0 + j;
                qs[(cn * 4 + 0) * XSTRIDE + node] = qtmp[j].x;
                qs[(cn * 4 + 1) * XSTRIDE + node] = qtmp[j].y;
                qs[(cn * 4 + 2) * XSTRIDE + node] = qtmp[j].z;
                qs[(cn * 4 + 3) * XSTRIDE + node] = qtmp[j].w;
            }
        }
    }

    // ---------------- in-block q' transform (Q blocks only) -------------------
    if (mat == 1) {
        __syncthreads();       // qs fully written
        int slot = tid & 31;           // d-pair within this 64-col half
        int grp  = tid >> 5;           // 8 groups x 16 nodes
        int dloc = 2 * slot;
        int d0g  = half + dloc;
        int h    = d0g >> 4;
        int dkp  = (d0g >> 1) & 7;
        int hrow = dloc & 0x30;        // local row base of this head
        const ull* rp = g_Rp + (h * 8 + dkp) * DKK;
#pragma unroll
        for (int r = 0; r < RR; r++) {
            for (int q4 = 0; q4 < 4; q4++) {
                int jb2 = grp * 16 + q4 * 4;
                ull a0 = 0, a1 = 0, a2 = 0, a3 = 0;
#pragma unroll
                for (int f = 0; f < DKK; f++) {
                    ull w = rp[r * 1024 + f];
                    float4 qf = *(const float4*)&qs[(hrow + f) * XSTRIDE + jb2];
                    fma2(a0, pack2(qf.x, qf.x), w);
                    fma2(a1, pack2(qf.y, qf.y), w);
                    fma2(a2, pack2(qf.z, qf.z), w);
                    fma2(a3, pack2(qf.w, qf.w), w);
                }
                ull av[4] = {a0, a1, a2, a3};
#pragma unroll
                for (int j = 0; j < 4; j++) {
                    int nd = nodes_s[jb2 + j];
                    if (nd >= 0) {
                        float lo, hi;
                        unpack2(av[j], lo, hi);
                        *(float2*)&g_qt[(nd * RR + r) * DD + d0g] = make_float2(lo, hi);
                    }
                }
            }
        }
    }
}

// ------------------------------ edge setup ------------------------------------
__global__ void k_edgestats(const int* __restrict__ ei, const int* __restrict__ et, int e) {
    int i = blockIdx.x * blockDim.x + threadIdx.x;
    if (i >= e) return;
    int tgt = ei[e + i];
    int r   = et[i];
    atomicAdd(&g_thist[tgt * RR + r], 1);
    if (r == 0) atomicMax(&g_win[ei[i]], i);
}

__global__ void k_scan1(int n4) {
    __shared__ int buf[1024];
    int t = threadIdx.x;
    int gid = blockIdx.x * 1024 + t;
    int v = (gid < n4) ? g_thist[gid] : 0;
    buf[t] = v;
    __syncthreads();
    for (int off = 1; off < 1024; off <<= 1) {
        int x = (t >= off) ? buf[t - off] : 0;
        __syncthreads();
        buf[t] += x;
        __syncthreads();
    }
    if (gid < n4) g_toff[gid] = buf[t] - v;
    if (t == 1023) g_bsum[blockIdx.x] = buf[t];
}

__global__ void k_scan2(int nblocks, int n4) {
    if (threadIdx.x == 0) {
        int run = 0;
        for (int b = 0; b < nblocks; b++) { int x = g_bsum[b]; g_bsum[b] = run; run += x; }
        g_toff[n4] = run;
    }
}

__global__ void k_scan3(int n4) {
    int gid = blockIdx.x * blockDim.x + threadIdx.x;
    if (gid < n4) {
        int v = g_toff[gid] + g_bsum[gid >> 10];
        g_toff[gid] = v;
        g_tcur[gid] = v;
    }
}

__global__ void k_scatter_edges(const int* __restrict__ ei, const int* __restrict__ et,
                                const int* __restrict__ ntype, int e) {
    int i = blockIdx.x * blockDim.x + threadIdx.x;
    if (i >= e) return;
    int src = ei[i];
    int tgt = ei[e + i];
    int r   = et[i];
    int st  = ntype[src];
    int pos = atomicAdd(&g_tcur[tgt * RR + r], 1);
    g_epack[pos] = src | (st << 16);
}

// ------- attention: warp per target, per-relation sub-loops, 2-wide unroll -----
__global__ void __launch_bounds__(256)
k_attn(const int* __restrict__ ntype, const float* __restrict__ pri,
       const float* __restrict__ Rmsg, int n) {
    __shared__ float accsh[8][RR][DD];
    int warp = threadIdx.x >> 5, lane = threadIdx.x & 31;
    int i = blockIdx.x * 8 + warp;
    if (i >= n) return;
    int d0 = lane * 4;
    int h  = lane >> 2;

    int tt = ntype[i];
    float p0[TT], p1[TT], p2[TT], p3[TT];
#pragma unroll
    for (int st = 0; st < TT; st++) {
        p0[st] = pri[((tt * RR + 0) * TT + st) * HH + h];
        p1[st] = pri[((tt * RR + 1) * TT + st) * HH + h];
        p2[st] = pri[((tt * RR + 2) * TT + st) * HH + h];
        p3[st] = pri[((tt * RR + 3) * TT + st) * HH + h];
    }

    float den = 0.f;
    float4 acc[RR];
#pragma unroll
    for (int r = 0; r < RR; r++) acc[r] = make_float4(0.f, 0.f, 0.f, 0.f);

#pragma unroll
    for (int r = 0; r < RR; r++) {
        int beg = g_toff[i * RR + r], end = g_toff[i * RR + r + 1];
        if (beg == end) continue;
        float4 qtr = *(const float4*)&g_qt[(i * RR + r) * DD + d0];
        float4 a = make_float4(0.f, 0.f, 0.f, 0.f);
        float pA = (r == 0) ? p0[0] : (r == 1) ? p1[0] : (r == 2) ? p2[0] : p3[0];
        float pB = (r == 0) ? p0[1] : (r == 1) ? p1[1] : (r == 2) ? p2[1] : p3[1];
        float pC = (r == 0) ? p0[2] : (r == 1) ? p1[2] : (r == 2) ? p2[2] : p3[2];
        int idx = beg;
        for (; idx + 2 <= end; idx += 2) {
            int pk0 = g_epack[idx];
            int pk1 = g_epack[idx + 1];
            int s0 = pk0 & 0xFFFF, st0 = pk0 >> 16;
            int s1 = pk1 & 0xFFFF, st1 = pk1 >> 16;
            const float4 ka = *(const float4*)&g_k[s0 * DD + d0];
            const float4 kb = *(const float4*)&g_k[s1 * DD + d0];
            const float4 va = *(const float4*)&g_v[s0 * DD + d0];
            const float4 vb = *(const float4*)&g_v[s1 * DD + d0];
            float sa = qtr.x * ka.x + qtr.y * ka.y + qtr.z * ka.z + qtr.w * ka.w;
            float sb = qtr.x * kb.x + qtr.y * kb.y + qtr.z * kb.z + qtr.w * kb.w;
            sa += __shfl_xor_sync(0xffffffffu, sa, 1);
            sb += __shfl_xor_sync(0xffffffffu, sb, 1);
            sa += __shfl_xor_sync(0xffffffffu, sa, 2);
            sb += __shfl_xor_sync(0xffffffffu, sb, 2);
            float pra = (st0 == 1) ? pB : (st0 == 2) ? pC : pA;
            float prb = (st1 == 1) ? pB : (st1 == 2) ? pC : pA;
            float pea = __expf(sa * pra * 0.25f);
            float peb = __expf(sb * prb * 0.25f);
            den += pea + peb;
            a.x += pea * va.x + peb * vb.x;
            a.y += pea * va.y + peb * vb.y;
            a.z += pea * va.z + peb * vb.z;
            a.w += pea * va.w + peb * vb.w;
        }
        if (idx < end) {
            int pk  = g_epack[idx];
            int src = pk & 0xFFFF;
            int st  = pk >> 16;
            const float4 k4 = *(const float4*)&g_k[src * DD + d0];
            float s = qtr.x * k4.x + qtr.y * k4.y + qtr.z * k4.z + qtr.w * k4.w;
            s += __shfl_xor_sync(0xffffffffu, s, 1);
            s += __shfl_xor_sync(0xffffffffu, s, 2);
            float pr = (st == 1) ? pB : (st == 2) ? pC : pA;
            float pe = __expf(s * pr * 0.25f);
            den += pe;
            const float4 v4 = *(const float4*)&g_v[src * DD + d0];
            a.x += pe * v4.x;
            a.y += pe * v4.y;
            a.z += pe * v4.z;
            a.w += pe * v4.w;
        }
        acc[r] = a;
    }

    float inv = 1.f / (den + 1e-16f);
#pragma unroll
    for (int r = 0; r < RR; r++) {
        accsh[warp][r][d0 + 0] = acc[r].x * inv;
        accsh[warp][r][d0 + 1] = acc[r].y * inv;
        accsh[warp][r][d0 + 2] = acc[r].z * inv;
        accsh[warp][r][d0 + 3] = acc[r].w * inv;
    }
    __syncwarp();

    int f0 = (lane & 3) * 4;
    float4 o = make_float4(0.f, 0.f, 0.f, 0.f);
#pragma unroll
    for (int r = 0; r < RR; r++) {
#pragma unroll 4
        for (int dk = 0; dk < DKK; dk++) {
            float a = accsh[warp][r][(h << 4) + dk];
            const float4 w = *(const float4*)&Rmsg[(((r * HH + h) * DKK + dk) * DKK) + f0];
            o.x += a * w.x;
            o.y += a * w.y;
            o.z += a * w.z;
            o.w += a * w.w;
        }
    }
    *(float4*)&g_aggr[i * DD + d0] = o;
}

// ------------- final: speaker add + GELU + per-type A projection + skip -------
__global__ void __launch_bounds__(256, 3)
k_final(const float* __restrict__ x, const int* __restrict__ ntype,
        const int* __restrict__ ei,
        const float* __restrict__ Aw, const float* __restrict__ Ab,
        const float* __restrict__ skip, float* __restrict__ out, int n, int e) {
    __shared__ __align__(16) float gsN[DD][GST];
    __shared__ int nodes_s[NPB], types_s[NPB], spsrc_s[NPB];
    int tid  = threadIdx.x;
    int base = blockIdx.x * NPB;
    if (tid < NPB) {
        int idx = base + tid;
        int cidx = (idx < n) ? idx : (n - 1);
        int nd = (idx < n) ? g_perm[idx] : -1;
        nodes_s[tid] = nd;
        types_s[tid] = ntype[g_perm[cidx]];
        int sps = -1;
        if (nd >= 0) {
            int we = g_win[nd];
            if (we >= 0) sps = ei[e + we];
        }
        spsrc_s[tid] = sps;
    }
    __syncthreads();

    for (int idx = tid; idx < NPB * DD; idx += 256) {
        int j = idx >> 7;
        int k = idx & 127;
        int nd = nodes_s[j];
        float v = 0.f;
        if (nd >= 0) {
            v = g_aggr[nd * DD + k];
            int sps = spsrc_s[j];
            if (sps >= 0) v += g_sp[sps * DD + k];
            v = 0.5f * v * (1.f + erff(v * 0.70710678118654752f));
        }
        gsN[k][j] = v;
    }
    __syncthreads();

    int g  = tid >> 6;
    int p  = tid & 63;
    int d0 = 2 * p;
    int jb = g * 8;

    int t0 = types_s[0];
    bool uniform = true;
#pragma unroll
    for (int j = 1; j < NPB; j++) uniform &= (types_s[j] == t0);

    if (uniform) {
        const float* pA = Aw + t0 * DD * DD + d0;
        ull bA = *(const ull*)&Ab[t0 * DD + d0];
        ull aA[8];
#pragma unroll
        for (int j = 0; j < 8; j++) aA[j] = bA;
#pragma unroll 4
        for (int k = 0; k < DD; k++) {
            ull w2 = *(const ull*)&pA[k * DD];
            float4 q0 = *(const float4*)&gsN[k][jb];
            float4 q1 = *(const float4*)&gsN[k][jb + 4];
            fma2(aA[0], pack2(q0.x, q0.x), w2);
            fma2(aA[1], pack2(q0.y, q0.y), w2);
            fma2(aA[2], pack2(q0.z, q0.z), w2);
            fma2(aA[3], pack2(q0.w, q0.w), w2);
            fma2(aA[4], pack2(q1.x, q1.x), w2);
            fma2(aA[5], pack2(q1.y, q1.y), w2);
            fma2(aA[6], pack2(q1.z, q1.z), w2);
            fma2(aA[7], pack2(q1.w, q1.w), w2);
        }
        float sk = skip[t0];
        float alpha = 1.f / (1.f + __expf(-sk));
        float beta  = 1.f - alpha;
#pragma unroll
        for (int j = 0; j < 8; j++) {
            int nd = nodes_s[jb + j];
            if (nd < 0) continue;
            float lo, hi;
            unpack2(aA[j], lo, hi);
            float2 xv = *(const float2*)&x[nd * DD + d0];
            *(float2*)&out[nd * DD + d0] =
                make_float2(lo * alpha + xv.x * beta, hi * alpha + xv.y * beta);
        }
    } else {
        for (int j = 0; j < 8; j++) {
            int nd = nodes_s[jb + j];
            if (nd < 0) continue;
            int t = types_s[jb + j];
            float2 aA = *(const float2*)&Ab[t * DD + d0];
            for (int k = 0; k < DD; k++) {
                float gv = gsN[k][jb + j];
                float2 w = *(const float2*)&Aw[(t * DD + k) * DD + d0];
                aA.x += gv * w.x; aA.y += gv * w.y;
            }
            float sk = skip[t];
            float alpha = 1.f / (1.f + __expf(-sk));
            float beta  = 1.f - alpha;
            float2 xv = *(const float2*)&x[nd * DD + d0];
            *(float2*)&out[nd * DD + d0] =
                make_float2(aA.x * alpha + xv.x * beta, aA.y * alpha + xv.y * beta);
        }
    }
}

// --------------------------------- launcher -----------------------------------
extern "C" void kernel_launch(void* const* d_in, const int* in_sizes, int n_in,
                              void* d_out, int out_size) {
    const float* node_inp  = (const float*)d_in[0];
    const int*   node_type = (const int*)  d_in[1];
    const int*   edge_index= (const int*)  d_in[2];
    const int*   edge_type = (const int*)  d_in[3];
    const float* Kw = (const float*)d_in[5];
    const float* Kb = (const float*)d_in[6];
    const float* Qw = (const float*)d_in[7];
    const float* Qb = (const float*)d_in[8];
    const float* Vw = (const float*)d_in[9];
    const float* Vb = (const float*)d_in[10];
    const float* Aw = (const float*)d_in[11];
    const float* Ab = (const float*)d_in[12];
    const float* pri  = (const float*)d_in[13];
    const float* Ratt = (const float*)d_in[14];
    const float* Rmsg = (const float*)d_in[15];
    const float* s2u  = (const float*)d_in[16];
    const float* skip = (const float*)d_in[17];
    float* out = (float*)d_out;

    int n = in_sizes[1];
    int e = in_sizes[3];
    if (n > NMAX) n = NMAX;
    if (e > EMAX) e = EMAX;
    int n4 = n * RR;

    int nb  = (n + 255) / 256;
    int n4b = (n4 + 255) / 256;
    int eb  = (e + 255) / 256;
    int sb  = (n4 + 1023) / 1024;
    int ngb = (n + GN - 1) / GN;

    cudaFuncSetAttribute(k_gemm_proj, cudaFuncAttributeMaxDynamicSharedMemorySize, SMEM_GEMM);

    k_init<<<n4b + 65 + 16, 256>>>(Vw, Vb, s2u, Ratt, n, n4b);
    k_nodehist<<<nb, 256>>>(node_type, n);
    k_nodescatter<<<nb, 256>>>(node_type, n);
    k_gemm_proj<<<dim3(ngb, 8), 256, SMEM_GEMM>>>(node_inp, node_type,
                                                  Kw, Kb, Qw, Qb, Vw, Vb, n);
    k_edgestats<<<eb, 256>>>(edge_index, edge_type, e);
    k_scan1<<<sb, 1024>>>(n4);
    k_scan2<<<1, 32>>>(sb, n4);
    k_scan3<<<n4b, 256>>>(n4);
    k_scatter_edges<<<eb, 256>>>(edge_index, edge_type, node_type, e);
    k_attn<<<(n + 7) / 8, 256>>>(node_type, pri, Rmsg, n);
    k_final<<<(n + NPB - 1) / NPB, 256>>>(node_inp, node_type, edge_index,
                                          Aw, Ab, skip, out, n, e);
}

// round 12
// speedup vs baseline: 1.2282x; 1.0142x over previous
#include <cuda_runtime.h>
#include <math.h>

#define NMAX 40000
#define EMAX 640000
#define DD   128
#define HH   8
#define DKK  16
#define TT   3
#define RR   4
#define N4   (NMAX * RR)

#define GN      128            // nodes per gemm block
#define XSTRIDE 132            // xs row stride (floats)
#define KTILE   32
#define NTILE   (DD / KTILE)
#define XS_BYTES (DD * XSTRIDE * 4)
#define WB_BYTES (2 * KTILE * 64 * 4)
#define SMEM_GEMM (XS_BYTES + WB_BYTES + GN * 2 * 4)
#define QST     68             // node-major q stash row stride (floats)

#define NPB  32              // nodes per final block
#define GST  36              // gsN row stride (floats)

typedef unsigned long long ull;

// ---------------- scratch (device globals) ------------------------------------
__device__ float g_k   [NMAX * DD];
__device__ float g_v   [NMAX * DD];
__device__ float g_qt  [NMAX * RR * DD];
__device__ float g_sp  [NMAX * DD];
__device__ float g_aggr[NMAX * DD];
__device__ float g_Wsp [DD * DD];
__device__ float g_bsp [DD];
__device__ ull   g_Rp  [RR * HH * 8 * DKK];
__device__ int   g_win [NMAX];
__device__ int   g_thist[N4];
__device__ int   g_toff [N4 + 1];
__device__ int   g_tcur [N4];
__device__ int   g_epack[EMAX];
__device__ int   g_bsum [256];
__device__ int   g_typehist[TT];
__device__ int   g_typecur [TT];
__device__ int   g_perm [NMAX];

// ---------------- packed f32x2 helpers ----------------------------------------
__device__ __forceinline__ ull pack2(float a, float b) {
    ull r;
    asm("mov.b64 %0, {%1, %2};" : "=l"(r) : "f"(a), "f"(b));
    return r;
}
__device__ __forceinline__ void unpack2(ull v, float& lo, float& hi) {
    asm("mov.b64 {%0, %1}, %2;" : "=f"(lo), "=f"(hi) : "l"(v));
}
__device__ __forceinline__ void fma2(ull& acc, ull x, ull w) {
    asm("fma.rn.f32x2 %0, %1, %2, %0;" : "+l"(acc) : "l"(x), "l"(w));
}
__device__ __forceinline__ void cpasync16(void* dst, const void* src) {
    unsigned int da = (unsigned int)__cvta_generic_to_shared(dst);
    asm volatile("cp.async.cg.shared.global [%0], [%1], 16;"
                 :: "r"(da), "l"(src) : "memory");
}

// ------------------ init: zero hists + Wsp + packed Ratt ----------------------
__global__ void k_init(const float* __restrict__ Vw, const float* __restrict__ Vb,
                       const float* __restrict__ s2u, const float* __restrict__ Ratt,
                       int n, int zb) {
    int b = blockIdx.x;
    if (b < zb) {
        int i = b * 256 + threadIdx.x;
        if (i < n) g_win[i] = -1;
        if (i < 4 * n) g_thist[i] = 0;
        if (i < TT) { g_typehist[i] = 0; g_typecur[i] = 0; }
    } else if (b < zb + 65) {
        int bi  = b - zb;
        int row = bi * 2 + (threadIdx.x >> 7);
        int d   = threadIdx.x & 127;
        if (row < DD) {
            float acc = 0.f;
            for (int m = 0; m < DD; m++)
                acc += Vw[(DD + row) * DD + m] * s2u[m * DD + d];
            g_Wsp[row * DD + d] = acc;
        } else if (row == DD) {
            float acc = 0.f;
            for (int m = 0; m < DD; m++)
                acc += Vb[DD + m] * s2u[m * DD + d];
            g_bsp[d] = acc;
        }
    } else {
        int idx = (b - zb - 65) * 256 + threadIdx.x;
        if (idx < RR * HH * 8 * DKK) {
            int f   = idx & 15;
            int dkp = (idx >> 4) & 7;
            int h   = (idx >> 7) & 7;
            int r   = idx >> 10;
            float a0 = Ratt[((r * HH + h) * DKK + 2 * dkp)     * DKK + f];
            float a1 = Ratt[((r * HH + h) * DKK + 2 * dkp + 1) * DKK + f];
            g_Rp[idx] = pack2(a0, a1);
        }
    }
}

__global__ void k_nodehist(const int* __restrict__ ntype, int n) {
    int i = blockIdx.x * blockDim.x + threadIdx.x;
    if (i < n) atomicAdd(&g_typehist[ntype[i]], 1);
}

__global__ void k_nodescatter(const int* __restrict__ ntype, int n) {
    int i = blockIdx.x * blockDim.x + threadIdx.x;
    if (i >= n) return;
    int t = ntype[i];
    int off = 0;
    for (int ty = 0; ty < TT; ty++) if (ty < t) off += g_typehist[ty];
    int pos = off + atomicAdd(&g_typecur[t], 1);
    g_perm[pos] = i;
}

// ----------------- register-tiled GEMM: K/Q/V/speaker projections -------------
// grid: (ceil(n/128), 8). matrix = y>>1 in {K,Q,V,Wsp}, half = (y&1)*64.
// Q blocks (mat==1) compute the per-relation q' transform in-block and write
// g_qt directly (each 64-col half holds 4 complete heads).
__global__ void __launch_bounds__(256, 2)
k_gemm_proj(const float* __restrict__ x, const int* __restrict__ ntype,
            const float* __restrict__ Kw, const float* __restrict__ Kb,
            const float* __restrict__ Qw, const float* __restrict__ Qb,
            const float* __restrict__ Vw, const float* __restrict__ Vb, int n) {
    extern __shared__ __align__(16) unsigned char sraw[];
    float (*xs)[XSTRIDE] = (float (*)[XSTRIDE])sraw;
    float* qs = (float*)sraw;                     // overlay: node-major q stash
    float (*wbuf)[KTILE][64] = (float (*)[KTILE][64])(sraw + XS_BYTES);
    int* nodes_s = (int*)(sraw + XS_BYTES + WB_BYTES);
    int* types_s = nodes_s + GN;
    __shared__ int s_uni;

    int tid  = threadIdx.x;
    int base = blockIdx.x * GN;
    if (tid == 0) s_uni = 1;
    if (tid < GN) {
        int idx  = base + tid;
        int cidx = (idx < n) ? idx : (n - 1);
        nodes_s[tid] = (idx < n) ? g_perm[idx] : -1;
        types_s[tid] = ntype[g_perm[cidx]];
    }
    __syncthreads();
    if (tid < GN && types_s[tid] != types_s[0]) s_uni = 0;
    __syncthreads();
    int  t0      = types_s[0];
    bool uniform = (s_uni != 0);

    int mat  = blockIdx.y >> 1;
    int half = (blockIdx.y & 1) * 64;
    const float* W; const float* B; float* dst;
    switch (mat) {
        case 0:  W = Kw + t0 * DD * DD; B = Kb + t0 * DD; dst = g_k;  break;
        case 1:  W = Qw + t0 * DD * DD; B = Qb + t0 * DD; dst = 0;    break;
        case 2:  W = Vw + t0 * DD * DD; B = Vb + t0 * DD; dst = g_v;  break;
        default: W = g_Wsp;             B = g_bsp;        dst = g_sp; break;
    }

    if (uniform) {
#pragma unroll
        for (int q = 0; q < 2; q++) {
            int f4  = tid + q * 256;
            int row = f4 >> 4;
            int c4  = f4 & 15;
            cpasync16(&wbuf[0][row][c4 * 4], W + row * DD + half + c4 * 4);
        }
        asm volatile("cp.async.commit_group;" ::: "memory");
    }

    // stage x transposed
#pragma unroll 4
    for (int it = 0; it < 16; it++) {
        int f4 = tid + it * 256;
        int j  = f4 >> 5;
        int c4 = f4 & 31;
        int nd = nodes_s[j];
        float4 v = (nd >= 0) ? *(const float4*)&x[nd * DD + c4 * 4]
                             : make_float4(0.f, 0.f, 0.f, 0.f);
        xs[c4 * 4 + 0][j] = v.x;
        xs[c4 * 4 + 1][j] = v.y;
        xs[c4 * 4 + 2][j] = v.z;
        xs[c4 * 4 + 3][j] = v.w;
    }
    __syncthreads();

    int cn = tid & 15, nn = tid >> 4;
    int col0 = half + cn * 4;
    int nb0  = nn * 8;

    if (uniform) {
        float4 bv = *(const float4*)&B[col0];
        ull bb0 = pack2(bv.x, bv.x), bb1 = pack2(bv.y, bv.y);
        ull bb2 = pack2(bv.z, bv.z), bb3 = pack2(bv.w, bv.w);
        ull acc[4][4];
#pragma unroll
        for (int np = 0; np < 4; np++) {
            acc[np][0] = bb0; acc[np][1] = bb1; acc[np][2] = bb2; acc[np][3] = bb3;
        }

        for (int tile = 0; tile < NTILE; tile++) {
            if (tile + 1 < NTILE) {
                int stg = (tile + 1) & 1;
#pragma unroll
                for (int q = 0; q < 2; q++) {
                    int f4  = tid + q * 256;
                    int row = f4 >> 4;
                    int c4  = f4 & 15;
                    cpasync16(&wbuf[stg][row][c4 * 4],
                              W + ((tile + 1) * KTILE + row) * DD + half + c4 * 4);
                }
                asm volatile("cp.async.commit_group;" ::: "memory");
                asm volatile("cp.async.wait_group 1;" ::: "memory");
            } else {
                asm volatile("cp.async.wait_group 0;" ::: "memory");
            }
            __syncthreads();
            int cur = tile & 1;
#pragma unroll
            for (int kk = 0; kk < KTILE; kk++) {
                int k = tile * KTILE + kk;
                ulonglong2 xlo = *(const ulonglong2*)&xs[k][nb0];
                ulonglong2 xhi = *(const ulonglong2*)&xs[k][nb0 + 4];
                float4 wv = *(const float4*)&wbuf[cur][kk][cn * 4];
                ull w0 = pack2(wv.x, wv.x), w1 = pack2(wv.y, wv.y);
                ull w2 = pack2(wv.z, wv.z), w3 = pack2(wv.w, wv.w);
                fma2(acc[0][0], xlo.x, w0); fma2(acc[0][1], xlo.x, w1);
                fma2(acc[0][2], xlo.x, w2); fma2(acc[0][3], xlo.x, w3);
                fma2(acc[1][0], xlo.y, w0); fma2(acc[1][1], xlo.y, w1);
                fma2(acc[1][2], xlo.y, w2); fma2(acc[1][3], xlo.y, w3);
                fma2(acc[2][0], xhi.x, w0); fma2(acc[2][1], xhi.x, w1);
                fma2(acc[2][2], xhi.x, w2); fma2(acc[2][3], xhi.x, w3);
                fma2(acc[3][0], xhi.y, w0); fma2(acc[3][1], xhi.y, w1);
                fma2(acc[3][2], xhi.y, w2); fma2(acc[3][3], xhi.y, w3);
            }
            __syncthreads();
        }

        if (mat != 1) {
#pragma unroll
            for (int np = 0; np < 4; np++) {
                int n0 = nodes_s[nb0 + np * 2], n1 = nodes_s[nb0 + np * 2 + 1];
                float4 o0, o1;
                unpack2(acc[np][0], o0.x, o1.x);
                unpack2(acc[np][1], o0.y, o1.y);
                unpack2(acc[np][2], o0.z, o1.z);
                unpack2(acc[np][3], o0.w, o1.w);
                if (n0 >= 0) *(float4*)&dst[n0 * DD + col0] = o0;
                if (n1 >= 0) *(float4*)&dst[n1 * DD + col0] = o1;
            }
        } else {
            // stash q half into smem, node-major: qs[node*QST + localcol]
            // (xs reads all complete: tile loop ends with __syncthreads)
#pragma unroll
            for (int np = 0; np < 4; np++) {
                int j0 = nb0 + np * 2;
                float4 o0, o1;
                unpack2(acc[np][0], o0.x, o1.x);
                unpack2(acc[np][1], o0.y, o1.y);
                unpack2(acc[np][2], o0.z, o1.z);
                unpack2(acc[np][3], o0.w, o1.w);
                *(float4*)&qs[j0 * QST + cn * 4]       = o0;
                *(float4*)&qs[(j0 + 1) * QST + cn * 4] = o1;
            }
        }
    } else {
        float4 qtmp[8];
        for (int j = 0; j < 8; j++) {
            int node = nb0 + j;
            int nd = nodes_s[node];
            int t = types_s[node];
            const float* Wt; const float* Bt;
            switch (mat) {
                case 0:  Wt = Kw + t * DD * DD; Bt = Kb + t * DD; break;
                case 1:  Wt = Qw + t * DD * DD; Bt = Qb + t * DD; break;
                case 2:  Wt = Vw + t * DD * DD; Bt = Vb + t * DD; break;
                default: Wt = g_Wsp;            Bt = g_bsp;       break;
            }
            float4 a = *(const float4*)&Bt[col0];
            for (int k = 0; k < DD; k++) {
                float xv = xs[k][node];
                float4 w = *(const float4*)&Wt[k * DD + col0];
                a.x += xv * w.x; a.y += xv * w.y; a.z += xv * w.z; a.w += xv * w.w;
            }
            if (mat != 1) {
                if (nd >= 0) *(float4*)&dst[nd * DD + col0] = a;
            } else {
                qtmp[j] = a;
            }
        }
        if (mat == 1) {
            __syncthreads();   // all xs reads done block-wide before overlay
#pragma unroll
            for (int j = 0; j < 8; j++) {
                *(float4*)&qs[(nb0 + j) * QST + cn * 4] = qtmp[j];
            }
        }
    }

    // ---------------- in-block q' transform (Q blocks only) -------------------
    if (mat == 1) {
        __syncthreads();       // qs fully written
        int slot = tid & 31;           // d-pair within this 64-col half
        int grp  = tid >> 5;           // 8 groups x 16 nodes
        int dloc = 2 * slot;
        int d0g  = half + dloc;
        int h    = d0g >> 4;
        int dkp  = (d0g >> 1) & 7;
        int hrow = dloc & 0x30;        // local col base of this head
        const ull* rp = g_Rp + (h * 8 + dkp) * DKK;
#pragma unroll
        for (int r = 0; r < RR; r++) {
            ull w[DKK];
#pragma unroll
            for (int f = 0; f < DKK; f++) w[f] = rp[r * 1024 + f];
            for (int jj = 0; jj < 16; jj++) {
                int jloc = grp * 16 + jj;
                int nd   = nodes_s[jloc];
                const float* qrow = &qs[jloc * QST + hrow];
                float4 q0 = *(const float4*)&qrow[0];
                float4 q1 = *(const float4*)&qrow[4];
                float4 q2 = *(const float4*)&qrow[8];
                float4 q3 = *(const float4*)&qrow[12];
                ull acc = 0;
                fma2(acc, pack2(q0.x, q0.x), w[0]);
                fma2(acc, pack2(q0.y, q0.y), w[1]);
                fma2(acc, pack2(q0.z, q0.z), w[2]);
                fma2(acc, pack2(q0.w, q0.w), w[3]);
                fma2(acc, pack2(q1.x, q1.x), w[4]);
                fma2(acc, pack2(q1.y, q1.y), w[5]);
                fma2(acc, pack2(q1.z, q1.z), w[6]);
                fma2(acc, pack2(q1.w, q1.w), w[7]);
                fma2(acc, pack2(q2.x, q2.x), w[8]);
                fma2(acc, pack2(q2.y, q2.y), w[9]);
                fma2(acc, pack2(q2.z, q2.z), w[10]);
                fma2(acc, pack2(q2.w, q2.w), w[11]);
                fma2(acc, pack2(q3.x, q3.x), w[12]);
                fma2(acc, pack2(q3.y, q3.y), w[13]);
                fma2(acc, pack2(q3.z, q3.z), w[14]);
                fma2(acc, pack2(q3.w, q3.w), w[15]);
                if (nd >= 0) {
                    float lo, hi;
                    unpack2(acc, lo, hi);
                    *(float2*)&g_qt[(nd * RR + r) * DD + d0g] = make_float2(lo, hi);
                }
            }
        }
    }
}

// ------------------------------ edge setup ------------------------------------
__global__ void k_edgestats(const int* __restrict__ ei, const int* __restrict__ et, int e) {
    int i = blockIdx.x * blockDim.x + threadIdx.x;
    if (i >= e) return;
    int tgt = ei[e + i];
    int r   = et[i];
    atomicAdd(&g_thist[tgt * RR + r], 1);
    if (r == 0) atomicMax(&g_win[ei[i]], i);
}

__global__ void k_scan1(int n4) {
    __shared__ int buf[1024];
    int t = threadIdx.x;
    int gid = blockIdx.x * 1024 + t;
    int v = (gid < n4) ? g_thist[gid] : 0;
    buf[t] = v;
    __syncthreads();
    for (int off = 1; off < 1024; off <<= 1) {
        int x = (t >= off) ? buf[t - off] : 0;
        __syncthreads();
        buf[t] += x;
        __syncthreads();
    }
    if (gid < n4) g_toff[gid] = buf[t] - v;
    if (t == 1023) g_bsum[blockIdx.x] = buf[t];
}

__global__ void k_scan2(int nblocks, int n4) {
    if (threadIdx.x == 0) {
        int run = 0;
        for (int b = 0; b < nblocks; b++) { int x = g_bsum[b]; g_bsum[b] = run; run += x; }
        g_toff[n4] = run;
    }
}

__global__ void k_scan3(int n4) {
    int gid = blockIdx.x * blockDim.x + threadIdx.x;
    if (gid < n4) {
        int v = g_toff[gid] + g_bsum[gid >> 10];
        g_toff[gid] = v;
        g_tcur[gid] = v;
    }
}

__global__ void k_scatter_edges(const int* __restrict__ ei, const int* __restrict__ et,
                                const int* __restrict__ ntype, int e) {
    int i = blockIdx.x * blockDim.x + threadIdx.x;
    if (i >= e) return;
    int src = ei[i];
    int tgt = ei[e + i];
    int r   = et[i];
    int st  = ntype[src];
    int pos = atomicAdd(&g_tcur[tgt * RR + r], 1);
    g_epack[pos] = src | (st << 16);
}

// ------- attention: warp per target, per-relation sub-loops, 2-wide unroll -----
__global__ void __launch_bounds__(256)
k_attn(const int* __restrict__ ntype, const float* __restrict__ pri,
       const float* __restrict__ Rmsg, int n) {
    __shared__ float accsh[8][RR][DD];
    int warp = threadIdx.x >> 5, lane = threadIdx.x & 31;
    int i = blockIdx.x * 8 + warp;
    if (i >= n) return;
    int d0 = lane * 4;
    int h  = lane >> 2;

    int tt = ntype[i];
    float p0[TT], p1[TT], p2[TT], p3[TT];
#pragma unroll
    for (int st = 0; st < TT; st++) {
        p0[st] = pri[((tt * RR + 0) * TT + st) * HH + h];
        p1[st] = pri[((tt * RR + 1) * TT + st) * HH + h];
        p2[st] = pri[((tt * RR + 2) * TT + st) * HH + h];
        p3[st] = pri[((tt * RR + 3) * TT + st) * HH + h];
    }

    float den = 0.f;
    float4 acc[RR];
#pragma unroll
    for (int r = 0; r < RR; r++) acc[r] = make_float4(0.f, 0.f, 0.f, 0.f);

#pragma unroll
    for (int r = 0; r < RR; r++) {
        int beg = g_toff[i * RR + r], end = g_toff[i * RR + r + 1];
        if (beg == end) continue;
        float4 qtr = *(const float4*)&g_qt[(i * RR + r) * DD + d0];
        float4 a = make_float4(0.f, 0.f, 0.f, 0.f);
        float pA = (r == 0) ? p0[0] : (r == 1) ? p1[0] : (r == 2) ? p2[0] : p3[0];
        float pB = (r == 0) ? p0[1] : (r == 1) ? p1[1] : (r == 2) ? p2[1] : p3[1];
        float pC = (r == 0) ? p0[2] : (r == 1) ? p1[2] : (r == 2) ? p2[2] : p3[2];
        int idx = beg;
        for (; idx + 2 <= end; idx += 2) {
            int pk0 = g_epack[idx];
            int pk1 = g_epack[idx + 1];
            int s0 = pk0 & 0xFFFF, st0 = pk0 >> 16;
            int s1 = pk1 & 0xFFFF, st1 = pk1 >> 16;
            const float4 ka = *(const float4*)&g_k[s0 * DD + d0];
            const float4 kb = *(const float4*)&g_k[s1 * DD + d0];
            const float4 va = *(const float4*)&g_v[s0 * DD + d0];
            const float4 vb = *(const float4*)&g_v[s1 * DD + d0];
            float sa = qtr.x * ka.x + qtr.y * ka.y + qtr.z * ka.z + qtr.w * ka.w;
            float sb = qtr.x * kb.x + qtr.y * kb.y + qtr.z * kb.z + qtr.w * kb.w;
            sa += __shfl_xor_sync(0xffffffffu, sa, 1);
            sb += __shfl_xor_sync(0xffffffffu, sb, 1);
            sa += __shfl_xor_sync(0xffffffffu, sa, 2);
            sb += __shfl_xor_sync(0xffffffffu, sb, 2);
            float pra = (st0 == 1) ? pB : (st0 == 2) ? pC : pA;
            float prb = (st1 == 1) ? pB : (st1 == 2) ? pC : pA;
            float pea = __expf(sa * pra * 0.25f);
            float peb = __expf(sb * prb * 0.25f);
            den += pea + peb;
            a.x += pea * va.x + peb * vb.x;
            a.y += pea * va.y + peb * vb.y;
            a.z += pea * va.z + peb * vb.z;
            a.w += pea * va.w + peb * vb.w;
        }
        if (idx < end) {
            int pk  = g_epack[idx];
            int src = pk & 0xFFFF;
            int st  = pk >> 16;
            const float4 k4 = *(const float4*)&g_k[src * DD + d0];
            float s = qtr.x * k4.x + qtr.y * k4.y + qtr.z * k4.z + qtr.w * k4.w;
            s += __shfl_xor_sync(0xffffffffu, s, 1);
            s += __shfl_xor_sync(0xffffffffu, s, 2);
            float pr = (st == 1) ? pB : (st == 2) ? pC : pA;
            float pe = __expf(s * pr * 0.25f);
            den += pe;
            const float4 v4 = *(const float4*)&g_v[src * DD + d0];
            a.x += pe * v4.x;
            a.y += pe * v4.y;
            a.z += pe * v4.z;
            a.w += pe * v4.w;
        }
        acc[r] = a;
    }

    float inv = 1.f / (den + 1e-16f);
#pragma unroll
    for (int r = 0; r < RR; r++) {
        accsh[warp][r][d0 + 0] = acc[r].x * inv;
        accsh[warp][r][d0 + 1] = acc[r].y * inv;
        accsh[warp][r][d0 + 2] = acc[r].z * inv;
        accsh[warp][r][d0 + 3] = acc[r].w * inv;
    }
    __syncwarp();

    int f0 = (lane & 3) * 4;
    float4 o = make_float4(0.f, 0.f, 0.f, 0.f);
#pragma unroll
    for (int r = 0; r < RR; r++) {
#pragma unroll 4
        for (int dk = 0; dk < DKK; dk++) {
            float a = accsh[warp][r][(h << 4) + dk];
            const float4 w = *(const float4*)&Rmsg[(((r * HH + h) * DKK + dk) * DKK) + f0];
            o.x += a * w.x;
            o.y += a * w.y;
            o.z += a * w.z;
            o.w += a * w.w;
        }
    }
    *(float4*)&g_aggr[i * DD + d0] = o;
}

// ------------- final: speaker add + GELU + per-type A projection + skip -------
__global__ void __launch_bounds__(256, 3)
k_final(const float* __restrict__ x, const int* __restrict__ ntype,
        const int* __restrict__ ei,
        const float* __restrict__ Aw, const float* __restrict__ Ab,
        const float* __restrict__ skip, float* __restrict__ out, int n, int e) {
    __shared__ __align__(16) float gsN[DD][GST];
    __shared__ int nodes_s[NPB], types_s[NPB], spsrc_s[NPB];
    int tid  = threadIdx.x;
    int base = blockIdx.x * NPB;
    if (tid < NPB) {
        int idx = base + tid;
        int cidx = (idx < n) ? idx : (n - 1);
        int nd = (idx < n) ? g_perm[idx] : -1;
        nodes_s[tid] = nd;
        types_s[tid] = ntype[g_perm[cidx]];
        int sps = -1;
        if (nd >= 0) {
            int we = g_win[nd];
            if (we >= 0) sps = ei[e + we];
        }
        spsrc_s[tid] = sps;
    }
    __syncthreads();

    for (int idx = tid; idx < NPB * DD; idx += 256) {
        int j = idx >> 7;
        int k = idx & 127;
        int nd = nodes_s[j];
        float v = 0.f;
        if (nd >= 0) {
            v = g_aggr[nd * DD + k];
            int sps = spsrc_s[j];
            if (sps >= 0) v += g_sp[sps * DD + k];
            v = 0.5f * v * (1.f + erff(v * 0.70710678118654752f));
        }
        gsN[k][j] = v;
    }
    __syncthreads();

    int g  = tid >> 6;
    int p  = tid & 63;
    int d0 = 2 * p;
    int jb = g * 8;

    int t0 = types_s[0];
    bool uniform = true;
#pragma unroll
    for (int j = 1; j < NPB; j++) uniform &= (types_s[j] == t0);

    if (uniform) {
        const float* pA = Aw + t0 * DD * DD + d0;
        ull bA = *(const ull*)&Ab[t0 * DD + d0];
        ull aA[8];
#pragma unroll
        for (int j = 0; j < 8; j++) aA[j] = bA;
#pragma unroll 4
        for (int k = 0; k < DD; k++) {
            ull w2 = *(const ull*)&pA[k * DD];
            float4 q0 = *(const float4*)&gsN[k][jb];
            float4 q1 = *(const float4*)&gsN[k][jb + 4];
            fma2(aA[0], pack2(q0.x, q0.x), w2);
            fma2(aA[1], pack2(q0.y, q0.y), w2);
            fma2(aA[2], pack2(q0.z, q0.z), w2);
            fma2(aA[3], pack2(q0.w, q0.w), w2);
            fma2(aA[4], pack2(q1.x, q1.x), w2);
            fma2(aA[5], pack2(q1.y, q1.y), w2);
            fma2(aA[6], pack2(q1.z, q1.z), w2);
            fma2(aA[7], pack2(q1.w, q1.w), w2);
        }
        float sk = skip[t0];
        float alpha = 1.f / (1.f + __expf(-sk));
        float beta  = 1.f - alpha;
#pragma unroll
        for (int j = 0; j < 8; j++) {
            int nd = nodes_s[jb + j];
            if (nd < 0) continue;
            float lo, hi;
            unpack2(aA[j], lo, hi);
            float2 xv = *(const float2*)&x[nd * DD + d0];
            *(float2*)&out[nd * DD + d0] =
                make_float2(lo * alpha + xv.x * beta, hi * alpha + xv.y * beta);
        }
    } else {
        for (int j = 0; j < 8; j++) {
            int nd = nodes_s[jb + j];
            if (nd < 0) continue;
            int t = types_s[jb + j];
            float2 aA = *(const float2*)&Ab[t * DD + d0];
            for (int k = 0; k < DD; k++) {
                float gv = gsN[k][jb + j];
                float2 w = *(const float2*)&Aw[(t * DD + k) * DD + d0];
                aA.x += gv * w.x; aA.y += gv * w.y;
            }
            float sk = skip[t];
            float alpha = 1.f / (1.f + __expf(-sk));
            float beta  = 1.f - alpha;
            float2 xv = *(const float2*)&x[nd * DD + d0];
            *(float2*)&out[nd * DD + d0] =
                make_float2(aA.x * alpha + xv.x * beta, aA.y * alpha + xv.y * beta);
        }
    }
}

// --------------------------------- launcher -----------------------------------
extern "C" void kernel_launch(void* const* d_in, const int* in_sizes, int n_in,
                              void* d_out, int out_size) {
    const float* node_inp  = (const float*)d_in[0];
    const int*   node_type = (const int*)  d_in[1];
    const int*   edge_index= (const int*)  d_in[2];
    const int*   edge_type = (const int*)  d_in[3];
    const float* Kw = (const float*)d_in[5];
    const float* Kb = (const float*)d_in[6];
    const float* Qw = (const float*)d_in[7];
    const float* Qb = (const float*)d_in[8];
    const float* Vw = (const float*)d_in[9];
    const float* Vb = (const float*)d_in[10];
    const float* Aw = (const float*)d_in[11];
    const float* Ab = (const float*)d_in[12];
    const float* pri  = (const float*)d_in[13];
    const float* Ratt = (const float*)d_in[14];
    const float* Rmsg = (const float*)d_in[15];
    const float* s2u  = (const float*)d_in[16];
    const float* skip = (const float*)d_in[17];
    float* out = (float*)d_out;

    int n = in_sizes[1];
    int e = in_sizes[3];
    if (n > NMAX) n = NMAX;
    if (e > EMAX) e = EMAX;
    int n4 = n * RR;

    int nb  = (n + 255) / 256;
    int n4b = (n4 + 255) / 256;
    int eb  = (e + 255) / 256;
    int sb  = (n4 + 1023) / 1024;
    int ngb = (n + GN - 1) / GN;

    cudaFuncSetAttribute(k_gemm_proj, cudaFuncAttributeMaxDynamicSharedMemorySize, SMEM_GEMM);

    k_init<<<n4b + 65 + 16, 256>>>(Vw, Vb, s2u, Ratt, n, n4b);
    k_nodehist<<<nb, 256>>>(node_type, n);
    k_nodescatter<<<nb, 256>>>(node_type, n);
    k_gemm_proj<<<dim3(ngb, 8), 256, SMEM_GEMM>>>(node_inp, node_type,
                                                  Kw, Kb, Qw, Qb, Vw, Vb, n);
    k_edgestats<<<eb, 256>>>(edge_index, edge_type, e);
    k_scan1<<<sb, 1024>>>(n4);
    k_scan2<<<1, 32>>>(sb, n4);
    k_scan3<<<n4b, 256>>>(n4);
    k_scatter_edges<<<eb, 256>>>(edge_index, edge_type, node_type, e);
    k_attn<<<(n + 7) / 8, 256>>>(node_type, pri, Rmsg, n);
    k_final<<<(n + NPB - 1) / NPB, 256>>>(node_inp, node_type, edge_index,
                                          Aw, Ab, skip, out, n, e);
}

// round 13
// speedup vs baseline: 1.2366x; 1.0068x over previous
#include <cuda_runtime.h>
#include <math.h>

#define NMAX 40000
#define EMAX 640000
#define DD   128
#define HH   8
#define DKK  16
#define TT   3
#define RR   4
#define N4   (NMAX * RR)

#define GN      128            // nodes per gemm block
#define XSTRIDE 132            // xs row stride (floats)
#define KTILE   32
#define NTILE   (DD / KTILE)
#define XS_BYTES (DD * XSTRIDE * 4)
#define WB_BYTES (2 * KTILE * 64 * 4)
#define SMEM_GEMM (XS_BYTES + WB_BYTES + GN * 2 * 4)
#define QST     68             // node-major q stash row stride (floats)

#define NPB  32              // nodes per final block
#define GST  36              // gsN row stride (floats)

typedef unsigned long long ull;

// ---------------- scratch (device globals) ------------------------------------
__device__ float g_k   [NMAX * DD];
__device__ float g_v   [NMAX * DD];
__device__ float g_qt  [NMAX * RR * DD];
__device__ float g_sp  [NMAX * DD];
__device__ float g_aggr[NMAX * DD];
__device__ float g_Wsp [DD * DD];
__device__ float g_bsp [DD];
__device__ ull   g_Rp  [RR * HH * 8 * DKK];
__device__ int   g_win [NMAX];
__device__ int   g_thist[N4];
__device__ int   g_toff [N4 + 1];
__device__ int   g_tcur [N4];
__device__ int   g_epack[EMAX];
__device__ int   g_bsum [256];
__device__ int   g_typehist[TT];
__device__ int   g_typecur [TT];
__device__ int   g_perm [NMAX];

// ---------------- packed f32x2 helpers ----------------------------------------
__device__ __forceinline__ ull pack2(float a, float b) {
    ull r;
    asm("mov.b64 %0, {%1, %2};" : "=l"(r) : "f"(a), "f"(b));
    return r;
}
__device__ __forceinline__ void unpack2(ull v, float& lo, float& hi) {
    asm("mov.b64 {%0, %1}, %2;" : "=f"(lo), "=f"(hi) : "l"(v));
}
__device__ __forceinline__ void fma2(ull& acc, ull x, ull w) {
    asm("fma.rn.f32x2 %0, %1, %2, %0;" : "+l"(acc) : "l"(x), "l"(w));
}
__device__ __forceinline__ void cpasync16(void* dst, const void* src) {
    unsigned int da = (unsigned int)__cvta_generic_to_shared(dst);
    asm volatile("cp.async.cg.shared.global [%0], [%1], 16;"
                 :: "r"(da), "l"(src) : "memory");
}

// ------------------ init: zero hists + Wsp + packed Ratt ----------------------
__global__ void k_init(const float* __restrict__ Vw, const float* __restrict__ Vb,
                       const float* __restrict__ s2u, const float* __restrict__ Ratt,
                       int n, int zb) {
    int b = blockIdx.x;
    if (b < zb) {
        int i = b * 256 + threadIdx.x;
        if (i < n) g_win[i] = -1;
        if (i < 4 * n) g_thist[i] = 0;
        if (i < TT) { g_typehist[i] = 0; g_typecur[i] = 0; }
    } else if (b < zb + 65) {
        int bi  = b - zb;
        int row = bi * 2 + (threadIdx.x >> 7);
        int d   = threadIdx.x & 127;
        if (row < DD) {
            float acc = 0.f;
            for (int m = 0; m < DD; m++)
                acc += Vw[(DD + row) * DD + m] * s2u[m * DD + d];
            g_Wsp[row * DD + d] = acc;
        } else if (row == DD) {
            float acc = 0.f;
            for (int m = 0; m < DD; m++)
                acc += Vb[DD + m] * s2u[m * DD + d];
            g_bsp[d] = acc;
        }
    } else {
        int idx = (b - zb - 65) * 256 + threadIdx.x;
        if (idx < RR * HH * 8 * DKK) {
            int f   = idx & 15;
            int dkp = (idx >> 4) & 7;
            int h   = (idx >> 7) & 7;
            int r   = idx >> 10;
            float a0 = Ratt[((r * HH + h) * DKK + 2 * dkp)     * DKK + f];
            float a1 = Ratt[((r * HH + h) * DKK + 2 * dkp + 1) * DKK + f];
            g_Rp[idx] = pack2(a0, a1);
        }
    }
}

__global__ void k_nodehist(const int* __restrict__ ntype, int n) {
    int i = blockIdx.x * blockDim.x + threadIdx.x;
    if (i < n) atomicAdd(&g_typehist[ntype[i]], 1);
}

__global__ void k_nodescatter(const int* __restrict__ ntype, int n) {
    int i = blockIdx.x * blockDim.x + threadIdx.x;
    if (i >= n) return;
    int t = ntype[i];
    int off = 0;
    for (int ty = 0; ty < TT; ty++) if (ty < t) off += g_typehist[ty];
    int pos = off + atomicAdd(&g_typecur[t], 1);
    g_perm[pos] = i;
}

// ----------------- register-tiled GEMM: K/Q/V/speaker projections -------------
__global__ void __launch_bounds__(256, 2)
k_gemm_proj(const float* __restrict__ x, const int* __restrict__ ntype,
            const float* __restrict__ Kw, const float* __restrict__ Kb,
            const float* __restrict__ Qw, const float* __restrict__ Qb,
            const float* __restrict__ Vw, const float* __restrict__ Vb, int n) {
    extern __shared__ __align__(16) unsigned char sraw[];
    float (*xs)[XSTRIDE] = (float (*)[XSTRIDE])sraw;
    float* qs = (float*)sraw;                     // overlay: node-major q stash
    float (*wbuf)[KTILE][64] = (float (*)[KTILE][64])(sraw + XS_BYTES);
    int* nodes_s = (int*)(sraw + XS_BYTES + WB_BYTES);
    int* types_s = nodes_s + GN;
    __shared__ int s_uni;

    int tid  = threadIdx.x;
    int base = blockIdx.x * GN;
    if (tid == 0) s_uni = 1;
    if (tid < GN) {
        int idx  = base + tid;
        int cidx = (idx < n) ? idx : (n - 1);
        nodes_s[tid] = (idx < n) ? g_perm[idx] : -1;
        types_s[tid] = ntype[g_perm[cidx]];
    }
    __syncthreads();
    if (tid < GN && types_s[tid] != types_s[0]) s_uni = 0;
    __syncthreads();
    int  t0      = types_s[0];
    bool uniform = (s_uni != 0);

    int mat  = blockIdx.y >> 1;
    int half = (blockIdx.y & 1) * 64;
    const float* W; const float* B; float* dst;
    switch (mat) {
        case 0:  W = Kw + t0 * DD * DD; B = Kb + t0 * DD; dst = g_k;  break;
        case 1:  W = Qw + t0 * DD * DD; B = Qb + t0 * DD; dst = 0;    break;
        case 2:  W = Vw + t0 * DD * DD; B = Vb + t0 * DD; dst = g_v;  break;
        default: W = g_Wsp;             B = g_bsp;        dst = g_sp; break;
    }

    if (uniform) {
#pragma unroll
        for (int q = 0; q < 2; q++) {
            int f4  = tid + q * 256;
            int row = f4 >> 4;
            int c4  = f4 & 15;
            cpasync16(&wbuf[0][row][c4 * 4], W + row * DD + half + c4 * 4);
        }
        asm volatile("cp.async.commit_group;" ::: "memory");
    }

    // stage x transposed
#pragma unroll 4
    for (int it = 0; it < 16; it++) {
        int f4 = tid + it * 256;
        int j  = f4 >> 5;
        int c4 = f4 & 31;
        int nd = nodes_s[j];
        float4 v = (nd >= 0) ? *(const float4*)&x[nd * DD + c4 * 4]
                             : make_float4(0.f, 0.f, 0.f, 0.f);
        xs[c4 * 4 + 0][j] = v.x;
        xs[c4 * 4 + 1][j] = v.y;
        xs[c4 * 4 + 2][j] = v.z;
        xs[c4 * 4 + 3][j] = v.w;
    }
    __syncthreads();

    int cn = tid & 15, nn = tid >> 4;
    int col0 = half + cn * 4;
    int nb0  = nn * 8;

    if (uniform) {
        float4 bv = *(const float4*)&B[col0];
        ull bb0 = pack2(bv.x, bv.x), bb1 = pack2(bv.y, bv.y);
        ull bb2 = pack2(bv.z, bv.z), bb3 = pack2(bv.w, bv.w);
        ull acc[4][4];
#pragma unroll
        for (int np = 0; np < 4; np++) {
            acc[np][0] = bb0; acc[np][1] = bb1; acc[np][2] = bb2; acc[np][3] = bb3;
        }

        for (int tile = 0; tile < NTILE; tile++) {
            if (tile + 1 < NTILE) {
                int stg = (tile + 1) & 1;
#pragma unroll
                for (int q = 0; q < 2; q++) {
                    int f4  = tid + q * 256;
                    int row = f4 >> 4;
                    int c4  = f4 & 15;
                    cpasync16(&wbuf[stg][row][c4 * 4],
                              W + ((tile + 1) * KTILE + row) * DD + half + c4 * 4);
                }
                asm volatile("cp.async.commit_group;" ::: "memory");
                asm volatile("cp.async.wait_group 1;" ::: "memory");
            } else {
                asm volatile("cp.async.wait_group 0;" ::: "memory");
            }
            __syncthreads();
            int cur = tile & 1;
#pragma unroll
            for (int kk = 0; kk < KTILE; kk++) {
                int k = tile * KTILE + kk;
                ulonglong2 xlo = *(const ulonglong2*)&xs[k][nb0];
                ulonglong2 xhi = *(const ulonglong2*)&xs[k][nb0 + 4];
                float4 wv = *(const float4*)&wbuf[cur][kk][cn * 4];
                ull w0 = pack2(wv.x, wv.x), w1 = pack2(wv.y, wv.y);
                ull w2 = pack2(wv.z, wv.z), w3 = pack2(wv.w, wv.w);
                fma2(acc[0][0], xlo.x, w0); fma2(acc[0][1], xlo.x, w1);
                fma2(acc[0][2], xlo.x, w2); fma2(acc[0][3], xlo.x, w3);
                fma2(acc[1][0], xlo.y, w0); fma2(acc[1][1], xlo.y, w1);
                fma2(acc[1][2], xlo.y, w2); fma2(acc[1][3], xlo.y, w3);
                fma2(acc[2][0], xhi.x, w0); fma2(acc[2][1], xhi.x, w1);
                fma2(acc[2][2], xhi.x, w2); fma2(acc[2][3], xhi.x, w3);
                fma2(acc[3][0], xhi.y, w0); fma2(acc[3][1], xhi.y, w1);
                fma2(acc[3][2], xhi.y, w2); fma2(acc[3][3], xhi.y, w3);
            }
            __syncthreads();
        }

        if (mat != 1) {
#pragma unroll
            for (int np = 0; np < 4; np++) {
                int n0 = nodes_s[nb0 + np * 2], n1 = nodes_s[nb0 + np * 2 + 1];
                float4 o0, o1;
                unpack2(acc[np][0], o0.x, o1.x);
                unpack2(acc[np][1], o0.y, o1.y);
                unpack2(acc[np][2], o0.z, o1.z);
                unpack2(acc[np][3], o0.w, o1.w);
                if (n0 >= 0) *(float4*)&dst[n0 * DD + col0] = o0;
                if (n1 >= 0) *(float4*)&dst[n1 * DD + col0] = o1;
            }
        } else {
#pragma unroll
            for (int np = 0; np < 4; np++) {
                int j0 = nb0 + np * 2;
                float4 o0, o1;
                unpack2(acc[np][0], o0.x, o1.x);
                unpack2(acc[np][1], o0.y, o1.y);
                unpack2(acc[np][2], o0.z, o1.z);
                unpack2(acc[np][3], o0.w, o1.w);
                *(float4*)&qs[j0 * QST + cn * 4]       = o0;
                *(float4*)&qs[(j0 + 1) * QST + cn * 4] = o1;
            }
        }
    } else {
        float4 qtmp[8];
        for (int j = 0; j < 8; j++) {
            int node = nb0 + j;
            int nd = nodes_s[node];
            int t = types_s[node];
            const float* Wt; const float* Bt;
            switch (mat) {
                case 0:  Wt = Kw + t * DD * DD; Bt = Kb + t * DD; break;
                case 1:  Wt = Qw + t * DD * DD; Bt = Qb + t * DD; break;
                case 2:  Wt = Vw + t * DD * DD; Bt = Vb + t * DD; break;
                default: Wt = g_Wsp;            Bt = g_bsp;       break;
            }
            float4 a = *(const float4*)&Bt[col0];
            for (int k = 0; k < DD; k++) {
                float xv = xs[k][node];
                float4 w = *(const float4*)&Wt[k * DD + col0];
                a.x += xv * w.x; a.y += xv * w.y; a.z += xv * w.z; a.w += xv * w.w;
            }
            if (mat != 1) {
                if (nd >= 0) *(float4*)&dst[nd * DD + col0] = a;
            } else {
                qtmp[j] = a;
            }
        }
        if (mat == 1) {
            __syncthreads();
#pragma unroll
            for (int j = 0; j < 8; j++) {
                *(float4*)&qs[(nb0 + j) * QST + cn * 4] = qtmp[j];
            }
        }
    }

    // ---------------- in-block q' transform (Q blocks only) -------------------
    if (mat == 1) {
        __syncthreads();
        int slot = tid & 31;
        int grp  = tid >> 5;
        int dloc = 2 * slot;
        int d0g  = half + dloc;
        int h    = d0g >> 4;
        int dkp  = (d0g >> 1) & 7;
        int hrow = dloc & 0x30;
        const ull* rp = g_Rp + (h * 8 + dkp) * DKK;
#pragma unroll
        for (int r = 0; r < RR; r++) {
            ull w[DKK];
#pragma unroll
            for (int f = 0; f < DKK; f++) w[f] = rp[r * 1024 + f];
            for (int jj = 0; jj < 16; jj++) {
                int jloc = grp * 16 + jj;
                int nd   = nodes_s[jloc];
                const float* qrow = &qs[jloc * QST + hrow];
                float4 q0 = *(const float4*)&qrow[0];
                float4 q1 = *(const float4*)&qrow[4];
                float4 q2 = *(const float4*)&qrow[8];
                float4 q3 = *(const float4*)&qrow[12];
                ull acc = 0;
                fma2(acc, pack2(q0.x, q0.x), w[0]);
                fma2(acc, pack2(q0.y, q0.y), w[1]);
                fma2(acc, pack2(q0.z, q0.z), w[2]);
                fma2(acc, pack2(q0.w, q0.w), w[3]);
                fma2(acc, pack2(q1.x, q1.x), w[4]);
                fma2(acc, pack2(q1.y, q1.y), w[5]);
                fma2(acc, pack2(q1.z, q1.z), w[6]);
                fma2(acc, pack2(q1.w, q1.w), w[7]);
                fma2(acc, pack2(q2.x, q2.x), w[8]);
                fma2(acc, pack2(q2.y, q2.y), w[9]);
                fma2(acc, pack2(q2.z, q2.z), w[10]);
                fma2(acc, pack2(q2.w, q2.w), w[11]);
                fma2(acc, pack2(q3.x, q3.x), w[12]);
                fma2(acc, pack2(q3.y, q3.y), w[13]);
                fma2(acc, pack2(q3.z, q3.z), w[14]);
                fma2(acc, pack2(q3.w, q3.w), w[15]);
                if (nd >= 0) {
                    float lo, hi;
                    unpack2(acc, lo, hi);
                    *(float2*)&g_qt[(nd * RR + r) * DD + d0g] = make_float2(lo, hi);
                }
            }
        }
    }
}

// ------------------------------ edge setup ------------------------------------
__global__ void k_edgestats(const int* __restrict__ ei, const int* __restrict__ et, int e) {
    int i = blockIdx.x * blockDim.x + threadIdx.x;
    if (i >= e) return;
    int tgt = ei[e + i];
    int r   = et[i];
    atomicAdd(&g_thist[tgt * RR + r], 1);
    if (r == 0) atomicMax(&g_win[ei[i]], i);
}

__global__ void k_scan1(int n4) {
    __shared__ int buf[1024];
    int t = threadIdx.x;
    int gid = blockIdx.x * 1024 + t;
    int v = (gid < n4) ? g_thist[gid] : 0;
    buf[t] = v;
    __syncthreads();
    for (int off = 1; off < 1024; off <<= 1) {
        int x = (t >= off) ? buf[t - off] : 0;
        __syncthreads();
        buf[t] += x;
        __syncthreads();
    }
    if (gid < n4) g_toff[gid] = buf[t] - v;
    if (t == 1023) g_bsum[blockIdx.x] = buf[t];
}

__global__ void k_scan2(int nblocks, int n4) {
    if (threadIdx.x == 0) {
        int run = 0;
        for (int b = 0; b < nblocks; b++) { int x = g_bsum[b]; g_bsum[b] = run; run += x; }
        g_toff[n4] = run;
    }
}

__global__ void k_scan3(int n4) {
    int gid = blockIdx.x * blockDim.x + threadIdx.x;
    if (gid < n4) {
        int v = g_toff[gid] + g_bsum[gid >> 10];
        g_toff[gid] = v;
        g_tcur[gid] = v;
    }
}

__global__ void k_scatter_edges(const int* __restrict__ ei, const int* __restrict__ et,
                                const int* __restrict__ ntype, int e) {
    int i = blockIdx.x * blockDim.x + threadIdx.x;
    if (i >= e) return;
    int src = ei[i];
    int tgt = ei[e + i];
    int r   = et[i];
    int st  = ntype[src];
    int pos = atomicAdd(&g_tcur[tgt * RR + r], 1);
    g_epack[pos] = src | (st << 16);
}

// ------- attention: warp per target, per-relation sub-loops, 4-wide unroll -----
__global__ void __launch_bounds__(256)
k_attn(const int* __restrict__ ntype, const float* __restrict__ pri,
       const float* __restrict__ Rmsg, int n) {
    __shared__ float accsh[8][RR][DD];
    int warp = threadIdx.x >> 5, lane = threadIdx.x & 31;
    int i = blockIdx.x * 8 + warp;
    if (i >= n) return;
    int d0 = lane * 4;
    int h  = lane >> 2;

    int tt = ntype[i];
    float p0[TT], p1[TT], p2[TT], p3[TT];
#pragma unroll
    for (int st = 0; st < TT; st++) {
        p0[st] = pri[((tt * RR + 0) * TT + st) * HH + h];
        p1[st] = pri[((tt * RR + 1) * TT + st) * HH + h];
        p2[st] = pri[((tt * RR + 2) * TT + st) * HH + h];
        p3[st] = pri[((tt * RR + 3) * TT + st) * HH + h];
    }

    float den = 0.f;
    float4 acc[RR];
#pragma unroll
    for (int r = 0; r < RR; r++) acc[r] = make_float4(0.f, 0.f, 0.f, 0.f);

#pragma unroll
    for (int r = 0; r < RR; r++) {
        int beg = g_toff[i * RR + r], end = g_toff[i * RR + r + 1];
        if (beg == end) continue;
        float4 qtr = *(const float4*)&g_qt[(i * RR + r) * DD + d0];
        float4 a = make_float4(0.f, 0.f, 0.f, 0.f);
        float pA = (r == 0) ? p0[0] : (r == 1) ? p1[0] : (r == 2) ? p2[0] : p3[0];
        float pB = (r == 0) ? p0[1] : (r == 1) ? p1[1] : (r == 2) ? p2[1] : p3[1];
        float pC = (r == 0) ? p0[2] : (r == 1) ? p1[2] : (r == 2) ? p2[2] : p3[2];
        int idx = beg;
        // 4-wide: 8 independent k/v loads in flight per iteration
        for (; idx + 4 <= end; idx += 4) {
            int pk0 = g_epack[idx];
            int pk1 = g_epack[idx + 1];
            int pk2 = g_epack[idx + 2];
            int pk3 = g_epack[idx + 3];
            int s0 = pk0 & 0xFFFF, st0 = pk0 >> 16;
            int s1 = pk1 & 0xFFFF, st1 = pk1 >> 16;
            int s2 = pk2 & 0xFFFF, st2 = pk2 >> 16;
            int s3 = pk3 & 0xFFFF, st3 = pk3 >> 16;
            const float4 k0 = *(const float4*)&g_k[s0 * DD + d0];
            const float4 k1 = *(const float4*)&g_k[s1 * DD + d0];
            const float4 k2 = *(const float4*)&g_k[s2 * DD + d0];
            const float4 k3 = *(const float4*)&g_k[s3 * DD + d0];
            const float4 v0 = *(const float4*)&g_v[s0 * DD + d0];
            const float4 v1 = *(const float4*)&g_v[s1 * DD + d0];
            const float4 v2 = *(const float4*)&g_v[s2 * DD + d0];
            const float4 v3 = *(const float4*)&g_v[s3 * DD + d0];
            float sa = qtr.x * k0.x + qtr.y * k0.y + qtr.z * k0.z + qtr.w * k0.w;
            float sb = qtr.x * k1.x + qtr.y * k1.y + qtr.z * k1.z + qtr.w * k1.w;
            float sc = qtr.x * k2.x + qtr.y * k2.y + qtr.z * k2.z + qtr.w * k2.w;
            float sd = qtr.x * k3.x + qtr.y * k3.y + qtr.z * k3.z + qtr.w * k3.w;
            sa += __shfl_xor_sync(0xffffffffu, sa, 1);
            sb += __shfl_xor_sync(0xffffffffu, sb, 1);
            sc += __shfl_xor_sync(0xffffffffu, sc, 1);
            sd += __shfl_xor_sync(0xffffffffu, sd, 1);
            sa += __shfl_xor_sync(0xffffffffu, sa, 2);
            sb += __shfl_xor_sync(0xffffffffu, sb, 2);
            sc += __shfl_xor_sync(0xffffffffu, sc, 2);
            sd += __shfl_xor_sync(0xffffffffu, sd, 2);
            float pra = (st0 == 1) ? pB : (st0 == 2) ? pC : pA;
            float prb = (st1 == 1) ? pB : (st1 == 2) ? pC : pA;
            float prc = (st2 == 1) ? pB : (st2 == 2) ? pC : pA;
            float prd = (st3 == 1) ? pB : (st3 == 2) ? pC : pA;
            float pea = __expf(sa * pra * 0.25f);
            float peb = __expf(sb * prb * 0.25f);
            float pec = __expf(sc * prc * 0.25f);
            float ped = __expf(sd * prd * 0.25f);
            den += (pea + peb) + (pec + ped);
            a.x += pea * v0.x + peb * v1.x + pec * v2.x + ped * v3.x;
            a.y += pea * v0.y + peb * v1.y + pec * v2.y + ped * v3.y;
            a.z += pea * v0.z + peb * v1.z + pec * v2.z + ped * v3.z;
            a.w += pea * v0.w + peb * v1.w + pec * v2.w + ped * v3.w;
        }
        for (; idx + 2 <= end; idx += 2) {
            int pk0 = g_epack[idx];
            int pk1 = g_epack[idx + 1];
            int s0 = pk0 & 0xFFFF, st0 = pk0 >> 16;
            int s1 = pk1 & 0xFFFF, st1 = pk1 >> 16;
            const float4 ka = *(const float4*)&g_k[s0 * DD + d0];
            const float4 kb = *(const float4*)&g_k[s1 * DD + d0];
            const float4 va = *(const float4*)&g_v[s0 * DD + d0];
            const float4 vb = *(const float4*)&g_v[s1 * DD + d0];
            float sa = qtr.x * ka.x + qtr.y * ka.y + qtr.z * ka.z + qtr.w * ka.w;
            float sb = qtr.x * kb.x + qtr.y * kb.y + qtr.z * kb.z + qtr.w * kb.w;
            sa += __shfl_xor_sync(0xffffffffu, sa, 1);
            sb += __shfl_xor_sync(0xffffffffu, sb, 1);
            sa += __shfl_xor_sync(0xffffffffu, sa, 2);
            sb += __shfl_xor_sync(0xffffffffu, sb, 2);
            float pra = (st0 == 1) ? pB : (st0 == 2) ? pC : pA;
            float prb = (st1 == 1) ? pB : (st1 == 2) ? pC : pA;
            float pea = __expf(sa * pra * 0.25f);
            float peb = __expf(sb * prb * 0.25f);
            den += pea + peb;
            a.x += pea * va.x + peb * vb.x;
            a.y += pea * va.y + peb * vb.y;
            a.z += pea * va.z + peb * vb.z;
            a.w += pea * va.w + peb * vb.w;
        }
        if (idx < end) {
            int pk  = g_epack[idx];
            int src = pk & 0xFFFF;
            int st  = pk >> 16;
            const float4 k4 = *(const float4*)&g_k[src * DD + d0];
            float s = qtr.x * k4.x + qtr.y * k4.y + qtr.z * k4.z + qtr.w * k4.w;
            s += __shfl_xor_sync(0xffffffffu, s, 1);
            s += __shfl_xor_sync(0xffffffffu, s, 2);
            float pr = (st == 1) ? pB : (st == 2) ? pC : pA;
            float pe = __expf(s * pr * 0.25f);
            den += pe;
            const float4 v4 = *(const float4*)&g_v[src * DD + d0];
            a.x += pe * v4.x;
            a.y += pe * v4.y;
            a.z += pe * v4.z;
            a.w += pe * v4.w;
        }
        acc[r] = a;
    }

    float inv = 1.f / (den + 1e-16f);
#pragma unroll
    for (int r = 0; r < RR; r++) {
        accsh[warp][r][d0 + 0] = acc[r].x * inv;
        accsh[warp][r][d0 + 1] = acc[r].y * inv;
        accsh[warp][r][d0 + 2] = acc[r].z * inv;
        accsh[warp][r][d0 + 3] = acc[r].w * inv;
    }
    __syncwarp();

    int f0 = (lane & 3) * 4;
    float4 o = make_float4(0.f, 0.f, 0.f, 0.f);
#pragma unroll
    for (int r = 0; r < RR; r++) {
#pragma unroll 4
        for (int dk = 0; dk < DKK; dk++) {
            float a = accsh[warp][r][(h << 4) + dk];
            const float4 w = *(const float4*)&Rmsg[(((r * HH + h) * DKK + dk) * DKK) + f0];
            o.x += a * w.x;
            o.y += a * w.y;
            o.z += a * w.z;
            o.w += a * w.w;
        }
    }
    *(float4*)&g_aggr[i * DD + d0] = o;
}

// ------------- final: speaker add + GELU + per-type A projection + skip -------
__global__ void __launch_bounds__(256, 3)
k_final(const float* __restrict__ x, const int* __restrict__ ntype,
        const int* __restrict__ ei,
        const float* __restrict__ Aw, const float* __restrict__ Ab,
        const float* __restrict__ skip, float* __restrict__ out, int n, int e) {
    __shared__ __align__(16) float gsN[DD][GST];
    __shared__ int nodes_s[NPB], types_s[NPB], spsrc_s[NPB];
    int tid  = threadIdx.x;
    int base = blockIdx.x * NPB;
    if (tid < NPB) {
        int idx = base + tid;
        int cidx = (idx < n) ? idx : (n - 1);
        int nd = (idx < n) ? g_perm[idx] : -1;
        nodes_s[tid] = nd;
        types_s[tid] = ntype[g_perm[cidx]];
        int sps = -1;
        if (nd >= 0) {
            int we = g_win[nd];
            if (we >= 0) sps = ei[e + we];
        }
        spsrc_s[tid] = sps;
    }
    __syncthreads();

    for (int idx = tid; idx < NPB * DD; idx += 256) {
        int j = idx >> 7;
        int k = idx & 127;
        int nd = nodes_s[j];
        float v = 0.f;
        if (nd >= 0) {
            v = g_aggr[nd * DD + k];
            int sps = spsrc_s[j];
            if (sps >= 0) v += g_sp[sps * DD + k];
            v = 0.5f * v * (1.f + erff(v * 0.70710678118654752f));
        }
        gsN[k][j] = v;
    }
    __syncthreads();

    int g  = tid >> 6;
    int p  = tid & 63;
    int d0 = 2 * p;
    int jb = g * 8;

    int t0 = types_s[0];
    bool uniform = true;
#pragma unroll
    for (int j = 1; j < NPB; j++) uniform &= (types_s[j] == t0);

    if (uniform) {
        const float* pA = Aw + t0 * DD * DD + d0;
        ull bA = *(const ull*)&Ab[t0 * DD + d0];
        ull aA[8];
#pragma unroll
        for (int j = 0; j < 8; j++) aA[j] = bA;
#pragma unroll 4
        for (int k = 0; k < DD; k++) {
            ull w2 = *(const ull*)&pA[k * DD];
            float4 q0 = *(const float4*)&gsN[k][jb];
            float4 q1 = *(const float4*)&gsN[k][jb + 4];
            fma2(aA[0], pack2(q0.x, q0.x), w2);
            fma2(aA[1], pack2(q0.y, q0.y), w2);
            fma2(aA[2], pack2(q0.z, q0.z), w2);
            fma2(aA[3], pack2(q0.w, q0.w), w2);
            fma2(aA[4], pack2(q1.x, q1.x), w2);
            fma2(aA[5], pack2(q1.y, q1.y), w2);
            fma2(aA[6], pack2(q1.z, q1.z), w2);
            fma2(aA[7], pack2(q1.w, q1.w), w2);
        }
        float sk = skip[t0];
        float alpha = 1.f / (1.f + __expf(-sk));
        float beta  = 1.f - alpha;
#pragma unroll
        for (int j = 0; j < 8; j++) {
            int nd = nodes_s[jb + j];
            if (nd < 0) continue;
            float lo, hi;
            unpack2(aA[j], lo, hi);
            float2 xv = *(const float2*)&x[nd * DD + d0];
            *(float2*)&out[nd * DD + d0] =
                make_float2(lo * alpha + xv.x * beta, hi * alpha + xv.y * beta);
        }
    } else {
        for (int j = 0; j < 8; j++) {
            int nd = nodes_s[jb + j];
            if (nd < 0) continue;
            int t = types_s[jb + j];
            float2 aA = *(const float2*)&Ab[t * DD + d0];
            for (int k = 0; k < DD; k++) {
                float gv = gsN[k][jb + j];
                float2 w = *(const float2*)&Aw[(t * DD + k) * DD + d0];
                aA.x += gv * w.x; aA.y += gv * w.y;
            }
            float sk = skip[t];
            float alpha = 1.f / (1.f + __expf(-sk));
            float beta  = 1.f - alpha;
            float2 xv = *(const float2*)&x[nd * DD + d0];
            *(float2*)&out[nd * DD + d0] =
                make_float2(aA.x * alpha + xv.x * beta, aA.y * alpha + xv.y * beta);
        }
    }
}

// --------------------------------- launcher -----------------------------------
extern "C" void kernel_launch(void* const* d_in, const int* in_sizes, int n_in,
                              void* d_out, int out_size) {
    const float* node_inp  = (const float*)d_in[0];
    const int*   node_type = (const int*)  d_in[1];
    const int*   edge_index= (const int*)  d_in[2];
    const int*   edge_type = (const int*)  d_in[3];
    const float* Kw = (const float*)d_in[5];
    const float* Kb = (const float*)d_in[6];
    const float* Qw = (const float*)d_in[7];
    const float* Qb = (const float*)d_in[8];
    const float* Vw = (const float*)d_in[9];
    const float* Vb = (const float*)d_in[10];
    const float* Aw = (const float*)d_in[11];
    const float* Ab = (const float*)d_in[12];
    const float* pri  = (const float*)d_in[13];
    const float* Ratt = (const float*)d_in[14];
    const float* Rmsg = (const float*)d_in[15];
    const float* s2u  = (const float*)d_in[16];
    const float* skip = (const float*)d_in[17];
    float* out = (float*)d_out;

    int n = in_sizes[1];
    int e = in_sizes[3];
    if (n > NMAX) n = NMAX;
    if (e > EMAX) e = EMAX;
    int n4 = n * RR;

    int nb  = (n + 255) / 256;
    int n4b = (n4 + 255) / 256;
    int eb  = (e + 255) / 256;
    int sb  = (n4 + 1023) / 1024;
    int ngb = (n + GN - 1) / GN;

    cudaFuncSetAttribute(k_gemm_proj, cudaFuncAttributeMaxDynamicSharedMemorySize, SMEM_GEMM);

    k_init<<<n4b + 65 + 16, 256>>>(Vw, Vb, s2u, Ratt, n, n4b);
    k_nodehist<<<nb, 256>>>(node_type, n);
    k_nodescatter<<<nb, 256>>>(node_type, n);
    k_gemm_proj<<<dim3(ngb, 8), 256, SMEM_GEMM>>>(node_inp, node_type,
                                                  Kw, Kb, Qw, Qb, Vw, Vb, n);
    k_edgestats<<<eb, 256>>>(edge_index, edge_type, e);
    k_scan1<<<sb, 1024>>>(n4);
    k_scan2<<<1, 32>>>(sb, n4);
    k_scan3<<<n4b, 256>>>(n4);
    k_scatter_edges<<<eb, 256>>>(edge_index, edge_type, node_type, e);
    k_attn<<<(n + 7) / 8, 256>>>(node_type, pri, Rmsg, n);
    k_final<<<(n + NPB - 1) / NPB, 256>>>(node_inp, node_type, edge_index,
                                          Aw, Ab, skip, out, n, e);
}

// round 14
// speedup vs baseline: 1.3488x; 1.0907x over previous
#include <cuda_runtime.h>
#include <math.h>

#define NMAX 40000
#define EMAX 640000
#define DD   128
#define HH   8
#define DKK  16
#define TT   3
#define RR   4
#define N4   (NMAX * RR)

#define GN      128            // nodes per gemm block
#define XSTRIDE 132            // xs row stride (floats)
#define KTILE   32
#define NTILE   (DD / KTILE)
#define XS_BYTES (DD * XSTRIDE * 4)
#define WB_BYTES (2 * KTILE * 64 * 4)
#define SMEM_GEMM (XS_BYTES + WB_BYTES + GN * 2 * 4)
#define QST     68             // node-major q stash row stride (floats)

#define NPB  32              // nodes per final block
#define GST  36              // gsN row stride (floats)

typedef unsigned long long ull;

// ---------------- scratch (device globals) ------------------------------------
__device__ float g_k   [NMAX * DD];
__device__ float g_v   [NMAX * DD];
__device__ float g_qt  [NMAX * RR * DD];
__device__ float g_sp  [NMAX * DD];
__device__ float g_aggr[NMAX * DD];
__device__ float g_Wsp [DD * DD];
__device__ float g_bsp [DD];
__device__ ull   g_Rp  [RR * HH * 8 * DKK];
__device__ int   g_win [NMAX];
__device__ int   g_thist[N4];
__device__ int   g_toff [N4 + 1];
__device__ int   g_tcur [N4];
__device__ int   g_epack[EMAX];
__device__ int   g_bsum [256];
__device__ int   g_typehist[TT];
__device__ int   g_typecur [TT];
__device__ int   g_perm [NMAX];

// ---------------- packed f32x2 helpers ----------------------------------------
__device__ __forceinline__ ull pack2(float a, float b) {
    ull r;
    asm("mov.b64 %0, {%1, %2};" : "=l"(r) : "f"(a), "f"(b));
    return r;
}
__device__ __forceinline__ void unpack2(ull v, float& lo, float& hi) {
    asm("mov.b64 {%0, %1}, %2;" : "=f"(lo), "=f"(hi) : "l"(v));
}
__device__ __forceinline__ void fma2(ull& acc, ull x, ull w) {
    asm("fma.rn.f32x2 %0, %1, %2, %0;" : "+l"(acc) : "l"(x), "l"(w));
}
__device__ __forceinline__ void cpasync16(void* dst, const void* src) {
    unsigned int da = (unsigned int)__cvta_generic_to_shared(dst);
    asm volatile("cp.async.cg.shared.global [%0], [%1], 16;"
                 :: "r"(da), "l"(src) : "memory");
}

// ------------------ init: zero hists + Wsp + packed Ratt ----------------------
__global__ void k_init(const float* __restrict__ Vw, const float* __restrict__ Vb,
                       const float* __restrict__ s2u, const float* __restrict__ Ratt,
                       int n, int zb) {
    int b = blockIdx.x;
    if (b < zb) {
        int i = b * 256 + threadIdx.x;
        if (i < n) g_win[i] = -1;
        if (i < 4 * n) g_thist[i] = 0;
        if (i < TT) { g_typehist[i] = 0; g_typecur[i] = 0; }
    } else if (b < zb + 65) {
        int bi  = b - zb;
        int row = bi * 2 + (threadIdx.x >> 7);
        int d   = threadIdx.x & 127;
        if (row < DD) {
            float acc = 0.f;
            for (int m = 0; m < DD; m++)
                acc += Vw[(DD + row) * DD + m] * s2u[m * DD + d];
            g_Wsp[row * DD + d] = acc;
        } else if (row == DD) {
            float acc = 0.f;
            for (int m = 0; m < DD; m++)
                acc += Vb[DD + m] * s2u[m * DD + d];
            g_bsp[d] = acc;
        }
    } else {
        int idx = (b - zb - 65) * 256 + threadIdx.x;
        if (idx < RR * HH * 8 * DKK) {
            int f   = idx & 15;
            int dkp = (idx >> 4) & 7;
            int h   = (idx >> 7) & 7;
            int r   = idx >> 10;
            float a0 = Ratt[((r * HH + h) * DKK + 2 * dkp)     * DKK + f];
            float a1 = Ratt[((r * HH + h) * DKK + 2 * dkp + 1) * DKK + f];
            g_Rp[idx] = pack2(a0, a1);
        }
    }
}

__global__ void k_nodehist(const int* __restrict__ ntype, int n) {
    int i = blockIdx.x * blockDim.x + threadIdx.x;
    if (i < n) atomicAdd(&g_typehist[ntype[i]], 1);
}

__global__ void k_nodescatter(const int* __restrict__ ntype, int n) {
    int i = blockIdx.x * blockDim.x + threadIdx.x;
    if (i >= n) return;
    int t = ntype[i];
    int off = 0;
    for (int ty = 0; ty < TT; ty++) if (ty < t) off += g_typehist[ty];
    int pos = off + atomicAdd(&g_typecur[t], 1);
    g_perm[pos] = i;
}

// ----------------- register-tiled GEMM: K/Q/V/speaker projections -------------
// grid: (ceil(n/128), 5).
//   y=0: K both halves; y=1: V both halves; y=2: Wsp both halves;
//   y=3: Q half 0 (+qt); y=4: Q half 1 (+qt).
__global__ void __launch_bounds__(256, 2)
k_gemm_proj(const float* __restrict__ x, const int* __restrict__ ntype,
            const float* __restrict__ Kw, const float* __restrict__ Kb,
            const float* __restrict__ Qw, const float* __restrict__ Qb,
            const float* __restrict__ Vw, const float* __restrict__ Vb, int n) {
    extern __shared__ __align__(16) unsigned char sraw[];
    float (*xs)[XSTRIDE] = (float (*)[XSTRIDE])sraw;
    float* qs = (float*)sraw;                     // overlay: node-major q stash
    float (*wbuf)[KTILE][64] = (float (*)[KTILE][64])(sraw + XS_BYTES);
    int* nodes_s = (int*)(sraw + XS_BYTES + WB_BYTES);
    int* types_s = nodes_s + GN;
    __shared__ int s_uni;

    int tid  = threadIdx.x;
    int base = blockIdx.x * GN;
    if (tid == 0) s_uni = 1;
    if (tid < GN) {
        int idx  = base + tid;
        int cidx = (idx < n) ? idx : (n - 1);
        nodes_s[tid] = (idx < n) ? g_perm[idx] : -1;
        types_s[tid] = ntype[g_perm[cidx]];
    }
    __syncthreads();
    if (tid < GN && types_s[tid] != types_s[0]) s_uni = 0;
    __syncthreads();
    int  t0      = types_s[0];
    bool uniform = (s_uni != 0);

    int yb = blockIdx.y;
    int mat;                 // 0=K, 1=Q, 2=V, 3=Wsp
    int half0, nhalf;
    if (yb == 0)      { mat = 0; half0 = 0;  nhalf = 2; }
    else if (yb == 1) { mat = 2; half0 = 0;  nhalf = 2; }
    else if (yb == 2) { mat = 3; half0 = 0;  nhalf = 2; }
    else              { mat = 1; half0 = (yb - 3) * 64; nhalf = 1; }

    const float* W; const float* B; float* dst;
    switch (mat) {
        case 0:  W = Kw + t0 * DD * DD; B = Kb + t0 * DD; dst = g_k;  break;
        case 1:  W = Qw + t0 * DD * DD; B = Qb + t0 * DD; dst = 0;    break;
        case 2:  W = Vw + t0 * DD * DD; B = Vb + t0 * DD; dst = g_v;  break;
        default: W = g_Wsp;             B = g_bsp;        dst = g_sp; break;
    }

    if (uniform) {   // prologue for first half
#pragma unroll
        for (int q = 0; q < 2; q++) {
            int f4  = tid + q * 256;
            int row = f4 >> 4;
            int c4  = f4 & 15;
            cpasync16(&wbuf[0][row][c4 * 4], W + row * DD + half0 + c4 * 4);
        }
        asm volatile("cp.async.commit_group;" ::: "memory");
    }

    // stage x transposed -- conflict-reduced mapping:
    // lane covers 4 nodes x 8 k-quads (store lanes span 8 bank-groups -> 4-way)
    {
        int jq = tid & 3;            // node within quad
        int cq = (tid >> 2) & 31;    // k-quad
        int gq = tid >> 7;           // 0/1: node-quad pair per iter
#pragma unroll 4
        for (int it = 0; it < 16; it++) {
            int j  = it * 8 + gq * 4 + jq;
            int nd = nodes_s[j];
            float4 v = (nd >= 0) ? *(const float4*)&x[nd * DD + cq * 4]
                                 : make_float4(0.f, 0.f, 0.f, 0.f);
            xs[cq * 4 + 0][j] = v.x;
            xs[cq * 4 + 1][j] = v.y;
            xs[cq * 4 + 2][j] = v.z;
            xs[cq * 4 + 3][j] = v.w;
        }
    }
    __syncthreads();

    int cn = tid & 15, nn = tid >> 4;
    int nb0  = nn * 8;

    if (uniform) {
        for (int hh = 0; hh < nhalf; hh++) {
            int half = half0 + hh * 64;
            int col0 = half + cn * 4;

            float4 bv = *(const float4*)&B[col0];
            ull acc[4][4];
            {
                ull bb0 = pack2(bv.x, bv.x), bb1 = pack2(bv.y, bv.y);
                ull bb2 = pack2(bv.z, bv.z), bb3 = pack2(bv.w, bv.w);
#pragma unroll
                for (int np = 0; np < 4; np++) {
                    acc[np][0] = bb0; acc[np][1] = bb1; acc[np][2] = bb2; acc[np][3] = bb3;
                }
            }

            for (int tile = 0; tile < NTILE; tile++) {
                bool more = (tile + 1 < NTILE) || (hh + 1 < nhalf);
                if (more) {
                    int stg = (tile + 1) & 1;
                    int nrow0 = (tile + 1 < NTILE) ? (tile + 1) * KTILE : 0;
                    int nhalfoff = (tile + 1 < NTILE) ? half : half0 + (hh + 1) * 64;
#pragma unroll
                    for (int q = 0; q < 2; q++) {
                        int f4  = tid + q * 256;
                        int row = f4 >> 4;
                        int c4  = f4 & 15;
                        cpasync16(&wbuf[stg][row][c4 * 4],
                                  W + (nrow0 + row) * DD + nhalfoff + c4 * 4);
                    }
                    asm volatile("cp.async.commit_group;" ::: "memory");
                    asm volatile("cp.async.wait_group 1;" ::: "memory");
                } else {
                    asm volatile("cp.async.wait_group 0;" ::: "memory");
                }
                __syncthreads();
                int cur = tile & 1;
#pragma unroll
                for (int kk = 0; kk < KTILE; kk++) {
                    int k = tile * KTILE + kk;
                    ulonglong2 xlo = *(const ulonglong2*)&xs[k][nb0];
                    ulonglong2 xhi = *(const ulonglong2*)&xs[k][nb0 + 4];
                    float4 wv = *(const float4*)&wbuf[cur][kk][cn * 4];
                    ull w0 = pack2(wv.x, wv.x), w1 = pack2(wv.y, wv.y);
                    ull w2 = pack2(wv.z, wv.z), w3 = pack2(wv.w, wv.w);
                    fma2(acc[0][0], xlo.x, w0); fma2(acc[0][1], xlo.x, w1);
                    fma2(acc[0][2], xlo.x, w2); fma2(acc[0][3], xlo.x, w3);
                    fma2(acc[1][0], xlo.y, w0); fma2(acc[1][1], xlo.y, w1);
                    fma2(acc[1][2], xlo.y, w2); fma2(acc[1][3], xlo.y, w3);
                    fma2(acc[2][0], xhi.x, w0); fma2(acc[2][1], xhi.x, w1);
                    fma2(acc[2][2], xhi.x, w2); fma2(acc[2][3], xhi.x, w3);
                    fma2(acc[3][0], xhi.y, w0); fma2(acc[3][1], xhi.y, w1);
                    fma2(acc[3][2], xhi.y, w2); fma2(acc[3][3], xhi.y, w3);
                }
                __syncthreads();
            }

            if (mat != 1) {
#pragma unroll
                for (int np = 0; np < 4; np++) {
                    int n0 = nodes_s[nb0 + np * 2], n1 = nodes_s[nb0 + np * 2 + 1];
                    float4 o0, o1;
                    unpack2(acc[np][0], o0.x, o1.x);
                    unpack2(acc[np][1], o0.y, o1.y);
                    unpack2(acc[np][2], o0.z, o1.z);
                    unpack2(acc[np][3], o0.w, o1.w);
                    if (n0 >= 0) *(float4*)&dst[n0 * DD + col0] = o0;
                    if (n1 >= 0) *(float4*)&dst[n1 * DD + col0] = o1;
                }
            } else {
#pragma unroll
                for (int np = 0; np < 4; np++) {
                    int j0 = nb0 + np * 2;
                    float4 o0, o1;
                    unpack2(acc[np][0], o0.x, o1.x);
                    unpack2(acc[np][1], o0.y, o1.y);
                    unpack2(acc[np][2], o0.z, o1.z);
                    unpack2(acc[np][3], o0.w, o1.w);
                    *(float4*)&qs[j0 * QST + cn * 4]       = o0;
                    *(float4*)&qs[(j0 + 1) * QST + cn * 4] = o1;
                }
            }
        }
    } else {
        for (int hh = 0; hh < nhalf; hh++) {
            int half = half0 + hh * 64;
            int col0 = half + cn * 4;
            float4 qtmp[8];
            for (int j = 0; j < 8; j++) {
                int node = nb0 + j;
                int nd = nodes_s[node];
                int t = types_s[node];
                const float* Wt; const float* Bt;
                switch (mat) {
                    case 0:  Wt = Kw + t * DD * DD; Bt = Kb + t * DD; break;
                    case 1:  Wt = Qw + t * DD * DD; Bt = Qb + t * DD; break;
                    case 2:  Wt = Vw + t * DD * DD; Bt = Vb + t * DD; break;
                    default: Wt = g_Wsp;            Bt = g_bsp;       break;
                }
                float4 a = *(const float4*)&Bt[col0];
                for (int k = 0; k < DD; k++) {
                    float xv = xs[k][node];
                    float4 w = *(const float4*)&Wt[k * DD + col0];
                    a.x += xv * w.x; a.y += xv * w.y; a.z += xv * w.z; a.w += xv * w.w;
                }
                if (mat != 1) {
                    if (nd >= 0) *(float4*)&dst[nd * DD + col0] = a;
                } else {
                    qtmp[j] = a;
                }
            }
            if (mat == 1) {
                __syncthreads();   // all xs reads done block-wide before overlay
#pragma unroll
                for (int j = 0; j < 8; j++) {
                    *(float4*)&qs[(nb0 + j) * QST + cn * 4] = qtmp[j];
                }
            }
        }
    }

    // ---------------- in-block q' transform (Q blocks only) -------------------
    if (mat == 1) {
        __syncthreads();
        int slot = tid & 31;
        int grp  = tid >> 5;
        int dloc = 2 * slot;
        int d0g  = half0 + dloc;
        int h    = d0g >> 4;
        int dkp  = (d0g >> 1) & 7;
        int hrow = dloc & 0x30;
        const ull* rp = g_Rp + (h * 8 + dkp) * DKK;
#pragma unroll
        for (int r = 0; r < RR; r++) {
            ull w[DKK];
#pragma unroll
            for (int f = 0; f < DKK; f++) w[f] = rp[r * 1024 + f];
            for (int jj = 0; jj < 16; jj++) {
                int jloc = grp * 16 + jj;
                int nd   = nodes_s[jloc];
                const float* qrow = &qs[jloc * QST + hrow];
                float4 q0 = *(const float4*)&qrow[0];
                float4 q1 = *(const float4*)&qrow[4];
                float4 q2 = *(const float4*)&qrow[8];
                float4 q3 = *(const float4*)&qrow[12];
                ull acc = 0;
                fma2(acc, pack2(q0.x, q0.x), w[0]);
                fma2(acc, pack2(q0.y, q0.y), w[1]);
                fma2(acc, pack2(q0.z, q0.z), w[2]);
                fma2(acc, pack2(q0.w, q0.w), w[3]);
                fma2(acc, pack2(q1.x, q1.x), w[4]);
                fma2(acc, pack2(q1.y, q1.y), w[5]);
                fma2(acc, pack2(q1.z, q1.z), w[6]);
                fma2(acc, pack2(q1.w, q1.w), w[7]);
                fma2(acc, pack2(q2.x, q2.x), w[8]);
                fma2(acc, pack2(q2.y, q2.y), w[9]);
                fma2(acc, pack2(q2.z, q2.z), w[10]);
                fma2(acc, pack2(q2.w, q2.w), w[11]);
                fma2(acc, pack2(q3.x, q3.x), w[12]);
                fma2(acc, pack2(q3.y, q3.y), w[13]);
                fma2(acc, pack2(q3.z, q3.z), w[14]);
                fma2(acc, pack2(q3.w, q3.w), w[15]);
                if (nd >= 0) {
                    float lo, hi;
                    unpack2(acc, lo, hi);
                    *(float2*)&g_qt[(nd * RR + r) * DD + d0g] = make_float2(lo, hi);
                }
            }
        }
    }
}

// ------------------------------ edge setup ------------------------------------
__global__ void k_edgestats(const int* __restrict__ ei, const int* __restrict__ et, int e) {
    int i = blockIdx.x * blockDim.x + threadIdx.x;
    if (i >= e) return;
    int tgt = ei[e + i];
    int r   = et[i];
    atomicAdd(&g_thist[tgt * RR + r], 1);
    if (r == 0) atomicMax(&g_win[ei[i]], i);
}

__global__ void k_scan1(int n4) {
    __shared__ int buf[1024];
    int t = threadIdx.x;
    int gid = blockIdx.x * 1024 + t;
    int v = (gid < n4) ? g_thist[gid] : 0;
    buf[t] = v;
    __syncthreads();
    for (int off = 1; off < 1024; off <<= 1) {
        int x = (t >= off) ? buf[t - off] : 0;
        __syncthreads();
        buf[t] += x;
        __syncthreads();
    }
    if (gid < n4) g_toff[gid] = buf[t] - v;
    if (t == 1023) g_bsum[blockIdx.x] = buf[t];
}

__global__ void k_scan2(int nblocks, int n4) {
    if (threadIdx.x == 0) {
        int run = 0;
        for (int b = 0; b < nblocks; b++) { int x = g_bsum[b]; g_bsum[b] = run; run += x; }
        g_toff[n4] = run;
    }
}

__global__ void k_scan3(int n4) {
    int gid = blockIdx.x * blockDim.x + threadIdx.x;
    if (gid < n4) {
        int v = g_toff[gid] + g_bsum[gid >> 10];
        g_toff[gid] = v;
        g_tcur[gid] = v;
    }
}

__global__ void k_scatter_edges(const int* __restrict__ ei, const int* __restrict__ et,
                                const int* __restrict__ ntype, int e) {
    int i = blockIdx.x * blockDim.x + threadIdx.x;
    if (i >= e) return;
    int src = ei[i];
    int tgt = ei[e + i];
    int r   = et[i];
    int st  = ntype[src];
    int pos = atomicAdd(&g_tcur[tgt * RR + r], 1);
    g_epack[pos] = src | (st << 16);
}

// ------- attention: warp per target, per-relation sub-loops, 4-wide unroll -----
__global__ void __launch_bounds__(256)
k_attn(const int* __restrict__ ntype, const float* __restrict__ pri,
       const float* __restrict__ Rmsg, int n) {
    __shared__ float accsh[8][RR][DD];
    int warp = threadIdx.x >> 5, lane = threadIdx.x & 31;
    int i = blockIdx.x * 8 + warp;
    if (i >= n) return;
    int d0 = lane * 4;
    int h  = lane >> 2;

    int tt = ntype[i];
    float p0[TT], p1[TT], p2[TT], p3[TT];
#pragma unroll
    for (int st = 0; st < TT; st++) {
        p0[st] = pri[((tt * RR + 0) * TT + st) * HH + h];
        p1[st] = pri[((tt * RR + 1) * TT + st) * HH + h];
        p2[st] = pri[((tt * RR + 2) * TT + st) * HH + h];
        p3[st] = pri[((tt * RR + 3) * TT + st) * HH + h];
    }

    float den = 0.f;
    float4 acc[RR];
#pragma unroll
    for (int r = 0; r < RR; r++) acc[r] = make_float4(0.f, 0.f, 0.f, 0.f);

#pragma unroll
    for (int r = 0; r < RR; r++) {
        int beg = g_toff[i * RR + r], end = g_toff[i * RR + r + 1];
        if (beg == end) continue;
        float4 qtr = *(const float4*)&g_qt[(i * RR + r) * DD + d0];
        float4 a = make_float4(0.f, 0.f, 0.f, 0.f);
        float pA = (r == 0) ? p0[0] : (r == 1) ? p1[0] : (r == 2) ? p2[0] : p3[0];
        float pB = (r == 0) ? p0[1] : (r == 1) ? p1[1] : (r == 2) ? p2[1] : p3[1];
        float pC = (r == 0) ? p0[2] : (r == 1) ? p1[2] : (r == 2) ? p2[2] : p3[2];
        int idx = beg;
        for (; idx + 4 <= end; idx += 4) {
            int pk0 = g_epack[idx];
            int pk1 = g_epack[idx + 1];
            int pk2 = g_epack[idx + 2];
            int pk3 = g_epack[idx + 3];
            int s0 = pk0 & 0xFFFF, st0 = pk0 >> 16;
            int s1 = pk1 & 0xFFFF, st1 = pk1 >> 16;
            int s2 = pk2 & 0xFFFF, st2 = pk2 >> 16;
            int s3 = pk3 & 0xFFFF, st3 = pk3 >> 16;
            const float4 k0 = *(const float4*)&g_k[s0 * DD + d0];
            const float4 k1 = *(const float4*)&g_k[s1 * DD + d0];
            const float4 k2 = *(const float4*)&g_k[s2 * DD + d0];
            const float4 k3 = *(const float4*)&g_k[s3 * DD + d0];
            const float4 v0 = *(const float4*)&g_v[s0 * DD + d0];
            const float4 v1 = *(const float4*)&g_v[s1 * DD + d0];
            const float4 v2 = *(const float4*)&g_v[s2 * DD + d0];
            const float4 v3 = *(const float4*)&g_v[s3 * DD + d0];
            float sa = qtr.x * k0.x + qtr.y * k0.y + qtr.z * k0.z + qtr.w * k0.w;
            float sb = qtr.x * k1.x + qtr.y * k1.y + qtr.z * k1.z + qtr.w * k1.w;
            float sc = qtr.x * k2.x + qtr.y * k2.y + qtr.z * k2.z + qtr.w * k2.w;
            float sd = qtr.x * k3.x + qtr.y * k3.y + qtr.z * k3.z + qtr.w * k3.w;
            sa += __shfl_xor_sync(0xffffffffu, sa, 1);
            sb += __shfl_xor_sync(0xffffffffu, sb, 1);
            sc += __shfl_xor_sync(0xffffffffu, sc, 1);
            sd += __shfl_xor_sync(0xffffffffu, sd, 1);
            sa += __shfl_xor_sync(0xffffffffu, sa, 2);
            sb += __shfl_xor_sync(0xffffffffu, sb, 2);
            sc += __shfl_xor_sync(0xffffffffu, sc, 2);
            sd += __shfl_xor_sync(0xffffffffu, sd, 2);
            float pra = (st0 == 1) ? pB : (st0 == 2) ? pC : pA;
            float prb = (st1 == 1) ? pB : (st1 == 2) ? pC : pA;
            float prc = (st2 == 1) ? pB : (st2 == 2) ? pC : pA;
            float prd = (st3 == 1) ? pB : (st3 == 2) ? pC : pA;
            float pea = __expf(sa * pra * 0.25f);
            float peb = __expf(sb * prb * 0.25f);
            float pec = __expf(sc * prc * 0.25f);
            float ped = __expf(sd * prd * 0.25f);
            den += (pea + peb) + (pec + ped);
            a.x += pea * v0.x + peb * v1.x + pec * v2.x + ped * v3.x;
            a.y += pea * v0.y + peb * v1.y + pec * v2.y + ped * v3.y;
            a.z += pea * v0.z + peb * v1.z + pec * v2.z + ped * v3.z;
            a.w += pea * v0.w + peb * v1.w + pec * v2.w + ped * v3.w;
        }
        for (; idx + 2 <= end; idx += 2) {
            int pk0 = g_epack[idx];
            int pk1 = g_epack[idx + 1];
            int s0 = pk0 & 0xFFFF, st0 = pk0 >> 16;
            int s1 = pk1 & 0xFFFF, st1 = pk1 >> 16;
            const float4 ka = *(const float4*)&g_k[s0 * DD + d0];
            const float4 kb = *(const float4*)&g_k[s1 * DD + d0];
            const float4 va = *(const float4*)&g_v[s0 * DD + d0];
            const float4 vb = *(const float4*)&g_v[s1 * DD + d0];
            float sa = qtr.x * ka.x + qtr.y * ka.y + qtr.z * ka.z + qtr.w * ka.w;
            float sb = qtr.x * kb.x + qtr.y * kb.y + qtr.z * kb.z + qtr.w * kb.w;
            sa += __shfl_xor_sync(0xffffffffu, sa, 1);
            sb += __shfl_xor_sync(0xffffffffu, sb, 1);
            sa += __shfl_xor_sync(0xffffffffu, sa, 2);
            sb += __shfl_xor_sync(0xffffffffu, sb, 2);
            float pra = (st0 == 1) ? pB : (st0 == 2) ? pC : pA;
            float prb = (st1 == 1) ? pB : (st1 == 2) ? pC : pA;
            float pea = __expf(sa * pra * 0.25f);
            float peb = __expf(sb * prb * 0.25f);
            den += pea + peb;
            a.x += pea * va.x + peb * vb.x;
            a.y += pea * va.y + peb * vb.y;
            a.z += pea * va.z + peb * vb.z;
            a.w += pea * va.w + peb * vb.w;
        }
        if (idx < end) {
            int pk  = g_epack[idx];
            int src = pk & 0xFFFF;
            int st  = pk >> 16;
            const float4 k4 = *(const float4*)&g_k[src * DD + d0];
            float s = qtr.x * k4.x + qtr.y * k4.y + qtr.z * k4.z + qtr.w * k4.w;
            s += __shfl_xor_sync(0xffffffffu, s, 1);
            s += __shfl_xor_sync(0xffffffffu, s, 2);
            float pr = (st == 1) ? pB : (st == 2) ? pC : pA;
            float pe = __expf(s * pr * 0.25f);
            den += pe;
            const float4 v4 = *(const float4*)&g_v[src * DD + d0];
            a.x += pe * v4.x;
            a.y += pe * v4.y;
            a.z += pe * v4.z;
            a.w += pe * v4.w;
        }
        acc[r] = a;
    }

    float inv = 1.f / (den + 1e-16f);
#pragma unroll
    for (int r = 0; r < RR; r++) {
        accsh[warp][r][d0 + 0] = acc[r].x * inv;
        accsh[warp][r][d0 + 1] = acc[r].y * inv;
        accsh[warp][r][d0 + 2] = acc[r].z * inv;
        accsh[warp][r][d0 + 3] = acc[r].w * inv;
    }
    __syncwarp();

    int f0 = (lane & 3) * 4;
    float4 o = make_float4(0.f, 0.f, 0.f, 0.f);
#pragma unroll
    for (int r = 0; r < RR; r++) {
#pragma unroll 4
        for (int dk = 0; dk < DKK; dk++) {
            float a = accsh[warp][r][(h << 4) + dk];
            const float4 w = *(const float4*)&Rmsg[(((r * HH + h) * DKK + dk) * DKK) + f0];
            o.x += a * w.x;
            o.y += a * w.y;
            o.z += a * w.z;
            o.w += a * w.w;
        }
    }
    *(float4*)&g_aggr[i * DD + d0] = o;
}

// ------------- final: speaker add + GELU + per-type A projection + skip -------
__global__ void __launch_bounds__(256, 3)
k_final(const float* __restrict__ x, const int* __restrict__ ntype,
        const int* __restrict__ ei,
        const float* __restrict__ Aw, const float* __restrict__ Ab,
        const float* __restrict__ skip, float* __restrict__ out, int n, int e) {
    __shared__ __align__(16) float gsN[DD][GST];
    __shared__ int nodes_s[NPB], types_s[NPB], spsrc_s[NPB];
    int tid  = threadIdx.x;
    int base = blockIdx.x * NPB;
    if (tid < NPB) {
        int idx = base + tid;
        int cidx = (idx < n) ? idx : (n - 1);
        int nd = (idx < n) ? g_perm[idx] : -1;
        nodes_s[tid] = nd;
        types_s[tid] = ntype[g_perm[cidx]];
        int sps = -1;
        if (nd >= 0) {
            int we = g_win[nd];
            if (we >= 0) sps = ei[e + we];
        }
        spsrc_s[tid] = sps;
    }
    __syncthreads();

    for (int idx = tid; idx < NPB * DD; idx += 256) {
        int j = idx >> 7;
        int k = idx & 127;
        int nd = nodes_s[j];
        float v = 0.f;
        if (nd >= 0) {
            v = g_aggr[nd * DD + k];
            int sps = spsrc_s[j];
            if (sps >= 0) v += g_sp[sps * DD + k];
            v = 0.5f * v * (1.f + erff(v * 0.70710678118654752f));
        }
        gsN[k][j] = v;
    }
    __syncthreads();

    int g  = tid >> 6;
    int p  = tid & 63;
    int d0 = 2 * p;
    int jb = g * 8;

    int t0 = types_s[0];
    bool uniform = true;
#pragma unroll
    for (int j = 1; j < NPB; j++) uniform &= (types_s[j] == t0);

    if (uniform) {
        const float* pA = Aw + t0 * DD * DD + d0;
        ull bA = *(const ull*)&Ab[t0 * DD + d0];
        ull aA[8];
#pragma unroll
        for (int j = 0; j < 8; j++) aA[j] = bA;
#pragma unroll 4
        for (int k = 0; k < DD; k++) {
            ull w2 = *(const ull*)&pA[k * DD];
            float4 q0 = *(const float4*)&gsN[k][jb];
            float4 q1 = *(const float4*)&gsN[k][jb + 4];
            fma2(aA[0], pack2(q0.x, q0.x), w2);
            fma2(aA[1], pack2(q0.y, q0.y), w2);
            fma2(aA[2], pack2(q0.z, q0.z), w2);
            fma2(aA[3], pack2(q0.w, q0.w), w2);
            fma2(aA[4], pack2(q1.x, q1.x), w2);
            fma2(aA[5], pack2(q1.y, q1.y), w2);
            fma2(aA[6], pack2(q1.z, q1.z), w2);
            fma2(aA[7], pack2(q1.w, q1.w), w2);
        }
        float sk = skip[t0];
        float alpha = 1.f / (1.f + __expf(-sk));
        float beta  = 1.f - alpha;
#pragma unroll
        for (int j = 0; j < 8; j++) {
            int nd = nodes_s[jb + j];
            if (nd < 0) continue;
            float lo, hi;
            unpack2(aA[j], lo, hi);
            float2 xv = *(const float2*)&x[nd * DD + d0];
            *(float2*)&out[nd * DD + d0] =
                make_float2(lo * alpha + xv.x * beta, hi * alpha + xv.y * beta);
        }
    } else {
        for (int j = 0; j < 8; j++) {
            int nd = nodes_s[jb + j];
            if (nd < 0) continue;
            int t = types_s[jb + j];
            float2 aA = *(const float2*)&Ab[t * DD + d0];
            for (int k = 0; k < DD; k++) {
                float gv = gsN[k][jb + j];
                float2 w = *(const float2*)&Aw[(t * DD + k) * DD + d0];
                aA.x += gv * w.x; aA.y += gv * w.y;
            }
            float sk = skip[t];
            float alpha = 1.f / (1.f + __expf(-sk));
            float beta  = 1.f - alpha;
            float2 xv = *(const float2*)&x[nd * DD + d0];
            *(float2*)&out[nd * DD + d0] =
                make_float2(aA.x * alpha + xv.x * beta, aA.y * alpha + xv.y * beta);
        }
    }
}

// --------------------------------- launcher -----------------------------------
extern "C" void kernel_launch(void* const* d_in, const int* in_sizes, int n_in,
                              void* d_out, int out_size) {
    const float* node_inp  = (const float*)d_in[0];
    const int*   node_type = (const int*)  d_in[1];
    const int*   edge_index= (const int*)  d_in[2];
    const int*   edge_type = (const int*)  d_in[3];
    const float* Kw = (const float*)d_in[5];
    const float* Kb = (const float*)d_in[6];
    const float* Qw = (const float*)d_in[7];
    const float* Qb = (const float*)d_in[8];
    const float* Vw = (const float*)d_in[9];
    const float* Vb = (const float*)d_in[10];
    const float* Aw = (const float*)d_in[11];
    const float* Ab = (const float*)d_in[12];
    const float* pri  = (const float*)d_in[13];
    const float* Ratt = (const float*)d_in[14];
    const float* Rmsg = (const float*)d_in[15];
    const float* s2u  = (const float*)d_in[16];
    const float* skip = (const float*)d_in[17];
    float* out = (float*)d_out;

    int n = in_sizes[1];
    int e = in_sizes[3];
    if (n > NMAX) n = NMAX;
    if (e > EMAX) e = EMAX;
    int n4 = n * RR;

    int nb  = (n + 255) / 256;
    int n4b = (n4 + 255) / 256;
    int eb  = (e + 255) / 256;
    int sb  = (n4 + 1023) / 1024;
    int ngb = (n + GN - 1) / GN;

    cudaFuncSetAttribute(k_gemm_proj, cudaFuncAttributeMaxDynamicSharedMemorySize, SMEM_GEMM);

    k_init<<<n4b + 65 + 16, 256>>>(Vw, Vb, s2u, Ratt, n, n4b);
    k_nodehist<<<nb, 256>>>(node_type, n);
    k_nodescatter<<<nb, 256>>>(node_type, n);
    k_gemm_proj<<<dim3(ngb, 5), 256, SMEM_GEMM>>>(node_inp, node_type,
                                                  Kw, Kb, Qw, Qb, Vw, Vb, n);
    k_edgestats<<<eb, 256>>>(edge_index, edge_type, e);
    k_scan1<<<sb, 1024>>>(n4);
    k_scan2<<<1, 32>>>(sb, n4);
    k_scan3<<<n4b, 256>>>(n4);
    k_scatter_edges<<<eb, 256>>>(edge_index, edge_type, node_type, e);
    k_attn<<<(n + 7) / 8, 256>>>(node_type, pri, Rmsg, n);
    k_final<<<(n + NPB - 1) / NPB, 256>>>(node_inp, node_type, edge_index,
                                          Aw, Ab, skip, out, n, e);
}

// round 15
// speedup vs baseline: 1.4081x; 1.0440x over previous
#include <cuda_runtime.h>
#include <math.h>

#define NMAX 40000
#define EMAX 640000
#define DD   128
#define HH   8
#define DKK  16
#define TT   3
#define RR   4
#define N4   (NMAX * RR)

#define GN      128            // nodes per gemm block
#define XSTRIDE 132            // xs row stride (floats)
#define KTILE   32
#define NTILE   (DD / KTILE)
#define XS_BYTES (DD * XSTRIDE * 4)
#define WB_BYTES (2 * KTILE * 64 * 4)
#define SMEM_GEMM (XS_BYTES + WB_BYTES + GN * 2 * 4)
#define QST     68             // node-major q stash row stride (floats)

#define NPB  32              // nodes per final block
#define GST  36              // gsN row stride (floats)

typedef unsigned long long ull;

// ---------------- scratch (device globals) ------------------------------------
__device__ float g_k   [NMAX * DD];
__device__ float g_v   [NMAX * DD];
__device__ float g_qt  [NMAX * RR * DD];
__device__ float g_sp  [NMAX * DD];
__device__ float g_aggr[NMAX * DD];
__device__ float g_Wsp [DD * DD];
__device__ float g_bsp [DD];
__device__ ull   g_Rp  [RR * HH * 8 * DKK];
__device__ int   g_win [NMAX];
__device__ int   g_thist[N4];
__device__ int   g_toff [N4 + 1];
__device__ int   g_tcur [N4];
__device__ int   g_epack[EMAX];
__device__ int   g_bsum [256];
__device__ int   g_typehist[TT];
__device__ int   g_typecur [TT];
__device__ int   g_perm [NMAX];

// ---------------- packed f32x2 helpers ----------------------------------------
__device__ __forceinline__ ull pack2(float a, float b) {
    ull r;
    asm("mov.b64 %0, {%1, %2};" : "=l"(r) : "f"(a), "f"(b));
    return r;
}
__device__ __forceinline__ void unpack2(ull v, float& lo, float& hi) {
    asm("mov.b64 {%0, %1}, %2;" : "=f"(lo), "=f"(hi) : "l"(v));
}
__device__ __forceinline__ void fma2(ull& acc, ull x, ull w) {
    asm("fma.rn.f32x2 %0, %1, %2, %0;" : "+l"(acc) : "l"(x), "l"(w));
}
__device__ __forceinline__ void cpasync16(void* dst, const void* src) {
    unsigned int da = (unsigned int)__cvta_generic_to_shared(dst);
    asm volatile("cp.async.cg.shared.global [%0], [%1], 16;"
                 :: "r"(da), "l"(src) : "memory");
}

// ------------------ init: zero hists + Wsp + packed Ratt ----------------------
__global__ void k_init(const float* __restrict__ Vw, const float* __restrict__ Vb,
                       const float* __restrict__ s2u, const float* __restrict__ Ratt,
                       int n, int zb) {
    int b = blockIdx.x;
    if (b < zb) {
        int i = b * 256 + threadIdx.x;
        if (i < n) g_win[i] = -1;
        if (i < 4 * n) g_thist[i] = 0;
        if (i < TT) { g_typehist[i] = 0; g_typecur[i] = 0; }
    } else if (b < zb + 65) {
        int bi  = b - zb;
        int row = bi * 2 + (threadIdx.x >> 7);
        int d   = threadIdx.x & 127;
        if (row < DD) {
            float acc = 0.f;
            for (int m = 0; m < DD; m++)
                acc += Vw[(DD + row) * DD + m] * s2u[m * DD + d];
            g_Wsp[row * DD + d] = acc;
        } else if (row == DD) {
            float acc = 0.f;
            for (int m = 0; m < DD; m++)
                acc += Vb[DD + m] * s2u[m * DD + d];
            g_bsp[d] = acc;
        }
    } else {
        int idx = (b - zb - 65) * 256 + threadIdx.x;
        if (idx < RR * HH * 8 * DKK) {
            int f   = idx & 15;
            int dkp = (idx >> 4) & 7;
            int h   = (idx >> 7) & 7;
            int r   = idx >> 10;
            float a0 = Ratt[((r * HH + h) * DKK + 2 * dkp)     * DKK + f];
            float a1 = Ratt[((r * HH + h) * DKK + 2 * dkp + 1) * DKK + f];
            g_Rp[idx] = pack2(a0, a1);
        }
    }
}

__global__ void k_nodehist(const int* __restrict__ ntype, int n) {
    int i = blockIdx.x * blockDim.x + threadIdx.x;
    if (i < n) atomicAdd(&g_typehist[ntype[i]], 1);
}

__global__ void k_nodescatter(const int* __restrict__ ntype, int n) {
    int i = blockIdx.x * blockDim.x + threadIdx.x;
    if (i >= n) return;
    int t = ntype[i];
    int off = 0;
    for (int ty = 0; ty < TT; ty++) if (ty < t) off += g_typehist[ty];
    int pos = off + atomicAdd(&g_typecur[t], 1);
    g_perm[pos] = i;
}

// ----------------- register-tiled GEMM: K/Q/V/speaker projections -------------
// grid: (ceil(n/128), 5).
//   y=0: K both halves; y=1: V both halves; y=2: Wsp both halves;
//   y=3: Q half 0 (+qt); y=4: Q half 1 (+qt).
__global__ void __launch_bounds__(256, 2)
k_gemm_proj(const float* __restrict__ x, const int* __restrict__ ntype,
            const float* __restrict__ Kw, const float* __restrict__ Kb,
            const float* __restrict__ Qw, const float* __restrict__ Qb,
            const float* __restrict__ Vw, const float* __restrict__ Vb, int n) {
    extern __shared__ __align__(16) unsigned char sraw[];
    float (*xs)[XSTRIDE] = (float (*)[XSTRIDE])sraw;
    float* qs = (float*)sraw;                     // overlay: node-major q stash
    float (*wbuf)[KTILE][64] = (float (*)[KTILE][64])(sraw + XS_BYTES);
    int* nodes_s = (int*)(sraw + XS_BYTES + WB_BYTES);
    int* types_s = nodes_s + GN;
    __shared__ int s_uni;

    int tid  = threadIdx.x;
    int base = blockIdx.x * GN;
    if (tid == 0) s_uni = 1;
    if (tid < GN) {
        int idx  = base + tid;
        int cidx = (idx < n) ? idx : (n - 1);
        nodes_s[tid] = (idx < n) ? g_perm[idx] : -1;
        types_s[tid] = ntype[g_perm[cidx]];
    }
    __syncthreads();
    if (tid < GN && types_s[tid] != types_s[0]) s_uni = 0;
    __syncthreads();
    int  t0      = types_s[0];
    bool uniform = (s_uni != 0);

    int yb = blockIdx.y;
    int mat;                 // 0=K, 1=Q, 2=V, 3=Wsp
    int half0, nhalf;
    if (yb == 0)      { mat = 0; half0 = 0;  nhalf = 2; }
    else if (yb == 1) { mat = 2; half0 = 0;  nhalf = 2; }
    else if (yb == 2) { mat = 3; half0 = 0;  nhalf = 2; }
    else              { mat = 1; half0 = (yb - 3) * 64; nhalf = 1; }

    const float* W; const float* B; float* dst;
    switch (mat) {
        case 0:  W = Kw + t0 * DD * DD; B = Kb + t0 * DD; dst = g_k;  break;
        case 1:  W = Qw + t0 * DD * DD; B = Qb + t0 * DD; dst = 0;    break;
        case 2:  W = Vw + t0 * DD * DD; B = Vb + t0 * DD; dst = g_v;  break;
        default: W = g_Wsp;             B = g_bsp;        dst = g_sp; break;
    }

    if (uniform) {   // prologue for first half
#pragma unroll
        for (int q = 0; q < 2; q++) {
            int f4  = tid + q * 256;
            int row = f4 >> 4;
            int c4  = f4 & 15;
            cpasync16(&wbuf[0][row][c4 * 4], W + row * DD + half0 + c4 * 4);
        }
        asm volatile("cp.async.commit_group;" ::: "memory");
    }

    // stage x transposed -- conflict-reduced mapping
    {
        int jq = tid & 3;
        int cq = (tid >> 2) & 31;
        int gq = tid >> 7;
#pragma unroll 4
        for (int it = 0; it < 16; it++) {
            int j  = it * 8 + gq * 4 + jq;
            int nd = nodes_s[j];
            float4 v = (nd >= 0) ? *(const float4*)&x[nd * DD + cq * 4]
                                 : make_float4(0.f, 0.f, 0.f, 0.f);
            xs[cq * 4 + 0][j] = v.x;
            xs[cq * 4 + 1][j] = v.y;
            xs[cq * 4 + 2][j] = v.z;
            xs[cq * 4 + 3][j] = v.w;
        }
    }
    __syncthreads();

    int cn = tid & 15, nn = tid >> 4;
    int nb0  = nn * 8;

    if (uniform) {
        for (int hh = 0; hh < nhalf; hh++) {
            int half = half0 + hh * 64;
            int col0 = half + cn * 4;

            float4 bv = *(const float4*)&B[col0];
            ull acc[4][4];
            {
                ull bb0 = pack2(bv.x, bv.x), bb1 = pack2(bv.y, bv.y);
                ull bb2 = pack2(bv.z, bv.z), bb3 = pack2(bv.w, bv.w);
#pragma unroll
                for (int np = 0; np < 4; np++) {
                    acc[np][0] = bb0; acc[np][1] = bb1; acc[np][2] = bb2; acc[np][3] = bb3;
                }
            }

            for (int tile = 0; tile < NTILE; tile++) {
                bool more = (tile + 1 < NTILE) || (hh + 1 < nhalf);
                if (more) {
                    int stg = (tile + 1) & 1;
                    int nrow0 = (tile + 1 < NTILE) ? (tile + 1) * KTILE : 0;
                    int nhalfoff = (tile + 1 < NTILE) ? half : half0 + (hh + 1) * 64;
#pragma unroll
                    for (int q = 0; q < 2; q++) {
                        int f4  = tid + q * 256;
                        int row = f4 >> 4;
                        int c4  = f4 & 15;
                        cpasync16(&wbuf[stg][row][c4 * 4],
                                  W + (nrow0 + row) * DD + nhalfoff + c4 * 4);
                    }
                    asm volatile("cp.async.commit_group;" ::: "memory");
                    asm volatile("cp.async.wait_group 1;" ::: "memory");
                } else {
                    asm volatile("cp.async.wait_group 0;" ::: "memory");
                }
                __syncthreads();
                int cur = tile & 1;
#pragma unroll
                for (int kk = 0; kk < KTILE; kk++) {
                    int k = tile * KTILE + kk;
                    ulonglong2 xlo = *(const ulonglong2*)&xs[k][nb0];
                    ulonglong2 xhi = *(const ulonglong2*)&xs[k][nb0 + 4];
                    float4 wv = *(const float4*)&wbuf[cur][kk][cn * 4];
                    ull w0 = pack2(wv.x, wv.x), w1 = pack2(wv.y, wv.y);
                    ull w2 = pack2(wv.z, wv.z), w3 = pack2(wv.w, wv.w);
                    fma2(acc[0][0], xlo.x, w0); fma2(acc[0][1], xlo.x, w1);
                    fma2(acc[0][2], xlo.x, w2); fma2(acc[0][3], xlo.x, w3);
                    fma2(acc[1][0], xlo.y, w0); fma2(acc[1][1], xlo.y, w1);
                    fma2(acc[1][2], xlo.y, w2); fma2(acc[1][3], xlo.y, w3);
                    fma2(acc[2][0], xhi.x, w0); fma2(acc[2][1], xhi.x, w1);
                    fma2(acc[2][2], xhi.x, w2); fma2(acc[2][3], xhi.x, w3);
                    fma2(acc[3][0], xhi.y, w0); fma2(acc[3][1], xhi.y, w1);
                    fma2(acc[3][2], xhi.y, w2); fma2(acc[3][3], xhi.y, w3);
                }
                __syncthreads();
            }

            if (mat != 1) {
#pragma unroll
                for (int np = 0; np < 4; np++) {
                    int n0 = nodes_s[nb0 + np * 2], n1 = nodes_s[nb0 + np * 2 + 1];
                    float4 o0, o1;
                    unpack2(acc[np][0], o0.x, o1.x);
                    unpack2(acc[np][1], o0.y, o1.y);
                    unpack2(acc[np][2], o0.z, o1.z);
                    unpack2(acc[np][3], o0.w, o1.w);
                    if (n0 >= 0) *(float4*)&dst[n0 * DD + col0] = o0;
                    if (n1 >= 0) *(float4*)&dst[n1 * DD + col0] = o1;
                }
            } else {
#pragma unroll
                for (int np = 0; np < 4; np++) {
                    int j0 = nb0 + np * 2;
                    float4 o0, o1;
                    unpack2(acc[np][0], o0.x, o1.x);
                    unpack2(acc[np][1], o0.y, o1.y);
                    unpack2(acc[np][2], o0.z, o1.z);
                    unpack2(acc[np][3], o0.w, o1.w);
                    *(float4*)&qs[j0 * QST + cn * 4]       = o0;
                    *(float4*)&qs[(j0 + 1) * QST + cn * 4] = o1;
                }
            }
        }
    } else {
        for (int hh = 0; hh < nhalf; hh++) {
            int half = half0 + hh * 64;
            int col0 = half + cn * 4;
            float4 qtmp[8];
            for (int j = 0; j < 8; j++) {
                int node = nb0 + j;
                int nd = nodes_s[node];
                int t = types_s[node];
                const float* Wt; const float* Bt;
                switch (mat) {
                    case 0:  Wt = Kw + t * DD * DD; Bt = Kb + t * DD; break;
                    case 1:  Wt = Qw + t * DD * DD; Bt = Qb + t * DD; break;
                    case 2:  Wt = Vw + t * DD * DD; Bt = Vb + t * DD; break;
                    default: Wt = g_Wsp;            Bt = g_bsp;       break;
                }
                float4 a = *(const float4*)&Bt[col0];
                for (int k = 0; k < DD; k++) {
                    float xv = xs[k][node];
                    float4 w = *(const float4*)&Wt[k * DD + col0];
                    a.x += xv * w.x; a.y += xv * w.y; a.z += xv * w.z; a.w += xv * w.w;
                }
                if (mat != 1) {
                    if (nd >= 0) *(float4*)&dst[nd * DD + col0] = a;
                } else {
                    qtmp[j] = a;
                }
            }
            if (mat == 1) {
                __syncthreads();
#pragma unroll
                for (int j = 0; j < 8; j++) {
                    *(float4*)&qs[(nb0 + j) * QST + cn * 4] = qtmp[j];
                }
            }
        }
    }

    // ---------------- in-block q' transform (Q blocks only) -------------------
    if (mat == 1) {
        __syncthreads();
        int slot = tid & 31;
        int grp  = tid >> 5;
        int dloc = 2 * slot;
        int d0g  = half0 + dloc;
        int h    = d0g >> 4;
        int dkp  = (d0g >> 1) & 7;
        int hrow = dloc & 0x30;
        const ull* rp = g_Rp + (h * 8 + dkp) * DKK;
#pragma unroll
        for (int r = 0; r < RR; r++) {
            ull w[DKK];
#pragma unroll
            for (int f = 0; f < DKK; f++) w[f] = rp[r * 1024 + f];
            for (int jj = 0; jj < 16; jj++) {
                int jloc = grp * 16 + jj;
                int nd   = nodes_s[jloc];
                const float* qrow = &qs[jloc * QST + hrow];
                float4 q0 = *(const float4*)&qrow[0];
                float4 q1 = *(const float4*)&qrow[4];
                float4 q2 = *(const float4*)&qrow[8];
                float4 q3 = *(const float4*)&qrow[12];
                ull acc = 0;
                fma2(acc, pack2(q0.x, q0.x), w[0]);
                fma2(acc, pack2(q0.y, q0.y), w[1]);
                fma2(acc, pack2(q0.z, q0.z), w[2]);
                fma2(acc, pack2(q0.w, q0.w), w[3]);
                fma2(acc, pack2(q1.x, q1.x), w[4]);
                fma2(acc, pack2(q1.y, q1.y), w[5]);
                fma2(acc, pack2(q1.z, q1.z), w[6]);
                fma2(acc, pack2(q1.w, q1.w), w[7]);
                fma2(acc, pack2(q2.x, q2.x), w[8]);
                fma2(acc, pack2(q2.y, q2.y), w[9]);
                fma2(acc, pack2(q2.z, q2.z), w[10]);
                fma2(acc, pack2(q2.w, q2.w), w[11]);
                fma2(acc, pack2(q3.x, q3.x), w[12]);
                fma2(acc, pack2(q3.y, q3.y), w[13]);
                fma2(acc, pack2(q3.z, q3.z), w[14]);
                fma2(acc, pack2(q3.w, q3.w), w[15]);
                if (nd >= 0) {
                    float lo, hi;
                    unpack2(acc, lo, hi);
                    *(float2*)&g_qt[(nd * RR + r) * DD + d0g] = make_float2(lo, hi);
                }
            }
        }
    }
}

// ------------------------------ edge setup ------------------------------------
__global__ void k_edgestats(const int* __restrict__ ei, const int* __restrict__ et, int e) {
    int i = blockIdx.x * blockDim.x + threadIdx.x;
    if (i >= e) return;
    int tgt = ei[e + i];
    int r   = et[i];
    atomicAdd(&g_thist[tgt * RR + r], 1);
    if (r == 0) atomicMax(&g_win[ei[i]], i);
}

__global__ void k_scan1(int n4) {
    __shared__ int buf[1024];
    int t = threadIdx.x;
    int gid = blockIdx.x * 1024 + t;
    int v = (gid < n4) ? g_thist[gid] : 0;
    buf[t] = v;
    __syncthreads();
    for (int off = 1; off < 1024; off <<= 1) {
        int x = (t >= off) ? buf[t - off] : 0;
        __syncthreads();
        buf[t] += x;
        __syncthreads();
    }
    if (gid < n4) g_toff[gid] = buf[t] - v;
    if (t == 1023) g_bsum[blockIdx.x] = buf[t];
}

__global__ void k_scan2(int nblocks, int n4) {
    if (threadIdx.x == 0) {
        int run = 0;
        for (int b = 0; b < nblocks; b++) { int x = g_bsum[b]; g_bsum[b] = run; run += x; }
        g_toff[n4] = run;
    }
}

__global__ void k_scan3(int n4) {
    int gid = blockIdx.x * blockDim.x + threadIdx.x;
    if (gid < n4) {
        int v = g_toff[gid] + g_bsum[gid >> 10];
        g_toff[gid] = v;
        g_tcur[gid] = v;
    }
}

__global__ void k_scatter_edges(const int* __restrict__ ei, const int* __restrict__ et,
                                const int* __restrict__ ntype, int e) {
    int i = blockIdx.x * blockDim.x + threadIdx.x;
    if (i >= e) return;
    int src = ei[i];
    int tgt = ei[e + i];
    int r   = et[i];
    int st  = ntype[src];
    int pos = atomicAdd(&g_tcur[tgt * RR + r], 1);
    g_epack[pos] = src | (st << 16);
}

// ------- attention: warp per target, per-relation sub-loops, 4-wide unroll -----
__global__ void __launch_bounds__(256)
k_attn(const int* __restrict__ ntype, const float* __restrict__ pri,
       const float* __restrict__ Rmsg, int n) {
    __shared__ float accsh[8][RR][DD];
    int warp = threadIdx.x >> 5, lane = threadIdx.x & 31;
    int i = blockIdx.x * 8 + warp;
    if (i >= n) return;
    int d0 = lane * 4;
    int h  = lane >> 2;

    int tt = ntype[i];
    float p0[TT], p1[TT], p2[TT], p3[TT];
#pragma unroll
    for (int st = 0; st < TT; st++) {
        p0[st] = pri[((tt * RR + 0) * TT + st) * HH + h];
        p1[st] = pri[((tt * RR + 1) * TT + st) * HH + h];
        p2[st] = pri[((tt * RR + 2) * TT + st) * HH + h];
        p3[st] = pri[((tt * RR + 3) * TT + st) * HH + h];
    }

    float den = 0.f;
    float4 acc[RR];
#pragma unroll
    for (int r = 0; r < RR; r++) acc[r] = make_float4(0.f, 0.f, 0.f, 0.f);

#pragma unroll
    for (int r = 0; r < RR; r++) {
        int beg = g_toff[i * RR + r], end = g_toff[i * RR + r + 1];
        if (beg == end) continue;
        float4 qtr = *(const float4*)&g_qt[(i * RR + r) * DD + d0];
        float4 a = make_float4(0.f, 0.f, 0.f, 0.f);
        float pA = (r == 0) ? p0[0] : (r == 1) ? p1[0] : (r == 2) ? p2[0] : p3[0];
        float pB = (r == 0) ? p0[1] : (r == 1) ? p1[1] : (r == 2) ? p2[1] : p3[1];
        float pC = (r == 0) ? p0[2] : (r == 1) ? p1[2] : (r == 2) ? p2[2] : p3[2];
        int idx = beg;
        for (; idx + 4 <= end; idx += 4) {
            int pk0 = g_epack[idx];
            int pk1 = g_epack[idx + 1];
            int pk2 = g_epack[idx + 2];
            int pk3 = g_epack[idx + 3];
            int s0 = pk0 & 0xFFFF, st0 = pk0 >> 16;
            int s1 = pk1 & 0xFFFF, st1 = pk1 >> 16;
            int s2 = pk2 & 0xFFFF, st2 = pk2 >> 16;
            int s3 = pk3 & 0xFFFF, st3 = pk3 >> 16;
            const float4 k0 = *(const float4*)&g_k[s0 * DD + d0];
            const float4 k1 = *(const float4*)&g_k[s1 * DD + d0];
            const float4 k2 = *(const float4*)&g_k[s2 * DD + d0];
            const float4 k3 = *(const float4*)&g_k[s3 * DD + d0];
            const float4 v0 = *(const float4*)&g_v[s0 * DD + d0];
            const float4 v1 = *(const float4*)&g_v[s1 * DD + d0];
            const float4 v2 = *(const float4*)&g_v[s2 * DD + d0];
            const float4 v3 = *(const float4*)&g_v[s3 * DD + d0];
            float sa = qtr.x * k0.x + qtr.y * k0.y + qtr.z * k0.z + qtr.w * k0.w;
            float sb = qtr.x * k1.x + qtr.y * k1.y + qtr.z * k1.z + qtr.w * k1.w;
            float sc = qtr.x * k2.x + qtr.y * k2.y + qtr.z * k2.z + qtr.w * k2.w;
            float sd = qtr.x * k3.x + qtr.y * k3.y + qtr.z * k3.z + qtr.w * k3.w;
            sa += __shfl_xor_sync(0xffffffffu, sa, 1);
            sb += __shfl_xor_sync(0xffffffffu, sb, 1);
            sc += __shfl_xor_sync(0xffffffffu, sc, 1);
            sd += __shfl_xor_sync(0xffffffffu, sd, 1);
            sa += __shfl_xor_sync(0xffffffffu, sa, 2);
            sb += __shfl_xor_sync(0xffffffffu, sb, 2);
            sc += __shfl_xor_sync(0xffffffffu, sc, 2);
            sd += __shfl_xor_sync(0xffffffffu, sd, 2);
            float pra = (st0 == 1) ? pB : (st0 == 2) ? pC : pA;
            float prb = (st1 == 1) ? pB : (st1 == 2) ? pC : pA;
            float prc = (st2 == 1) ? pB : (st2 == 2) ? pC : pA;
            float prd = (st3 == 1) ? pB : (st3 == 2) ? pC : pA;
            float pea = __expf(sa * pra * 0.25f);
            float peb = __expf(sb * prb * 0.25f);
            float pec = __expf(sc * prc * 0.25f);
            float ped = __expf(sd * prd * 0.25f);
            den += (pea + peb) + (pec + ped);
            a.x += pea * v0.x + peb * v1.x + pec * v2.x + ped * v3.x;
            a.y += pea * v0.y + peb * v1.y + pec * v2.y + ped * v3.y;
            a.z += pea * v0.z + peb * v1.z + pec * v2.z + ped * v3.z;
            a.w += pea * v0.w + peb * v1.w + pec * v2.w + ped * v3.w;
        }
        for (; idx + 2 <= end; idx += 2) {
            int pk0 = g_epack[idx];
            int pk1 = g_epack[idx + 1];
            int s0 = pk0 & 0xFFFF, st0 = pk0 >> 16;
            int s1 = pk1 & 0xFFFF, st1 = pk1 >> 16;
            const float4 ka = *(const float4*)&g_k[s0 * DD + d0];
            const float4 kb = *(const float4*)&g_k[s1 * DD + d0];
            const float4 va = *(const float4*)&g_v[s0 * DD + d0];
            const float4 vb = *(const float4*)&g_v[s1 * DD + d0];
            float sa = qtr.x * ka.x + qtr.y * ka.y + qtr.z * ka.z + qtr.w * ka.w;
            float sb = qtr.x * kb.x + qtr.y * kb.y + qtr.z * kb.z + qtr.w * kb.w;
            sa += __shfl_xor_sync(0xffffffffu, sa, 1);
            sb += __shfl_xor_sync(0xffffffffu, sb, 1);
            sa += __shfl_xor_sync(0xffffffffu, sa, 2);
            sb += __shfl_xor_sync(0xffffffffu, sb, 2);
            float pra = (st0 == 1) ? pB : (st0 == 2) ? pC : pA;
            float prb = (st1 == 1) ? pB : (st1 == 2) ? pC : pA;
            float pea = __expf(sa * pra * 0.25f);
            float peb = __expf(sb * prb * 0.25f);
            den += pea + peb;
            a.x += pea * va.x + peb * vb.x;
            a.y += pea * va.y + peb * vb.y;
            a.z += pea * va.z + peb * vb.z;
            a.w += pea * va.w + peb * vb.w;
        }
        if (idx < end) {
            int pk  = g_epack[idx];
            int src = pk & 0xFFFF;
            int st  = pk >> 16;
            const float4 k4 = *(const float4*)&g_k[src * DD + d0];
            float s = qtr.x * k4.x + qtr.y * k4.y + qtr.z * k4.z + qtr.w * k4.w;
            s += __shfl_xor_sync(0xffffffffu, s, 1);
            s += __shfl_xor_sync(0xffffffffu, s, 2);
            float pr = (st == 1) ? pB : (st == 2) ? pC : pA;
            float pe = __expf(s * pr * 0.25f);
            den += pe;
            const float4 v4 = *(const float4*)&g_v[src * DD + d0];
            a.x += pe * v4.x;
            a.y += pe * v4.y;
            a.z += pe * v4.z;
            a.w += pe * v4.w;
        }
        acc[r] = a;
    }

    float inv = 1.f / (den + 1e-16f);
#pragma unroll
    for (int r = 0; r < RR; r++) {
        accsh[warp][r][d0 + 0] = acc[r].x * inv;
        accsh[warp][r][d0 + 1] = acc[r].y * inv;
        accsh[warp][r][d0 + 2] = acc[r].z * inv;
        accsh[warp][r][d0 + 3] = acc[r].w * inv;
    }
    __syncwarp();

    int f0 = (lane & 3) * 4;
    float4 o = make_float4(0.f, 0.f, 0.f, 0.f);
#pragma unroll
    for (int r = 0; r < RR; r++) {
#pragma unroll 4
        for (int dk = 0; dk < DKK; dk++) {
            float a = accsh[warp][r][(h << 4) + dk];
            const float4 w = *(const float4*)&Rmsg[(((r * HH + h) * DKK + dk) * DKK) + f0];
            o.x += a * w.x;
            o.y += a * w.y;
            o.z += a * w.z;
            o.w += a * w.w;
        }
    }
    *(float4*)&g_aggr[i * DD + d0] = o;
}

// ------------- final: speaker add + GELU + per-type A projection + skip -------
__global__ void __launch_bounds__(256, 3)
k_final(const float* __restrict__ x, const int* __restrict__ ntype,
        const int* __restrict__ ei,
        const float* __restrict__ Aw, const float* __restrict__ Ab,
        const float* __restrict__ skip, float* __restrict__ out, int n, int e) {
    __shared__ __align__(16) float gsN[DD][GST];
    __shared__ int nodes_s[NPB], types_s[NPB], spsrc_s[NPB];
    int tid  = threadIdx.x;
    int base = blockIdx.x * NPB;
    if (tid < NPB) {
        int idx = base + tid;
        int cidx = (idx < n) ? idx : (n - 1);
        int nd = (idx < n) ? g_perm[idx] : -1;
        nodes_s[tid] = nd;
        types_s[tid] = ntype[g_perm[cidx]];
        int sps = -1;
        if (nd >= 0) {
            int we = g_win[nd];
            if (we >= 0) sps = ei[e + we];
        }
        spsrc_s[tid] = sps;
    }
    __syncthreads();

    for (int idx = tid; idx < NPB * DD; idx += 256) {
        int j = idx >> 7;
        int k = idx & 127;
        int nd = nodes_s[j];
        float v = 0.f;
        if (nd >= 0) {
            v = g_aggr[nd * DD + k];
            int sps = spsrc_s[j];
            if (sps >= 0) v += g_sp[sps * DD + k];
            v = 0.5f * v * (1.f + erff(v * 0.70710678118654752f));
        }
        gsN[k][j] = v;
    }
    __syncthreads();

    int g  = tid >> 6;
    int p  = tid & 63;
    int d0 = 2 * p;
    int jb = g * 8;

    int t0 = types_s[0];
    bool uniform = true;
#pragma unroll
    for (int j = 1; j < NPB; j++) uniform &= (types_s[j] == t0);

    if (uniform) {
        const float* pA = Aw + t0 * DD * DD + d0;
        ull bA = *(const ull*)&Ab[t0 * DD + d0];
        ull aA[8];
#pragma unroll
        for (int j = 0; j < 8; j++) aA[j] = bA;
#pragma unroll 4
        for (int k = 0; k < DD; k++) {
            ull w2 = *(const ull*)&pA[k * DD];
            float4 q0 = *(const float4*)&gsN[k][jb];
            float4 q1 = *(const float4*)&gsN[k][jb + 4];
            fma2(aA[0], pack2(q0.x, q0.x), w2);
            fma2(aA[1], pack2(q0.y, q0.y), w2);
            fma2(aA[2], pack2(q0.z, q0.z), w2);
            fma2(aA[3], pack2(q0.w, q0.w), w2);
            fma2(aA[4], pack2(q1.x, q1.x), w2);
            fma2(aA[5], pack2(q1.y, q1.y), w2);
            fma2(aA[6], pack2(q1.z, q1.z), w2);
            fma2(aA[7], pack2(q1.w, q1.w), w2);
        }
        float sk = skip[t0];
        float alpha = 1.f / (1.f + __expf(-sk));
        float beta  = 1.f - alpha;
#pragma unroll
        for (int j = 0; j < 8; j++) {
            int nd = nodes_s[jb + j];
            if (nd < 0) continue;
            float lo, hi;
            unpack2(aA[j], lo, hi);
            float2 xv = *(const float2*)&x[nd * DD + d0];
            *(float2*)&out[nd * DD + d0] =
                make_float2(lo * alpha + xv.x * beta, hi * alpha + xv.y * beta);
        }
    } else {
        for (int j = 0; j < 8; j++) {
            int nd = nodes_s[jb + j];
            if (nd < 0) continue;
            int t = types_s[jb + j];
            float2 aA = *(const float2*)&Ab[t * DD + d0];
            for (int k = 0; k < DD; k++) {
                float gv = gsN[k][jb + j];
                float2 w = *(const float2*)&Aw[(t * DD + k) * DD + d0];
                aA.x += gv * w.x; aA.y += gv * w.y;
            }
            float sk = skip[t];
            float alpha = 1.f / (1.f + __expf(-sk));
            float beta  = 1.f - alpha;
            float2 xv = *(const float2*)&x[nd * DD + d0];
            *(float2*)&out[nd * DD + d0] =
                make_float2(aA.x * alpha + xv.x * beta, aA.y * alpha + xv.y * beta);
        }
    }
}

// --------------------------------- launcher -----------------------------------
extern "C" void kernel_launch(void* const* d_in, const int* in_sizes, int n_in,
                              void* d_out, int out_size) {
    const float* node_inp  = (const float*)d_in[0];
    const int*   node_type = (const int*)  d_in[1];
    const int*   edge_index= (const int*)  d_in[2];
    const int*   edge_type = (const int*)  d_in[3];
    const float* Kw = (const float*)d_in[5];
    const float* Kb = (const float*)d_in[6];
    const float* Qw = (const float*)d_in[7];
    const float* Qb = (const float*)d_in[8];
    const float* Vw = (const float*)d_in[9];
    const float* Vb = (const float*)d_in[10];
    const float* Aw = (const float*)d_in[11];
    const float* Ab = (const float*)d_in[12];
    const float* pri  = (const float*)d_in[13];
    const float* Ratt = (const float*)d_in[14];
    const float* Rmsg = (const float*)d_in[15];
    const float* s2u  = (const float*)d_in[16];
    const float* skip = (const float*)d_in[17];
    float* out = (float*)d_out;

    int n = in_sizes[1];
    int e = in_sizes[3];
    if (n > NMAX) n = NMAX;
    if (e > EMAX) e = EMAX;
    int n4 = n * RR;

    int nb  = (n + 255) / 256;
    int n4b = (n4 + 255) / 256;
    int eb  = (e + 255) / 256;
    int sb  = (n4 + 1023) / 1024;
    int ngb = (n + GN - 1) / GN;

    cudaFuncSetAttribute(k_gemm_proj, cudaFuncAttributeMaxDynamicSharedMemorySize, SMEM_GEMM);

    // side stream + fork/join events (created per call; host-side objects only,
    // never destroyed so captured-graph references stay valid)
    cudaStream_t side;
    cudaStreamCreateWithFlags(&side, cudaStreamNonBlocking);
    cudaEvent_t evFork, evJoin;
    cudaEventCreateWithFlags(&evFork, cudaEventDisableTiming);
    cudaEventCreateWithFlags(&evJoin, cudaEventDisableTiming);

    // main stream: init (zeroes thist/win + Wsp + Rp + type hists)
    k_init<<<n4b + 65 + 16, 256>>>(Vw, Vb, s2u, Ratt, n, n4b);
    cudaEventRecord(evFork, 0);
    cudaStreamWaitEvent(side, evFork, 0);

    // side stream: edge CSR construction (independent of projections)
    k_edgestats<<<eb, 256, 0, side>>>(edge_index, edge_type, e);
    k_scan1<<<sb, 1024, 0, side>>>(n4);
    k_scan2<<<1, 32, 0, side>>>(sb, n4);
    k_scan3<<<n4b, 256, 0, side>>>(n4);
    k_scatter_edges<<<eb, 256, 0, side>>>(edge_index, edge_type, node_type, e);
    cudaEventRecord(evJoin, side);

    // main stream: node permutation + projections (the long pole)
    k_nodehist<<<nb, 256>>>(node_type, n);
    k_nodescatter<<<nb, 256>>>(node_type, n);
    k_gemm_proj<<<dim3(ngb, 5), 256, SMEM_GEMM>>>(node_inp, node_type,
                                                  Kw, Kb, Qw, Qb, Vw, Vb, n);

    // join: attention needs both projections and the edge CSR
    cudaStreamWaitEvent(0, evJoin, 0);
    k_attn<<<(n + 7) / 8, 256>>>(node_type, pri, Rmsg, n);
    k_final<<<(n + NPB - 1) / NPB, 256>>>(node_inp, node_type, edge_index,
                                          Aw, Ab, skip, out, n, e);
}

// round 16
// speedup vs baseline: 1.4487x; 1.0288x over previous
#include <cuda_runtime.h>
#include <cuda_fp16.h>
#include <math.h>

#define NMAX 40000
#define EMAX 640000
#define DD   128
#define HH   8
#define DKK  16
#define TT   3
#define RR   4
#define N4   (NMAX * RR)

#define GN      128            // nodes per gemm block
#define XSTRIDE 132            // xs row stride (floats)
#define KTILE   32
#define NTILE   (DD / KTILE)
#define XS_BYTES (DD * XSTRIDE * 4)
#define WB_BYTES (2 * KTILE * 64 * 4)
#define SMEM_GEMM (XS_BYTES + WB_BYTES + GN * 2 * 4)
#define QST     68             // node-major q stash row stride (floats)

#define NPB  32              // nodes per final block
#define GST  36              // gsN row stride (floats)

typedef unsigned long long ull;

// ---------------- scratch (device globals) ------------------------------------
__device__ __half g_k [NMAX * DD];      // fp16 K rows (written once, read ~16x)
__device__ __half g_v [NMAX * DD];      // fp16 V rows
__device__ float g_qt  [NMAX * RR * DD];
__device__ float g_sp  [NMAX * DD];
__device__ float g_aggr[NMAX * DD];
__device__ float g_Wsp [DD * DD];
__device__ float g_bsp [DD];
__device__ ull   g_Rp  [RR * HH * 8 * DKK];
__device__ int   g_win [NMAX];
__device__ int   g_thist[N4];
__device__ int   g_toff [N4 + 1];
__device__ int   g_tcur [N4];
__device__ int   g_epack[EMAX];
__device__ int   g_bsum [256];
__device__ int   g_typehist[TT];
__device__ int   g_typecur [TT];
__device__ int   g_perm [NMAX];

// ---------------- packed helpers -----------------------------------------------
__device__ __forceinline__ ull pack2(float a, float b) {
    ull r;
    asm("mov.b64 %0, {%1, %2};" : "=l"(r) : "f"(a), "f"(b));
    return r;
}
__device__ __forceinline__ void unpack2(ull v, float& lo, float& hi) {
    asm("mov.b64 {%0, %1}, %2;" : "=f"(lo), "=f"(hi) : "l"(v));
}
__device__ __forceinline__ void fma2(ull& acc, ull x, ull w) {
    asm("fma.rn.f32x2 %0, %1, %2, %0;" : "+l"(acc) : "l"(x), "l"(w));
}
__device__ __forceinline__ void cpasync16(void* dst, const void* src) {
    unsigned int da = (unsigned int)__cvta_generic_to_shared(dst);
    asm volatile("cp.async.cg.shared.global [%0], [%1], 16;"
                 :: "r"(da), "l"(src) : "memory");
}
__device__ __forceinline__ unsigned int ph2(float a, float b) {
    __half2 h = __floats2half2_rn(a, b);
    return *(unsigned int*)&h;
}

// ------------------ init: zero hists + Wsp + packed Ratt ----------------------
__global__ void k_init(const float* __restrict__ Vw, const float* __restrict__ Vb,
                       const float* __restrict__ s2u, const float* __restrict__ Ratt,
                       int n, int zb) {
    int b = blockIdx.x;
    if (b < zb) {
        int i = b * 256 + threadIdx.x;
        if (i < n) g_win[i] = -1;
        if (i < 4 * n) g_thist[i] = 0;
        if (i < TT) { g_typehist[i] = 0; g_typecur[i] = 0; }
    } else if (b < zb + 65) {
        int bi  = b - zb;
        int row = bi * 2 + (threadIdx.x >> 7);
        int d   = threadIdx.x & 127;
        if (row < DD) {
            float acc = 0.f;
            for (int m = 0; m < DD; m++)
                acc += Vw[(DD + row) * DD + m] * s2u[m * DD + d];
            g_Wsp[row * DD + d] = acc;
        } else if (row == DD) {
            float acc = 0.f;
            for (int m = 0; m < DD; m++)
                acc += Vb[DD + m] * s2u[m * DD + d];
            g_bsp[d] = acc;
        }
    } else {
        int idx = (b - zb - 65) * 256 + threadIdx.x;
        if (idx < RR * HH * 8 * DKK) {
            int f   = idx & 15;
            int dkp = (idx >> 4) & 7;
            int h   = (idx >> 7) & 7;
            int r   = idx >> 10;
            float a0 = Ratt[((r * HH + h) * DKK + 2 * dkp)     * DKK + f];
            float a1 = Ratt[((r * HH + h) * DKK + 2 * dkp + 1) * DKK + f];
            g_Rp[idx] = pack2(a0, a1);
        }
    }
}

__global__ void k_nodehist(const int* __restrict__ ntype, int n) {
    int i = blockIdx.x * blockDim.x + threadIdx.x;
    if (i < n) atomicAdd(&g_typehist[ntype[i]], 1);
}

__global__ void k_nodescatter(const int* __restrict__ ntype, int n) {
    int i = blockIdx.x * blockDim.x + threadIdx.x;
    if (i >= n) return;
    int t = ntype[i];
    int off = 0;
    for (int ty = 0; ty < TT; ty++) if (ty < t) off += g_typehist[ty];
    int pos = off + atomicAdd(&g_typecur[t], 1);
    g_perm[pos] = i;
}

// ----------------- register-tiled GEMM: K/Q/V/speaker projections -------------
// grid: (ceil(n/128), 5).
__global__ void __launch_bounds__(256, 2)
k_gemm_proj(const float* __restrict__ x, const int* __restrict__ ntype,
            const float* __restrict__ Kw, const float* __restrict__ Kb,
            const float* __restrict__ Qw, const float* __restrict__ Qb,
            const float* __restrict__ Vw, const float* __restrict__ Vb, int n) {
    extern __shared__ __align__(16) unsigned char sraw[];
    float (*xs)[XSTRIDE] = (float (*)[XSTRIDE])sraw;
    float* qs = (float*)sraw;                     // overlay: node-major q stash
    float (*wbuf)[KTILE][64] = (float (*)[KTILE][64])(sraw + XS_BYTES);
    int* nodes_s = (int*)(sraw + XS_BYTES + WB_BYTES);
    int* types_s = nodes_s + GN;
    __shared__ int s_uni;

    int tid  = threadIdx.x;
    int base = blockIdx.x * GN;
    if (tid == 0) s_uni = 1;
    if (tid < GN) {
        int idx  = base + tid;
        int cidx = (idx < n) ? idx : (n - 1);
        nodes_s[tid] = (idx < n) ? g_perm[idx] : -1;
        types_s[tid] = ntype[g_perm[cidx]];
    }
    __syncthreads();
    if (tid < GN && types_s[tid] != types_s[0]) s_uni = 0;
    __syncthreads();
    int  t0      = types_s[0];
    bool uniform = (s_uni != 0);

    int yb = blockIdx.y;
    int mat;                 // 0=K, 1=Q, 2=V, 3=Wsp
    int half0, nhalf;
    if (yb == 0)      { mat = 0; half0 = 0;  nhalf = 2; }
    else if (yb == 1) { mat = 2; half0 = 0;  nhalf = 2; }
    else if (yb == 2) { mat = 3; half0 = 0;  nhalf = 2; }
    else              { mat = 1; half0 = (yb - 3) * 64; nhalf = 1; }

    const float* W; const float* B;
    __half* hdst = 0; float* fdst = 0;
    switch (mat) {
        case 0:  W = Kw + t0 * DD * DD; B = Kb + t0 * DD; hdst = g_k;  break;
        case 1:  W = Qw + t0 * DD * DD; B = Qb + t0 * DD;              break;
        case 2:  W = Vw + t0 * DD * DD; B = Vb + t0 * DD; hdst = g_v;  break;
        default: W = g_Wsp;             B = g_bsp;        fdst = g_sp; break;
    }

    if (uniform) {   // prologue for first half
#pragma unroll
        for (int q = 0; q < 2; q++) {
            int f4  = tid + q * 256;
            int row = f4 >> 4;
            int c4  = f4 & 15;
            cpasync16(&wbuf[0][row][c4 * 4], W + row * DD + half0 + c4 * 4);
        }
        asm volatile("cp.async.commit_group;" ::: "memory");
    }

    // stage x transposed -- conflict-reduced mapping
    {
        int jq = tid & 3;
        int cq = (tid >> 2) & 31;
        int gq = tid >> 7;
#pragma unroll 4
        for (int it = 0; it < 16; it++) {
            int j  = it * 8 + gq * 4 + jq;
            int nd = nodes_s[j];
            float4 v = (nd >= 0) ? *(const float4*)&x[nd * DD + cq * 4]
                                 : make_float4(0.f, 0.f, 0.f, 0.f);
            xs[cq * 4 + 0][j] = v.x;
            xs[cq * 4 + 1][j] = v.y;
            xs[cq * 4 + 2][j] = v.z;
            xs[cq * 4 + 3][j] = v.w;
        }
    }
    __syncthreads();

    int cn = tid & 15, nn = tid >> 4;
    int nb0  = nn * 8;

    if (uniform) {
        for (int hh = 0; hh < nhalf; hh++) {
            int half = half0 + hh * 64;
            int col0 = half + cn * 4;

            float4 bv = *(const float4*)&B[col0];
            ull acc[4][4];
            {
                ull bb0 = pack2(bv.x, bv.x), bb1 = pack2(bv.y, bv.y);
                ull bb2 = pack2(bv.z, bv.z), bb3 = pack2(bv.w, bv.w);
#pragma unroll
                for (int np = 0; np < 4; np++) {
                    acc[np][0] = bb0; acc[np][1] = bb1; acc[np][2] = bb2; acc[np][3] = bb3;
                }
            }

            for (int tile = 0; tile < NTILE; tile++) {
                bool more = (tile + 1 < NTILE) || (hh + 1 < nhalf);
                if (more) {
                    int stg = (tile + 1) & 1;
                    int nrow0 = (tile + 1 < NTILE) ? (tile + 1) * KTILE : 0;
                    int nhalfoff = (tile + 1 < NTILE) ? half : half0 + (hh + 1) * 64;
#pragma unroll
                    for (int q = 0; q < 2; q++) {
                        int f4  = tid + q * 256;
                        int row = f4 >> 4;
                        int c4  = f4 & 15;
                        cpasync16(&wbuf[stg][row][c4 * 4],
                                  W + (nrow0 + row) * DD + nhalfoff + c4 * 4);
                    }
                    asm volatile("cp.async.commit_group;" ::: "memory");
                    asm volatile("cp.async.wait_group 1;" ::: "memory");
                } else {
                    asm volatile("cp.async.wait_group 0;" ::: "memory");
                }
                __syncthreads();
                int cur = tile & 1;
#pragma unroll
                for (int kk = 0; kk < KTILE; kk++) {
                    int k = tile * KTILE + kk;
                    ulonglong2 xlo = *(const ulonglong2*)&xs[k][nb0];
                    ulonglong2 xhi = *(const ulonglong2*)&xs[k][nb0 + 4];
                    float4 wv = *(const float4*)&wbuf[cur][kk][cn * 4];
                    ull w0 = pack2(wv.x, wv.x), w1 = pack2(wv.y, wv.y);
                    ull w2 = pack2(wv.z, wv.z), w3 = pack2(wv.w, wv.w);
                    fma2(acc[0][0], xlo.x, w0); fma2(acc[0][1], xlo.x, w1);
                    fma2(acc[0][2], xlo.x, w2); fma2(acc[0][3], xlo.x, w3);
                    fma2(acc[1][0], xlo.y, w0); fma2(acc[1][1], xlo.y, w1);
                    fma2(acc[1][2], xlo.y, w2); fma2(acc[1][3], xlo.y, w3);
                    fma2(acc[2][0], xhi.x, w0); fma2(acc[2][1], xhi.x, w1);
                    fma2(acc[2][2], xhi.x, w2); fma2(acc[2][3], xhi.x, w3);
                    fma2(acc[3][0], xhi.y, w0); fma2(acc[3][1], xhi.y, w1);
                    fma2(acc[3][2], xhi.y, w2); fma2(acc[3][3], xhi.y, w3);
                }
                __syncthreads();
            }

            if (mat == 1) {
#pragma unroll
                for (int np = 0; np < 4; np++) {
                    int j0 = nb0 + np * 2;
                    float4 o0, o1;
                    unpack2(acc[np][0], o0.x, o1.x);
                    unpack2(acc[np][1], o0.y, o1.y);
                    unpack2(acc[np][2], o0.z, o1.z);
                    unpack2(acc[np][3], o0.w, o1.w);
                    *(float4*)&qs[j0 * QST + cn * 4]       = o0;
                    *(float4*)&qs[(j0 + 1) * QST + cn * 4] = o1;
                }
            } else if (mat == 3) {
#pragma unroll
                for (int np = 0; np < 4; np++) {
                    int n0 = nodes_s[nb0 + np * 2], n1 = nodes_s[nb0 + np * 2 + 1];
                    float4 o0, o1;
                    unpack2(acc[np][0], o0.x, o1.x);
                    unpack2(acc[np][1], o0.y, o1.y);
                    unpack2(acc[np][2], o0.z, o1.z);
                    unpack2(acc[np][3], o0.w, o1.w);
                    if (n0 >= 0) *(float4*)&fdst[n0 * DD + col0] = o0;
                    if (n1 >= 0) *(float4*)&fdst[n1 * DD + col0] = o1;
                }
            } else {
#pragma unroll
                for (int np = 0; np < 4; np++) {
                    int n0 = nodes_s[nb0 + np * 2], n1 = nodes_s[nb0 + np * 2 + 1];
                    float4 o0, o1;
                    unpack2(acc[np][0], o0.x, o1.x);
                    unpack2(acc[np][1], o0.y, o1.y);
                    unpack2(acc[np][2], o0.z, o1.z);
                    unpack2(acc[np][3], o0.w, o1.w);
                    if (n0 >= 0) {
                        uint2 p = make_uint2(ph2(o0.x, o0.y), ph2(o0.z, o0.w));
                        *(uint2*)&hdst[n0 * DD + col0] = p;
                    }
                    if (n1 >= 0) {
                        uint2 p = make_uint2(ph2(o1.x, o1.y), ph2(o1.z, o1.w));
                        *(uint2*)&hdst[n1 * DD + col0] = p;
                    }
                }
            }
        }
    } else {
        for (int hh = 0; hh < nhalf; hh++) {
            int half = half0 + hh * 64;
            int col0 = half + cn * 4;
            float4 qtmp[8];
            for (int j = 0; j < 8; j++) {
                int node = nb0 + j;
                int nd = nodes_s[node];
                int t = types_s[node];
                const float* Wt; const float* Bt;
                switch (mat) {
                    case 0:  Wt = Kw + t * DD * DD; Bt = Kb + t * DD; break;
                    case 1:  Wt = Qw + t * DD * DD; Bt = Qb + t * DD; break;
                    case 2:  Wt = Vw + t * DD * DD; Bt = Vb + t * DD; break;
                    default: Wt = g_Wsp;            Bt = g_bsp;       break;
                }
                float4 a = *(const float4*)&Bt[col0];
                for (int k = 0; k < DD; k++) {
                    float xv = xs[k][node];
                    float4 w = *(const float4*)&Wt[k * DD + col0];
                    a.x += xv * w.x; a.y += xv * w.y; a.z += xv * w.z; a.w += xv * w.w;
                }
                if (mat == 1) {
                    qtmp[j] = a;
                } else if (mat == 3) {
                    if (nd >= 0) *(float4*)&fdst[nd * DD + col0] = a;
                } else {
                    if (nd >= 0) {
                        uint2 p = make_uint2(ph2(a.x, a.y), ph2(a.z, a.w));
                        *(uint2*)&hdst[nd * DD + col0] = p;
                    }
                }
            }
            if (mat == 1) {
                __syncthreads();
#pragma unroll
                for (int j = 0; j < 8; j++) {
                    *(float4*)&qs[(nb0 + j) * QST + cn * 4] = qtmp[j];
                }
            }
        }
    }

    // ---------------- in-block q' transform (Q blocks only) -------------------
    if (mat == 1) {
        __syncthreads();
        int slot = tid & 31;
        int grp  = tid >> 5;
        int dloc = 2 * slot;
        int d0g  = half0 + dloc;
        int h    = d0g >> 4;
        int dkp  = (d0g >> 1) & 7;
        int hrow = dloc & 0x30;
        const ull* rp = g_Rp + (h * 8 + dkp) * DKK;
#pragma unroll
        for (int r = 0; r < RR; r++) {
            ull w[DKK];
#pragma unroll
            for (int f = 0; f < DKK; f++) w[f] = rp[r * 1024 + f];
            for (int jj = 0; jj < 16; jj++) {
                int jloc = grp * 16 + jj;
                int nd   = nodes_s[jloc];
                const float* qrow = &qs[jloc * QST + hrow];
                float4 q0 = *(const float4*)&qrow[0];
                float4 q1 = *(const float4*)&qrow[4];
                float4 q2 = *(const float4*)&qrow[8];
                float4 q3 = *(const float4*)&qrow[12];
                ull acc = 0;
                fma2(acc, pack2(q0.x, q0.x), w[0]);
                fma2(acc, pack2(q0.y, q0.y), w[1]);
                fma2(acc, pack2(q0.z, q0.z), w[2]);
                fma2(acc, pack2(q0.w, q0.w), w[3]);
                fma2(acc, pack2(q1.x, q1.x), w[4]);
                fma2(acc, pack2(q1.y, q1.y), w[5]);
                fma2(acc, pack2(q1.z, q1.z), w[6]);
                fma2(acc, pack2(q1.w, q1.w), w[7]);
                fma2(acc, pack2(q2.x, q2.x), w[8]);
                fma2(acc, pack2(q2.y, q2.y), w[9]);
                fma2(acc, pack2(q2.z, q2.z), w[10]);
                fma2(acc, pack2(q2.w, q2.w), w[11]);
                fma2(acc, pack2(q3.x, q3.x), w[12]);
                fma2(acc, pack2(q3.y, q3.y), w[13]);
                fma2(acc, pack2(q3.z, q3.z), w[14]);
                fma2(acc, pack2(q3.w, q3.w), w[15]);
                if (nd >= 0) {
                    float lo, hi;
                    unpack2(acc, lo, hi);
                    *(float2*)&g_qt[(nd * RR + r) * DD + d0g] = make_float2(lo, hi);
                }
            }
        }
    }
}

// ------------------------------ edge setup ------------------------------------
__global__ void k_edgestats(const int* __restrict__ ei, const int* __restrict__ et, int e) {
    int i = blockIdx.x * blockDim.x + threadIdx.x;
    if (i >= e) return;
    int tgt = ei[e + i];
    int r   = et[i];
    atomicAdd(&g_thist[tgt * RR + r], 1);
    if (r == 0) atomicMax(&g_win[ei[i]], i);
}

__global__ void k_scan1(int n4) {
    __shared__ int buf[1024];
    int t = threadIdx.x;
    int gid = blockIdx.x * 1024 + t;
    int v = (gid < n4) ? g_thist[gid] : 0;
    buf[t] = v;
    __syncthreads();
    for (int off = 1; off < 1024; off <<= 1) {
        int x = (t >= off) ? buf[t - off] : 0;
        __syncthreads();
        buf[t] += x;
        __syncthreads();
    }
    if (gid < n4) g_toff[gid] = buf[t] - v;
    if (t == 1023) g_bsum[blockIdx.x] = buf[t];
}

__global__ void k_scan2(int nblocks, int n4) {
    if (threadIdx.x == 0) {
        int run = 0;
        for (int b = 0; b < nblocks; b++) { int x = g_bsum[b]; g_bsum[b] = run; run += x; }
        g_toff[n4] = run;
    }
}

__global__ void k_scan3(int n4) {
    int gid = blockIdx.x * blockDim.x + threadIdx.x;
    if (gid < n4) {
        int v = g_toff[gid] + g_bsum[gid >> 10];
        g_toff[gid] = v;
        g_tcur[gid] = v;
    }
}

__global__ void k_scatter_edges(const int* __restrict__ ei, const int* __restrict__ et,
                                const int* __restrict__ ntype, int e) {
    int i = blockIdx.x * blockDim.x + threadIdx.x;
    if (i >= e) return;
    int src = ei[i];
    int tgt = ei[e + i];
    int r   = et[i];
    int st  = ntype[src];
    int pos = atomicAdd(&g_tcur[tgt * RR + r], 1);
    g_epack[pos] = src | (st << 16);
}

// ------- attention: warp per target, fp16 k/v rows, 4-wide unroll --------------
__global__ void __launch_bounds__(256)
k_attn(const int* __restrict__ ntype, const float* __restrict__ pri,
       const float* __restrict__ Rmsg, int n) {
    __shared__ float accsh[8][RR][DD];
    int warp = threadIdx.x >> 5, lane = threadIdx.x & 31;
    int i = blockIdx.x * 8 + warp;
    if (i >= n) return;
    int d0 = lane * 4;
    int h  = lane >> 2;

    int tt = ntype[i];
    float p0[TT], p1[TT], p2[TT], p3[TT];
#pragma unroll
    for (int st = 0; st < TT; st++) {
        p0[st] = pri[((tt * RR + 0) * TT + st) * HH + h];
        p1[st] = pri[((tt * RR + 1) * TT + st) * HH + h];
        p2[st] = pri[((tt * RR + 2) * TT + st) * HH + h];
        p3[st] = pri[((tt * RR + 3) * TT + st) * HH + h];
    }

    float den = 0.f;
    float4 acc[RR];
#pragma unroll
    for (int r = 0; r < RR; r++) acc[r] = make_float4(0.f, 0.f, 0.f, 0.f);

#pragma unroll
    for (int r = 0; r < RR; r++) {
        int beg = g_toff[i * RR + r], end = g_toff[i * RR + r + 1];
        if (beg == end) continue;
        float4 qtr = *(const float4*)&g_qt[(i * RR + r) * DD + d0];
        float4 a = make_float4(0.f, 0.f, 0.f, 0.f);
        float pA = (r == 0) ? p0[0] : (r == 1) ? p1[0] : (r == 2) ? p2[0] : p3[0];
        float pB = (r == 0) ? p0[1] : (r == 1) ? p1[1] : (r == 2) ? p2[1] : p3[1];
        float pC = (r == 0) ? p0[2] : (r == 1) ? p1[2] : (r == 2) ? p2[2] : p3[2];
        int idx = beg;
        for (; idx + 4 <= end; idx += 4) {
            int pk0 = g_epack[idx];
            int pk1 = g_epack[idx + 1];
            int pk2 = g_epack[idx + 2];
            int pk3 = g_epack[idx + 3];
            int s0 = pk0 & 0xFFFF, st0 = pk0 >> 16;
            int s1 = pk1 & 0xFFFF, st1 = pk1 >> 16;
            int s2 = pk2 & 0xFFFF, st2 = pk2 >> 16;
            int s3 = pk3 & 0xFFFF, st3 = pk3 >> 16;
            uint2 kr0 = *(const uint2*)&g_k[s0 * DD + d0];
            uint2 kr1 = *(const uint2*)&g_k[s1 * DD + d0];
            uint2 kr2 = *(const uint2*)&g_k[s2 * DD + d0];
            uint2 kr3 = *(const uint2*)&g_k[s3 * DD + d0];
            uint2 vr0 = *(const uint2*)&g_v[s0 * DD + d0];
            uint2 vr1 = *(const uint2*)&g_v[s1 * DD + d0];
            uint2 vr2 = *(const uint2*)&g_v[s2 * DD + d0];
            uint2 vr3 = *(const uint2*)&g_v[s3 * DD + d0];
            float2 k0a = __half22float2(*(__half2*)&kr0.x), k0b = __half22float2(*(__half2*)&kr0.y);
            float2 k1a = __half22float2(*(__half2*)&kr1.x), k1b = __half22float2(*(__half2*)&kr1.y);
            float2 k2a = __half22float2(*(__half2*)&kr2.x), k2b = __half22float2(*(__half2*)&kr2.y);
            float2 k3a = __half22float2(*(__half2*)&kr3.x), k3b = __half22float2(*(__half2*)&kr3.y);
            float sa = qtr.x * k0a.x + qtr.y * k0a.y + qtr.z * k0b.x + qtr.w * k0b.y;
            float sb = qtr.x * k1a.x + qtr.y * k1a.y + qtr.z * k1b.x + qtr.w * k1b.y;
            float sc = qtr.x * k2a.x + qtr.y * k2a.y + qtr.z * k2b.x + qtr.w * k2b.y;
            float sd = qtr.x * k3a.x + qtr.y * k3a.y + qtr.z * k3b.x + qtr.w * k3b.y;
            sa += __shfl_xor_sync(0xffffffffu, sa, 1);
            sb += __shfl_xor_sync(0xffffffffu, sb, 1);
            sc += __shfl_xor_sync(0xffffffffu, sc, 1);
            sd += __shfl_xor_sync(0xffffffffu, sd, 1);
            sa += __shfl_xor_sync(0xffffffffu, sa, 2);
            sb += __shfl_xor_sync(0xffffffffu, sb, 2);
            sc += __shfl_xor_sync(0xffffffffu, sc, 2);
            sd += __shfl_xor_sync(0xffffffffu, sd, 2);
            float pra = (st0 == 1) ? pB : (st0 == 2) ? pC : pA;
            float prb = (st1 == 1) ? pB : (st1 == 2) ? pC : pA;
            float prc = (st2 == 1) ? pB : (st2 == 2) ? pC : pA;
            float prd = (st3 == 1) ? pB : (st3 == 2) ? pC : pA;
            float pea = __expf(sa * pra * 0.25f);
            float peb = __expf(sb * prb * 0.25f);
            float pec = __expf(sc * prc * 0.25f);
            float ped = __expf(sd * prd * 0.25f);
            den += (pea + peb) + (pec + ped);
            float2 v0a = __half22float2(*(__half2*)&vr0.x), v0b = __half22float2(*(__half2*)&vr0.y);
            float2 v1a = __half22float2(*(__half2*)&vr1.x), v1b = __half22float2(*(__half2*)&vr1.y);
            float2 v2a = __half22float2(*(__half2*)&vr2.x), v2b = __half22float2(*(__half2*)&vr2.y);
            float2 v3a = __half22float2(*(__half2*)&vr3.x), v3b = __half22float2(*(__half2*)&vr3.y);
            a.x += pea * v0a.x + peb * v1a.x + pec * v2a.x + ped * v3a.x;
            a.y += pea * v0a.y + peb * v1a.y + pec * v2a.y + ped * v3a.y;
            a.z += pea * v0b.x + peb * v1b.x + pec * v2b.x + ped * v3b.x;
            a.w += pea * v0b.y + peb * v1b.y + pec * v2b.y + ped * v3b.y;
        }
        for (; idx < end; idx++) {
            int pk  = g_epack[idx];
            int src = pk & 0xFFFF;
            int st  = pk >> 16;
            uint2 kr = *(const uint2*)&g_k[src * DD + d0];
            uint2 vr = *(const uint2*)&g_v[src * DD + d0];
            float2 ka = __half22float2(*(__half2*)&kr.x), kb = __half22float2(*(__half2*)&kr.y);
            float s = qtr.x * ka.x + qtr.y * ka.y + qtr.z * kb.x + qtr.w * kb.y;
            s += __shfl_xor_sync(0xffffffffu, s, 1);
            s += __shfl_xor_sync(0xffffffffu, s, 2);
            float pr = (st == 1) ? pB : (st == 2) ? pC : pA;
            float pe = __expf(s * pr * 0.25f);
            den += pe;
            float2 va = __half22float2(*(__half2*)&vr.x), vb = __half22float2(*(__half2*)&vr.y);
            a.x += pe * va.x;
            a.y += pe * va.y;
            a.z += pe * vb.x;
            a.w += pe * vb.y;
        }
        acc[r] = a;
    }

    float inv = 1.f / (den + 1e-16f);
#pragma unroll
    for (int r = 0; r < RR; r++) {
        accsh[warp][r][d0 + 0] = acc[r].x * inv;
        accsh[warp][r][d0 + 1] = acc[r].y * inv;
        accsh[warp][r][d0 + 2] = acc[r].z * inv;
        accsh[warp][r][d0 + 3] = acc[r].w * inv;
    }
    __syncwarp();

    int f0 = (lane & 3) * 4;
    float4 o = make_float4(0.f, 0.f, 0.f, 0.f);
#pragma unroll
    for (int r = 0; r < RR; r++) {
#pragma unroll 4
        for (int dk = 0; dk < DKK; dk++) {
            float a = accsh[warp][r][(h << 4) + dk];
            const float4 w = *(const float4*)&Rmsg[(((r * HH + h) * DKK + dk) * DKK) + f0];
            o.x += a * w.x;
            o.y += a * w.y;
            o.z += a * w.z;
            o.w += a * w.w;
        }
    }
    *(float4*)&g_aggr[i * DD + d0] = o;
}

// ------------- final: speaker add + GELU + per-type A projection + skip -------
__global__ void __launch_bounds__(256, 3)
k_final(const float* __restrict__ x, const int* __restrict__ ntype,
        const int* __restrict__ ei,
        const float* __restrict__ Aw, const float* __restrict__ Ab,
        const float* __restrict__ skip, float* __restrict__ out, int n, int e) {
    __shared__ __align__(16) float gsN[DD][GST];
    __shared__ int nodes_s[NPB], types_s[NPB], spsrc_s[NPB];
    int tid  = threadIdx.x;
    int base = blockIdx.x * NPB;
    if (tid < NPB) {
        int idx = base + tid;
        int cidx = (idx < n) ? idx : (n - 1);
        int nd = (idx < n) ? g_perm[idx] : -1;
        nodes_s[tid] = nd;
        types_s[tid] = ntype[g_perm[cidx]];
        int sps = -1;
        if (nd >= 0) {
            int we = g_win[nd];
            if (we >= 0) sps = ei[e + we];
        }
        spsrc_s[tid] = sps;
    }
    __syncthreads();

    for (int idx = tid; idx < NPB * DD; idx += 256) {
        int j = idx >> 7;
        int k = idx & 127;
        int nd = nodes_s[j];
        float v = 0.f;
        if (nd >= 0) {
            v = g_aggr[nd * DD + k];
            int sps = spsrc_s[j];
            if (sps >= 0) v += g_sp[sps * DD + k];
            v = 0.5f * v * (1.f + erff(v * 0.70710678118654752f));
        }
        gsN[k][j] = v;
    }
    __syncthreads();

    int g  = tid >> 6;
    int p  = tid & 63;
    int d0 = 2 * p;
    int jb = g * 8;

    int t0 = types_s[0];
    bool uniform = true;
#pragma unroll
    for (int j = 1; j < NPB; j++) uniform &= (types_s[j] == t0);

    if (uniform) {
        const float* pA = Aw + t0 * DD * DD + d0;
        ull bA = *(const ull*)&Ab[t0 * DD + d0];
        ull aA[8];
#pragma unroll
        for (int j = 0; j < 8; j++) aA[j] = bA;
#pragma unroll 4
        for (int k = 0; k < DD; k++) {
            ull w2 = *(const ull*)&pA[k * DD];
            float4 q0 = *(const float4*)&gsN[k][jb];
            float4 q1 = *(const float4*)&gsN[k][jb + 4];
            fma2(aA[0], pack2(q0.x, q0.x), w2);
            fma2(aA[1], pack2(q0.y, q0.y), w2);
            fma2(aA[2], pack2(q0.z, q0.z), w2);
            fma2(aA[3], pack2(q0.w, q0.w), w2);
            fma2(aA[4], pack2(q1.x, q1.x), w2);
            fma2(aA[5], pack2(q1.y, q1.y), w2);
            fma2(aA[6], pack2(q1.z, q1.z), w2);
            fma2(aA[7], pack2(q1.w, q1.w), w2);
        }
        float sk = skip[t0];
        float alpha = 1.f / (1.f + __expf(-sk));
        float beta  = 1.f - alpha;
#pragma unroll
        for (int j = 0; j < 8; j++) {
            int nd = nodes_s[jb + j];
            if (nd < 0) continue;
            float lo, hi;
            unpack2(aA[j], lo, hi);
            float2 xv = *(const float2*)&x[nd * DD + d0];
            *(float2*)&out[nd * DD + d0] =
                make_float2(lo * alpha + xv.x * beta, hi * alpha + xv.y * beta);
        }
    } else {
        for (int j = 0; j < 8; j++) {
            int nd = nodes_s[jb + j];
            if (nd < 0) continue;
            int t = types_s[jb + j];
            float2 aA = *(const float2*)&Ab[t * DD + d0];
            for (int k = 0; k < DD; k++) {
                float gv = gsN[k][jb + j];
                float2 w = *(const float2*)&Aw[(t * DD + k) * DD + d0];
                aA.x += gv * w.x; aA.y += gv * w.y;
            }
            float sk = skip[t];
            float alpha = 1.f / (1.f + __expf(-sk));
            float beta  = 1.f - alpha;
            float2 xv = *(const float2*)&x[nd * DD + d0];
            *(float2*)&out[nd * DD + d0] =
                make_float2(aA.x * alpha + xv.x * beta, aA.y * alpha + xv.y * beta);
        }
    }
}

// --------------------------------- launcher -----------------------------------
extern "C" void kernel_launch(void* const* d_in, const int* in_sizes, int n_in,
                              void* d_out, int out_size) {
    const float* node_inp  = (const float*)d_in[0];
    const int*   node_type = (const int*)  d_in[1];
    const int*   edge_index= (const int*)  d_in[2];
    const int*   edge_type = (const int*)  d_in[3];
    const float* Kw = (const float*)d_in[5];
    const float* Kb = (const float*)d_in[6];
    const float* Qw = (const float*)d_in[7];
    const float* Qb = (const float*)d_in[8];
    const float* Vw = (const float*)d_in[9];
    const float* Vb = (const float*)d_in[10];
    const float* Aw = (const float*)d_in[11];
    const float* Ab = (const float*)d_in[12];
    const float* pri  = (const float*)d_in[13];
    const float* Ratt = (const float*)d_in[14];
    const float* Rmsg = (const float*)d_in[15];
    const float* s2u  = (const float*)d_in[16];
    const float* skip = (const float*)d_in[17];
    float* out = (float*)d_out;

    int n = in_sizes[1];
    int e = in_sizes[3];
    if (n > NMAX) n = NMAX;
    if (e > EMAX) e = EMAX;
    int n4 = n * RR;

    int nb  = (n + 255) / 256;
    int n4b = (n4 + 255) / 256;
    int eb  = (e + 255) / 256;
    int sb  = (n4 + 1023) / 1024;
    int ngb = (n + GN - 1) / GN;

    cudaFuncSetAttribute(k_gemm_proj, cudaFuncAttributeMaxDynamicSharedMemorySize, SMEM_GEMM);

    cudaStream_t side;
    cudaStreamCreateWithFlags(&side, cudaStreamNonBlocking);
    cudaEvent_t evFork, evJoin;
    cudaEventCreateWithFlags(&evFork, cudaEventDisableTiming);
    cudaEventCreateWithFlags(&evJoin, cudaEventDisableTiming);

    k_init<<<n4b + 65 + 16, 256>>>(Vw, Vb, s2u, Ratt, n, n4b);
    cudaEventRecord(evFork, 0);
    cudaStreamWaitEvent(side, evFork, 0);

    k_edgestats<<<eb, 256, 0, side>>>(edge_index, edge_type, e);
    k_scan1<<<sb, 1024, 0, side>>>(n4);
    k_scan2<<<1, 32, 0, side>>>(sb, n4);
    k_scan3<<<n4b, 256, 0, side>>>(n4);
    k_scatter_edges<<<eb, 256, 0, side>>>(edge_index, edge_type, node_type, e);
    cudaEventRecord(evJoin, side);

    k_nodehist<<<nb, 256>>>(node_type, n);
    k_nodescatter<<<nb, 256>>>(node_type, n);
    k_gemm_proj<<<dim3(ngb, 5), 256, SMEM_GEMM>>>(node_inp, node_type,
                                                  Kw, Kb, Qw, Qb, Vw, Vb, n);

    cudaStreamWaitEvent(0, evJoin, 0);
    k_attn<<<(n + 7) / 8, 256>>>(node_type, pri, Rmsg, n);
    k_final<<<(n + NPB - 1) / NPB, 256>>>(node_inp, node_type, edge_index,
                                          Aw, Ab, skip, out, n, e);
}